// round 3
// baseline (speedup 1.0000x reference)
#include <cuda_runtime.h>
#include <mma.h>
using namespace nvcuda;

#define BB 2
#define LL 1536
#define DD 1024
#define HH 16
#define PP 1024
#define HDIM 64

#define QROWS 32
#define PSTRIDE 1544          // 4 front pad + 1536 + 4 spare
#define FUSED_SMEM_FLOATS (QROWS * PSTRIDE + 64 * 68 + LL + 8)
#define FUSED_SMEM_BYTES (FUSED_SMEM_FLOATS * 4)      // 221216
#define SCORES_SMEM_BYTES (2 * 128 * 68 * 4)          // 69632

// ---------------- device scratch ----------------
__device__ float g_Q[BB * HH * LL * HDIM];      // head-major [b,h,l,d]
__device__ float g_K[BB * HH * LL * HDIM];
__device__ float g_V[BB * HH * LL * HDIM];
__device__ float g_attn[BB * LL * PP];          // [b,l,h*64+d]
__device__ float g_S[BB * HH * LL * LL];        // scores

typedef wmma::fragment<wmma::matrix_a, 16, 16, 8, wmma::precision::tf32, wmma::row_major> FragA;
typedef wmma::fragment<wmma::matrix_b, 16, 16, 8, wmma::precision::tf32, wmma::row_major> FragB;
typedef wmma::fragment<wmma::matrix_b, 16, 16, 8, wmma::precision::tf32, wmma::col_major> FragBc;
typedef wmma::fragment<wmma::accumulator, 16, 16, 8, float> FragC;

__device__ __forceinline__ void cvt_a(FragA& f) {
#pragma unroll
    for (int e = 0; e < f.num_elements; e++) f.x[e] = wmma::__float_to_tf32(f.x[e]);
}
__device__ __forceinline__ void cvt_b(FragB& f) {
#pragma unroll
    for (int e = 0; e < f.num_elements; e++) f.x[e] = wmma::__float_to_tf32(f.x[e]);
}
__device__ __forceinline__ void cvt_bc(FragBc& f) {
#pragma unroll
    for (int e = 0; e < f.num_elements; e++) f.x[e] = wmma::__float_to_tf32(f.x[e]);
}

// ---------------- projection GEMM (tf32 wmma, pipelined): C = A @ W + bias ----------
__global__ __launch_bounds__(256) void proj_wmma(const float* __restrict__ Ain,
                                                 const float* __restrict__ W,
                                                 const float* __restrict__ bias,
                                                 float* __restrict__ Cout, int mode) {
    const float* A = (mode == 3) ? g_attn : Ain;
    float* C;
    if (mode == 0) C = g_Q;
    else if (mode == 1) C = g_K;
    else if (mode == 2) C = g_V;
    else C = Cout;

    __shared__ float As[128][36];
    __shared__ float Bs[32][132];
    __shared__ float BiasT[16][132];

    const int m0 = blockIdx.y * 128;
    const int n0 = blockIdx.x * 128;
    const int t = threadIdx.x;
    const int warp = t >> 5;
    const int wm = (warp & 3) * 32;
    const int wn = (warp >> 2) * 64;

#pragma unroll
    for (int r = 0; r < 2; r++) {
        int idx = t + r * 256;
        int row = idx >> 5;
        int col = (idx & 31) << 2;
        *(float4*)&BiasT[row][col] = *(const float4*)(bias + n0 + col);
    }

    FragC c[2][4];
#pragma unroll
    for (int i = 0; i < 2; i++)
#pragma unroll
        for (int j = 0; j < 4; j++) wmma::fill_fragment(c[i][j], 0.f);

    const int arow = t >> 3, acol = (t & 7) << 2;
    const int brow = t >> 5, bcol = (t & 31) << 2;

    float4 apre[4], bpre[4];
#pragma unroll
    for (int r = 0; r < 4; r++) {
        apre[r] = *(const float4*)(A + (size_t)(m0 + arow + r * 32) * DD + acol);
        bpre[r] = *(const float4*)(W + (size_t)(brow + r * 8) * PP + n0 + bcol);
    }

    for (int k0 = 0; k0 < DD; k0 += 32) {
#pragma unroll
        for (int r = 0; r < 4; r++) {
            *(float4*)&As[arow + r * 32][acol] = apre[r];
            *(float4*)&Bs[brow + r * 8][bcol] = bpre[r];
        }
        __syncthreads();
        if (k0 + 32 < DD) {
#pragma unroll
            for (int r = 0; r < 4; r++) {
                apre[r] = *(const float4*)(A + (size_t)(m0 + arow + r * 32) * DD + k0 + 32 + acol);
                bpre[r] = *(const float4*)(W + (size_t)(k0 + 32 + brow + r * 8) * PP + n0 + bcol);
            }
        }
#pragma unroll
        for (int kk = 0; kk < 32; kk += 8) {
            FragA a[2];
            FragB b[4];
#pragma unroll
            for (int i = 0; i < 2; i++) { wmma::load_matrix_sync(a[i], &As[wm + i * 16][kk], 36); cvt_a(a[i]); }
#pragma unroll
            for (int j = 0; j < 4; j++) { wmma::load_matrix_sync(b[j], &Bs[kk][wn + j * 16], 132); cvt_b(b[j]); }
#pragma unroll
            for (int i = 0; i < 2; i++)
#pragma unroll
                for (int j = 0; j < 4; j++) wmma::mma_sync(c[i][j], a[i], b[j], c[i][j]);
        }
        __syncthreads();
    }

#pragma unroll
    for (int i = 0; i < 2; i++)
#pragma unroll
        for (int j = 0; j < 4; j++) {
            FragC bf;
            wmma::load_matrix_sync(bf, &BiasT[0][wn + j * 16], 132, wmma::mem_row_major);
#pragma unroll
            for (int e = 0; e < bf.num_elements; e++) c[i][j].x[e] += bf.x[e];
        }

    if (mode <= 2) {
        const int b = m0 / LL;
        const int l0 = m0 - b * LL;
        const int h = (n0 + wn) >> 6;
        float* base = C + (((size_t)(b * HH + h)) * LL + l0 + wm) * HDIM;
#pragma unroll
        for (int i = 0; i < 2; i++)
#pragma unroll
            for (int j = 0; j < 4; j++)
                wmma::store_matrix_sync(base + (size_t)(i * 16) * HDIM + j * 16, c[i][j],
                                        HDIM, wmma::mem_row_major);
    } else {
        float* base = C + (size_t)(m0 + wm) * PP + n0 + wn;
#pragma unroll
        for (int i = 0; i < 2; i++)
#pragma unroll
            for (int j = 0; j < 4; j++)
                wmma::store_matrix_sync(base + (size_t)(i * 16) * PP + j * 16, c[i][j],
                                        PP, wmma::mem_row_major);
    }
}

// ---------------- scores: whole K-dim (64) resident in SMEM, single sync ----------------
__global__ __launch_bounds__(256, 2) void scores_wmma() {
    extern __shared__ float sm2[];
    float* As = sm2;              // [128][68]  Q (pre-scaled)
    float* Bs = sm2 + 128 * 68;   // [128][68]  K

    const int z = blockIdx.z;
    const float* Qb = g_Q + (size_t)z * LL * HDIM;
    const float* Kb = g_K + (size_t)z * LL * HDIM;
    float* Sb = g_S + (size_t)z * LL * LL;
    const int q0 = blockIdx.y * 128;
    const int n0 = blockIdx.x * 128;

    const int t = threadIdx.x;
    const int warp = t >> 5;
    const int wm = (warp & 3) * 32;
    const int wn = (warp >> 2) * 64;

#pragma unroll
    for (int r = 0; r < 8; r++) {
        int idx = t + r * 256;
        int row = idx >> 4;
        int col = (idx & 15) << 2;
        float4 q4 = *(const float4*)(Qb + (size_t)(q0 + row) * HDIM + col);
        q4.x *= 0.125f; q4.y *= 0.125f; q4.z *= 0.125f; q4.w *= 0.125f;
        *(float4*)(As + row * 68 + col) = q4;
        *(float4*)(Bs + row * 68 + col) = *(const float4*)(Kb + (size_t)(n0 + row) * HDIM + col);
    }
    __syncthreads();

    FragC c[2][4];
#pragma unroll
    for (int i = 0; i < 2; i++)
#pragma unroll
        for (int j = 0; j < 4; j++) wmma::fill_fragment(c[i][j], 0.f);

#pragma unroll
    for (int kk = 0; kk < 64; kk += 8) {
        FragA a[2];
        FragBc b[4];
#pragma unroll
        for (int i = 0; i < 2; i++) { wmma::load_matrix_sync(a[i], As + (wm + i * 16) * 68 + kk, 68); cvt_a(a[i]); }
#pragma unroll
        for (int j = 0; j < 4; j++) { wmma::load_matrix_sync(b[j], Bs + (wn + j * 16) * 68 + kk, 68); cvt_bc(b[j]); }
#pragma unroll
        for (int i = 0; i < 2; i++)
#pragma unroll
            for (int j = 0; j < 4; j++) wmma::mma_sync(c[i][j], a[i], b[j], c[i][j]);
    }

    float* base = Sb + (size_t)(q0 + wm) * LL + n0 + wn;
#pragma unroll
    for (int i = 0; i < 2; i++)
#pragma unroll
        for (int j = 0; j < 4; j++)
            wmma::store_matrix_sync(base + (size_t)(i * 16) * LL + j * 16, c[i][j],
                                    LL, wmma::mem_row_major);
}

// ---------------- fused: mask + softmax + 3 diffusion steps + p@V ----------------
// One block = 32 q-rows of one (b,h). p lives entirely in SMEM; DRAM sees
// one read of scores and one write of attn.
__global__ __launch_bounds__(256) void fused_sda(const int* __restrict__ mask,
                                                 const float* __restrict__ kw) {
    extern __shared__ float sm[];
    float* p = sm;                              // [32][1544], 4-float zero pad at row start
    float* Vs = sm + QROWS * PSTRIDE;           // [64][68]
    float* kvs = Vs + 64 * 68;                  // [1536]
    float* w5 = kvs + LL;                       // [5]

    const int t = threadIdx.x;
    const int warp = t >> 5, lane = t & 31;
    const int q0 = blockIdx.x * QROWS;
    const int z = blockIdx.y;
    const int b = z >> 4;
    const int h = z & 15;
    const float* Sbase = g_S + ((size_t)z * LL + q0) * LL;
    const float* Vb = g_V + (size_t)z * LL * HDIM;
    const int* mrow = mask + b * LL;

    if (t == 0) {
        float mx = kw[0];
#pragma unroll
        for (int j = 1; j < 5; j++) mx = fmaxf(mx, kw[j]);
        float e[5], s = 0.f;
#pragma unroll
        for (int j = 0; j < 5; j++) { e[j] = __expf(kw[j] - mx); s += e[j]; }
#pragma unroll
        for (int j = 0; j < 5; j++) w5[j] = e[j] / s;
    }
    // kvs + zero pads
    for (int i = t; i < LL / 4; i += 256) {
        int4 m4 = *(const int4*)(mrow + i * 4);
        *(float4*)(kvs + i * 4) = make_float4(m4.x > 0 ? 1.f : 0.f, m4.y > 0 ? 1.f : 0.f,
                                              m4.z > 0 ? 1.f : 0.f, m4.w > 0 ? 1.f : 0.f);
    }
    if (t < QROWS) {
        float* r = p + t * PSTRIDE;
        r[0] = r[1] = r[2] = r[3] = 0.f;
    }
    // load scores with additive mask
    for (int idx = t; idx < QROWS * (LL / 4); idx += 256) {
        int row = idx / (LL / 4);
        int c4 = idx - row * (LL / 4);
        float4 s4 = *(const float4*)(Sbase + (size_t)row * LL + c4 * 4);
        int4 m4 = *(const int4*)(mrow + c4 * 4);
        s4.x += (m4.x > 0) ? 0.f : -1e9f;
        s4.y += (m4.y > 0) ? 0.f : -1e9f;
        s4.z += (m4.z > 0) ? 0.f : -1e9f;
        s4.w += (m4.w > 0) ? 0.f : -1e9f;
        *(float4*)(p + row * PSTRIDE + 4 + c4 * 4) = s4;
    }
    __syncthreads();

    const float w0 = w5[0], w1 = w5[1], w2 = w5[2], w3 = w5[3], w4 = w5[4];
    const float4* kvs4 = (const float4*)kvs;

    // ---- per-warp rows: softmax + diffusion (no block syncs) ----
    for (int rr = 0; rr < 4; rr++) {
        const int row = warp * 4 + rr;
        float* bufm4 = p + row * PSTRIDE;       // bufm4[4+i] = element i
        float4* buf4 = (float4*)(bufm4 + 4);    // group m = elements [4m,4m+4)

        // softmax
        float mx = -3.4e38f;
#pragma unroll
        for (int k = 0; k < 12; k++) {
            float4 v = buf4[lane + 32 * k];
            mx = fmaxf(mx, fmaxf(fmaxf(v.x, v.y), fmaxf(v.z, v.w)));
        }
#pragma unroll
        for (int o = 16; o; o >>= 1) mx = fmaxf(mx, __shfl_xor_sync(0xffffffffu, mx, o));
        float s = 0.f;
#pragma unroll
        for (int k = 0; k < 12; k++) {
            int m = lane + 32 * k;
            float4 v = buf4[m];
            v.x = __expf(v.x - mx); v.y = __expf(v.y - mx);
            v.z = __expf(v.z - mx); v.w = __expf(v.w - mx);
            buf4[m] = v;
            s += v.x + v.y + v.z + v.w;
        }
#pragma unroll
        for (int o = 16; o; o >>= 1) s += __shfl_xor_sync(0xffffffffu, s, o);
        float inv = 1.f / s;
#pragma unroll
        for (int k = 0; k < 12; k++) {
            int m = lane + 32 * k;
            float4 v = buf4[m];
            v.x *= inv; v.y *= inv; v.z *= inv; v.w *= inv;
            buf4[m] = v;
        }
        __syncwarp();

        // 3 diffusion steps
        for (int step = 0; step < 3; step++) {
            // pass A: sum of conv*kv (read-only; halo via direct LDS, group -1 = zero pad)
            float sa = 0.f;
#pragma unroll
            for (int k = 0; k < 12; k++) {
                int m = lane + 32 * k;
                float4 o4 = buf4[m];
                float4 h4 = *(float4*)(bufm4 + 4 * m);   // = buf4[m-1], pad for m==0
                float4 kv = kvs4[m];
                float cx = w0 * h4.x + w1 * h4.y + w2 * h4.z + w3 * h4.w + w4 * o4.x;
                float cy = w0 * h4.y + w1 * h4.z + w2 * h4.w + w3 * o4.x + w4 * o4.y;
                float cz = w0 * h4.z + w1 * h4.w + w2 * o4.x + w3 * o4.y + w4 * o4.z;
                float cw = w0 * h4.w + w1 * o4.x + w2 * o4.y + w3 * o4.z + w4 * o4.w;
                sa += cx * kv.x + cy * kv.y + cz * kv.z + cw * kv.w;
            }
#pragma unroll
            for (int o = 16; o; o >>= 1) sa += __shfl_xor_sync(0xffffffffu, sa, o);
            const float rmul = 0.02f / (sa + 1e-9f);
            __syncwarp();

            // pass B: in-place mix; halo passed lane-to-lane through registers
            float4 prev31 = make_float4(0.f, 0.f, 0.f, 0.f);
#pragma unroll
            for (int k = 0; k < 12; k++) {
                int m = lane + 32 * k;
                float4 o4 = buf4[m];
                float4 h4;
                h4.x = __shfl_up_sync(0xffffffffu, o4.x, 1);
                h4.y = __shfl_up_sync(0xffffffffu, o4.y, 1);
                h4.z = __shfl_up_sync(0xffffffffu, o4.z, 1);
                h4.w = __shfl_up_sync(0xffffffffu, o4.w, 1);
                float4 n31;
                n31.x = __shfl_sync(0xffffffffu, o4.x, 31);
                n31.y = __shfl_sync(0xffffffffu, o4.y, 31);
                n31.z = __shfl_sync(0xffffffffu, o4.z, 31);
                n31.w = __shfl_sync(0xffffffffu, o4.w, 31);
                if (lane == 0) h4 = prev31;
                prev31 = n31;
                float4 kv = kvs4[m];
                float cx = w0 * h4.x + w1 * h4.y + w2 * h4.z + w3 * h4.w + w4 * o4.x;
                float cy = w0 * h4.y + w1 * h4.z + w2 * h4.w + w3 * o4.x + w4 * o4.y;
                float cz = w0 * h4.z + w1 * h4.w + w2 * o4.x + w3 * o4.y + w4 * o4.z;
                float cw = w0 * h4.w + w1 * o4.x + w2 * o4.y + w3 * o4.z + w4 * o4.w;
                float4 nw;
                nw.x = 0.98f * o4.x + rmul * (cx * kv.x);
                nw.y = 0.98f * o4.y + rmul * (cy * kv.y);
                nw.z = 0.98f * o4.z + rmul * (cz * kv.z);
                nw.w = 0.98f * o4.w + rmul * (cw * kv.w);
                buf4[m] = nw;
            }
            __syncwarp();
        }
    }
    __syncthreads();

    // ---- attn = p @ V : warp per 16x16 output tile ----
    const int wi = warp >> 2;   // 0..1 (q sub-block)
    const int wj = warp & 3;    // 0..3 (d sub-block)
    FragC c;
    wmma::fill_fragment(c, 0.f);

    for (int k0 = 0; k0 < LL; k0 += 64) {
#pragma unroll
        for (int r = 0; r < 4; r++) {
            int id = t + r * 256;
            int row = id >> 4;
            int c4 = (id & 15) << 2;
            *(float4*)(Vs + row * 68 + c4) = *(const float4*)(Vb + (size_t)(k0 + row) * HDIM + c4);
        }
        __syncthreads();
#pragma unroll
        for (int kk = 0; kk < 64; kk += 8) {
            FragA a;
            FragB bb;
            wmma::load_matrix_sync(a, p + (16 * wi) * PSTRIDE + 4 + k0 + kk, PSTRIDE);
            cvt_a(a);
            wmma::load_matrix_sync(bb, Vs + kk * 68 + 16 * wj, 68);
            cvt_b(bb);
            wmma::mma_sync(c, a, bb, c);
        }
        __syncthreads();
    }

    float* Cptr = g_attn + ((size_t)(b * LL + q0 + 16 * wi)) * PP + h * 64 + 16 * wj;
    wmma::store_matrix_sync(Cptr, c, PP, wmma::mem_row_major);
}

// ---------------- launch ----------------
extern "C" void kernel_launch(void* const* d_in, const int* in_sizes, int n_in,
                              void* d_out, int out_size) {
    const float* hs = (const float*)d_in[0];
    const int* mask = (const int*)d_in[1];
    const float* Wq = (const float*)d_in[2];
    const float* bq = (const float*)d_in[3];
    const float* Wk = (const float*)d_in[4];
    const float* bk = (const float*)d_in[5];
    const float* Wv = (const float*)d_in[6];
    const float* bv = (const float*)d_in[7];
    const float* Wo = (const float*)d_in[8];
    const float* bo = (const float*)d_in[9];
    const float* kw = (const float*)d_in[10];

    cudaFuncSetAttribute(scores_wmma, cudaFuncAttributeMaxDynamicSharedMemorySize, SCORES_SMEM_BYTES);
    cudaFuncSetAttribute(fused_sda, cudaFuncAttributeMaxDynamicSharedMemorySize, FUSED_SMEM_BYTES);

    dim3 gProj(PP / 128, (BB * LL) / 128);
    proj_wmma<<<gProj, 256>>>(hs, Wq, bq, nullptr, 0);
    proj_wmma<<<gProj, 256>>>(hs, Wk, bk, nullptr, 1);
    proj_wmma<<<gProj, 256>>>(hs, Wv, bv, nullptr, 2);

    scores_wmma<<<dim3(LL / 128, LL / 128, BB * HH), 256, SCORES_SMEM_BYTES>>>();

    fused_sda<<<dim3(LL / QROWS, BB * HH), 256, FUSED_SMEM_BYTES>>>(mask, kw);

    proj_wmma<<<gProj, 256>>>(nullptr, Wo, bo, (float*)d_out, 3);
}

// round 4
// speedup vs baseline: 1.2319x; 1.2319x over previous
#include <cuda_runtime.h>
#include <mma.h>
using namespace nvcuda;

#define BB 2
#define LL 1536
#define DD 1024
#define HH 16
#define PP 1024
#define HDIM 64

#define SCORES_SMEM_BYTES (2 * 128 * 68 * 4)          // 69632

// ---------------- device scratch ----------------
__device__ float g_Q[BB * HH * LL * HDIM];      // head-major [b,h,l,d]
__device__ float g_K[BB * HH * LL * HDIM];
__device__ float g_V[BB * HH * LL * HDIM];
__device__ float g_attn[BB * LL * PP];          // [b,l,h*64+d]
__device__ float g_S[BB * HH * LL * LL];        // scores -> p in-place

typedef wmma::fragment<wmma::matrix_a, 16, 16, 8, wmma::precision::tf32, wmma::row_major> FragA;
typedef wmma::fragment<wmma::matrix_b, 16, 16, 8, wmma::precision::tf32, wmma::row_major> FragB;
typedef wmma::fragment<wmma::matrix_b, 16, 16, 8, wmma::precision::tf32, wmma::col_major> FragBc;
typedef wmma::fragment<wmma::accumulator, 16, 16, 8, float> FragC;

__device__ __forceinline__ void cvt_a(FragA& f) {
#pragma unroll
    for (int e = 0; e < f.num_elements; e++) f.x[e] = wmma::__float_to_tf32(f.x[e]);
}
__device__ __forceinline__ void cvt_b(FragB& f) {
#pragma unroll
    for (int e = 0; e < f.num_elements; e++) f.x[e] = wmma::__float_to_tf32(f.x[e]);
}
__device__ __forceinline__ void cvt_bc(FragBc& f) {
#pragma unroll
    for (int e = 0; e < f.num_elements; e++) f.x[e] = wmma::__float_to_tf32(f.x[e]);
}

// ---------------- projection GEMM (tf32 wmma, pipelined): C = A @ W + bias ----------
__global__ __launch_bounds__(256) void proj_wmma(const float* __restrict__ Ain,
                                                 const float* __restrict__ W,
                                                 const float* __restrict__ bias,
                                                 float* __restrict__ Cout, int mode) {
    const float* A = (mode == 3) ? g_attn : Ain;
    float* C;
    if (mode == 0) C = g_Q;
    else if (mode == 1) C = g_K;
    else if (mode == 2) C = g_V;
    else C = Cout;

    __shared__ float As[128][36];
    __shared__ float Bs[32][132];
    __shared__ float BiasT[16][132];

    const int m0 = blockIdx.y * 128;
    const int n0 = blockIdx.x * 128;
    const int t = threadIdx.x;
    const int warp = t >> 5;
    const int wm = (warp & 3) * 32;
    const int wn = (warp >> 2) * 64;

#pragma unroll
    for (int r = 0; r < 2; r++) {
        int idx = t + r * 256;
        int row = idx >> 5;
        int col = (idx & 31) << 2;
        *(float4*)&BiasT[row][col] = *(const float4*)(bias + n0 + col);
    }

    FragC c[2][4];
#pragma unroll
    for (int i = 0; i < 2; i++)
#pragma unroll
        for (int j = 0; j < 4; j++) wmma::fill_fragment(c[i][j], 0.f);

    const int arow = t >> 3, acol = (t & 7) << 2;
    const int brow = t >> 5, bcol = (t & 31) << 2;

    float4 apre[4], bpre[4];
#pragma unroll
    for (int r = 0; r < 4; r++) {
        apre[r] = *(const float4*)(A + (size_t)(m0 + arow + r * 32) * DD + acol);
        bpre[r] = *(const float4*)(W + (size_t)(brow + r * 8) * PP + n0 + bcol);
    }

    for (int k0 = 0; k0 < DD; k0 += 32) {
#pragma unroll
        for (int r = 0; r < 4; r++) {
            *(float4*)&As[arow + r * 32][acol] = apre[r];
            *(float4*)&Bs[brow + r * 8][bcol] = bpre[r];
        }
        __syncthreads();
        if (k0 + 32 < DD) {
#pragma unroll
            for (int r = 0; r < 4; r++) {
                apre[r] = *(const float4*)(A + (size_t)(m0 + arow + r * 32) * DD + k0 + 32 + acol);
                bpre[r] = *(const float4*)(W + (size_t)(k0 + 32 + brow + r * 8) * PP + n0 + bcol);
            }
        }
#pragma unroll
        for (int kk = 0; kk < 32; kk += 8) {
            FragA a[2];
            FragB b[4];
#pragma unroll
            for (int i = 0; i < 2; i++) { wmma::load_matrix_sync(a[i], &As[wm + i * 16][kk], 36); cvt_a(a[i]); }
#pragma unroll
            for (int j = 0; j < 4; j++) { wmma::load_matrix_sync(b[j], &Bs[kk][wn + j * 16], 132); cvt_b(b[j]); }
#pragma unroll
            for (int i = 0; i < 2; i++)
#pragma unroll
                for (int j = 0; j < 4; j++) wmma::mma_sync(c[i][j], a[i], b[j], c[i][j]);
        }
        __syncthreads();
    }

#pragma unroll
    for (int i = 0; i < 2; i++)
#pragma unroll
        for (int j = 0; j < 4; j++) {
            FragC bf;
            wmma::load_matrix_sync(bf, &BiasT[0][wn + j * 16], 132, wmma::mem_row_major);
#pragma unroll
            for (int e = 0; e < bf.num_elements; e++) c[i][j].x[e] += bf.x[e];
        }

    if (mode <= 2) {
        const int b = m0 / LL;
        const int l0 = m0 - b * LL;
        const int h = (n0 + wn) >> 6;
        float* base = C + (((size_t)(b * HH + h)) * LL + l0 + wm) * HDIM;
#pragma unroll
        for (int i = 0; i < 2; i++)
#pragma unroll
            for (int j = 0; j < 4; j++)
                wmma::store_matrix_sync(base + (size_t)(i * 16) * HDIM + j * 16, c[i][j],
                                        HDIM, wmma::mem_row_major);
    } else {
        float* base = C + (size_t)(m0 + wm) * PP + n0 + wn;
#pragma unroll
        for (int i = 0; i < 2; i++)
#pragma unroll
            for (int j = 0; j < 4; j++)
                wmma::store_matrix_sync(base + (size_t)(i * 16) * PP + j * 16, c[i][j],
                                        PP, wmma::mem_row_major);
    }
}

// ---------------- scores: whole K-dim (64) resident in SMEM, single sync ----------------
__global__ __launch_bounds__(256, 2) void scores_wmma() {
    extern __shared__ float sm2[];
    float* As = sm2;              // [128][68]  Q (pre-scaled)
    float* Bs = sm2 + 128 * 68;   // [128][68]  K

    const int z = blockIdx.z;
    const float* Qb = g_Q + (size_t)z * LL * HDIM;
    const float* Kb = g_K + (size_t)z * LL * HDIM;
    float* Sb = g_S + (size_t)z * LL * LL;
    const int q0 = blockIdx.y * 128;
    const int n0 = blockIdx.x * 128;

    const int t = threadIdx.x;
    const int warp = t >> 5;
    const int wm = (warp & 3) * 32;
    const int wn = (warp >> 2) * 64;

#pragma unroll
    for (int r = 0; r < 8; r++) {
        int idx = t + r * 256;
        int row = idx >> 4;
        int col = (idx & 15) << 2;
        float4 q4 = *(const float4*)(Qb + (size_t)(q0 + row) * HDIM + col);
        q4.x *= 0.125f; q4.y *= 0.125f; q4.z *= 0.125f; q4.w *= 0.125f;
        *(float4*)(As + row * 68 + col) = q4;
        *(float4*)(Bs + row * 68 + col) = *(const float4*)(Kb + (size_t)(n0 + row) * HDIM + col);
    }
    __syncthreads();

    FragC c[2][4];
#pragma unroll
    for (int i = 0; i < 2; i++)
#pragma unroll
        for (int j = 0; j < 4; j++) wmma::fill_fragment(c[i][j], 0.f);

#pragma unroll
    for (int kk = 0; kk < 64; kk += 8) {
        FragA a[2];
        FragBc b[4];
#pragma unroll
        for (int i = 0; i < 2; i++) { wmma::load_matrix_sync(a[i], As + (wm + i * 16) * 68 + kk, 68); cvt_a(a[i]); }
#pragma unroll
        for (int j = 0; j < 4; j++) { wmma::load_matrix_sync(b[j], Bs + (wn + j * 16) * 68 + kk, 68); cvt_bc(b[j]); }
#pragma unroll
        for (int i = 0; i < 2; i++)
#pragma unroll
            for (int j = 0; j < 4; j++) wmma::mma_sync(c[i][j], a[i], b[j], c[i][j]);
    }

    float* base = Sb + (size_t)(q0 + wm) * LL + n0 + wn;
#pragma unroll
    for (int i = 0; i < 2; i++)
#pragma unroll
        for (int j = 0; j < 4; j++)
            wmma::store_matrix_sync(base + (size_t)(i * 16) * LL + j * 16, c[i][j],
                                    LL, wmma::mem_row_major);
}

// ---------------- softmax + 3 diffusion steps, warp-per-row, register-resident ------
// One warp owns a full 1536 row in 12 float4 regs. Element m*4.. of group m = lane+32k.
// Halo (group m-1) via shfl_up within k, and lane31->lane0 carry across k.
__global__ __launch_bounds__(256) void softmax_diff_reg(const int* __restrict__ mask,
                                                        const float* __restrict__ kw) {
    __shared__ float kvs[LL];
    __shared__ float w5s[5];

    const int t = threadIdx.x;
    const int warp = t >> 5, lane = t & 31;
    const size_t row0 = (size_t)blockIdx.x * 8;      // 8 rows per block, same z (1536%8==0)
    const int z = (int)(row0 / LL);
    const int b = z >> 4;
    const int* mrow = mask + b * LL;

    if (t == 0) {
        float mxw = kw[0];
#pragma unroll
        for (int j = 1; j < 5; j++) mxw = fmaxf(mxw, kw[j]);
        float e[5], s = 0.f;
#pragma unroll
        for (int j = 0; j < 5; j++) { e[j] = __expf(kw[j] - mxw); s += e[j]; }
#pragma unroll
        for (int j = 0; j < 5; j++) w5s[j] = e[j] / s;
    }
    for (int i = t; i < LL / 4; i += 256) {
        int4 m4 = *(const int4*)(mrow + i * 4);
        *(float4*)(kvs + i * 4) = make_float4(m4.x > 0 ? 1.f : 0.f, m4.y > 0 ? 1.f : 0.f,
                                              m4.z > 0 ? 1.f : 0.f, m4.w > 0 ? 1.f : 0.f);
    }
    __syncthreads();

    const float w0 = w5s[0], w1 = w5s[1], w2 = w5s[2], w3 = w5s[3], w4 = w5s[4];
    const float4* kvs4 = (const float4*)kvs;
    float* prow = g_S + (row0 + warp) * LL;

    // load row + additive mask
    float4 p4[12];
    float mx = -3.4e38f;
#pragma unroll
    for (int k = 0; k < 12; k++) {
        int m = lane + 32 * k;
        float4 v = *(const float4*)(prow + (size_t)m * 4);
        float4 kv = kvs4[m];
        v.x += (kv.x > 0.f) ? 0.f : -1e9f;
        v.y += (kv.y > 0.f) ? 0.f : -1e9f;
        v.z += (kv.z > 0.f) ? 0.f : -1e9f;
        v.w += (kv.w > 0.f) ? 0.f : -1e9f;
        p4[k] = v;
        mx = fmaxf(mx, fmaxf(fmaxf(v.x, v.y), fmaxf(v.z, v.w)));
    }
#pragma unroll
    for (int o = 16; o; o >>= 1) mx = fmaxf(mx, __shfl_xor_sync(0xffffffffu, mx, o));

    float s = 0.f;
#pragma unroll
    for (int k = 0; k < 12; k++) {
        float4 v = p4[k];
        v.x = __expf(v.x - mx); v.y = __expf(v.y - mx);
        v.z = __expf(v.z - mx); v.w = __expf(v.w - mx);
        p4[k] = v;
        s += v.x + v.y + v.z + v.w;
    }
#pragma unroll
    for (int o = 16; o; o >>= 1) s += __shfl_xor_sync(0xffffffffu, s, o);
    float inv = 1.f / s;
#pragma unroll
    for (int k = 0; k < 12; k++) {
        p4[k].x *= inv; p4[k].y *= inv; p4[k].z *= inv; p4[k].w *= inv;
    }

    // 3 diffusion steps
#pragma unroll 1
    for (int step = 0; step < 3; step++) {
        float4 c4[12];
        float sa = 0.f;
        float4 prev31 = make_float4(0.f, 0.f, 0.f, 0.f);
#pragma unroll
        for (int k = 0; k < 12; k++) {
            float4 o4 = p4[k];
            float4 h4;
            h4.x = __shfl_up_sync(0xffffffffu, o4.x, 1);
            h4.y = __shfl_up_sync(0xffffffffu, o4.y, 1);
            h4.z = __shfl_up_sync(0xffffffffu, o4.z, 1);
            h4.w = __shfl_up_sync(0xffffffffu, o4.w, 1);
            float4 n31;
            n31.x = __shfl_sync(0xffffffffu, o4.x, 31);
            n31.y = __shfl_sync(0xffffffffu, o4.y, 31);
            n31.z = __shfl_sync(0xffffffffu, o4.z, 31);
            n31.w = __shfl_sync(0xffffffffu, o4.w, 31);
            if (lane == 0) h4 = prev31;
            prev31 = n31;
            float4 kv = kvs4[lane + 32 * k];
            float4 cc;
            cc.x = (w0 * h4.x + w1 * h4.y + w2 * h4.z + w3 * h4.w + w4 * o4.x) * kv.x;
            cc.y = (w0 * h4.y + w1 * h4.z + w2 * h4.w + w3 * o4.x + w4 * o4.y) * kv.y;
            cc.z = (w0 * h4.z + w1 * h4.w + w2 * o4.x + w3 * o4.y + w4 * o4.z) * kv.z;
            cc.w = (w0 * h4.w + w1 * o4.x + w2 * o4.y + w3 * o4.z + w4 * o4.w) * kv.w;
            c4[k] = cc;
            sa += cc.x + cc.y + cc.z + cc.w;
        }
#pragma unroll
        for (int o = 16; o; o >>= 1) sa += __shfl_xor_sync(0xffffffffu, sa, o);
        const float rmul = 0.02f / (sa + 1e-9f);
#pragma unroll
        for (int k = 0; k < 12; k++) {
            p4[k].x = 0.98f * p4[k].x + rmul * c4[k].x;
            p4[k].y = 0.98f * p4[k].y + rmul * c4[k].y;
            p4[k].z = 0.98f * p4[k].z + rmul * c4[k].z;
            p4[k].w = 0.98f * p4[k].w + rmul * c4[k].w;
        }
    }

#pragma unroll
    for (int k = 0; k < 12; k++)
        *(float4*)(prow + (size_t)(lane + 32 * k) * 4) = p4[k];
}

// ---------------- attn = p @ V (tf32 wmma, pipelined), 256 thr, tile 128x64 ----------
__global__ __launch_bounds__(256) void attn_wmma() {
    const int z = blockIdx.z;
    const int b = z >> 4;
    const int h = z & 15;
    const float* Pb = g_S + (size_t)z * LL * LL;
    const float* Vb = g_V + (size_t)z * LL * HDIM;
    float* Cb = g_attn + (size_t)b * LL * PP + h * HDIM;
    const int m0 = blockIdx.x * 128;

    __shared__ float As[128][36];   // p tile [m][k]
    __shared__ float Bs[32][68];    // V tile [k][n]

    const int t = threadIdx.x;
    const int warp = t >> 5;
    const int wm = (warp >> 1) * 32;
    const int wn = (warp & 1) * 32;

    FragC c[2][2];
#pragma unroll
    for (int i = 0; i < 2; i++)
#pragma unroll
        for (int j = 0; j < 2; j++) wmma::fill_fragment(c[i][j], 0.f);

    const int arow = t >> 3, acol = (t & 7) << 2;      // A: 1024 float4, 4/thread
    const int brow = t >> 4, bcol = (t & 15) << 2;     // B: 512 float4, 2/thread

    float4 apre[4], bpre[2];
#pragma unroll
    for (int r = 0; r < 4; r++)
        apre[r] = *(const float4*)(Pb + (size_t)(m0 + arow + r * 32) * LL + acol);
#pragma unroll
    for (int r = 0; r < 2; r++)
        bpre[r] = *(const float4*)(Vb + (size_t)(brow + r * 16) * HDIM + bcol);

    for (int k0 = 0; k0 < LL; k0 += 32) {
#pragma unroll
        for (int r = 0; r < 4; r++) *(float4*)&As[arow + r * 32][acol] = apre[r];
#pragma unroll
        for (int r = 0; r < 2; r++) *(float4*)&Bs[brow + r * 16][bcol] = bpre[r];
        __syncthreads();
        if (k0 + 32 < LL) {
#pragma unroll
            for (int r = 0; r < 4; r++)
                apre[r] = *(const float4*)(Pb + (size_t)(m0 + arow + r * 32) * LL + k0 + 32 + acol);
#pragma unroll
            for (int r = 0; r < 2; r++)
                bpre[r] = *(const float4*)(Vb + (size_t)(k0 + 32 + brow + r * 16) * HDIM + bcol);
        }
#pragma unroll
        for (int kk = 0; kk < 32; kk += 8) {
            FragA a[2];
            FragB bb[2];
#pragma unroll
            for (int i = 0; i < 2; i++) { wmma::load_matrix_sync(a[i], &As[wm + i * 16][kk], 36); cvt_a(a[i]); }
#pragma unroll
            for (int j = 0; j < 2; j++) { wmma::load_matrix_sync(bb[j], &Bs[kk][wn + j * 16], 68); cvt_b(bb[j]); }
#pragma unroll
            for (int i = 0; i < 2; i++)
#pragma unroll
                for (int j = 0; j < 2; j++) wmma::mma_sync(c[i][j], a[i], bb[j], c[i][j]);
        }
        __syncthreads();
    }

#pragma unroll
    for (int i = 0; i < 2; i++)
#pragma unroll
        for (int j = 0; j < 2; j++)
            wmma::store_matrix_sync(Cb + (size_t)(m0 + wm + i * 16) * PP + wn + j * 16,
                                    c[i][j], PP, wmma::mem_row_major);
}

// ---------------- launch ----------------
extern "C" void kernel_launch(void* const* d_in, const int* in_sizes, int n_in,
                              void* d_out, int out_size) {
    const float* hs = (const float*)d_in[0];
    const int* mask = (const int*)d_in[1];
    const float* Wq = (const float*)d_in[2];
    const float* bq = (const float*)d_in[3];
    const float* Wk = (const float*)d_in[4];
    const float* bk = (const float*)d_in[5];
    const float* Wv = (const float*)d_in[6];
    const float* bv = (const float*)d_in[7];
    const float* Wo = (const float*)d_in[8];
    const float* bo = (const float*)d_in[9];
    const float* kw = (const float*)d_in[10];

    cudaFuncSetAttribute(scores_wmma, cudaFuncAttributeMaxDynamicSharedMemorySize, SCORES_SMEM_BYTES);

    dim3 gProj(PP / 128, (BB * LL) / 128);
    proj_wmma<<<gProj, 256>>>(hs, Wq, bq, nullptr, 0);
    proj_wmma<<<gProj, 256>>>(hs, Wk, bk, nullptr, 1);
    proj_wmma<<<gProj, 256>>>(hs, Wv, bv, nullptr, 2);

    scores_wmma<<<dim3(LL / 128, LL / 128, BB * HH), 256, SCORES_SMEM_BYTES>>>();

    softmax_diff_reg<<<(BB * HH * LL) / 8, 256>>>(mask, kw);

    attn_wmma<<<dim3(LL / 128, 1, BB * HH), 256>>>();

    proj_wmma<<<gProj, 256>>>(nullptr, Wo, bo, (float*)d_out, 3);
}

// round 5
// speedup vs baseline: 1.2999x; 1.0552x over previous
#include <cuda_runtime.h>
#include <mma.h>
using namespace nvcuda;

#define BB 2
#define LL 1536
#define DD 1024
#define HH 16
#define PP 1024
#define HDIM 64

#define SCORES_SMEM_BYTES (2 * 128 * 68 * 4)          // 69632 (As+Bs; reused as C staging)

// fused kernel smem
#define FROWS 16
#define PSTR 1540                                     // 16B-aligned rows, 2-way conflict max
#define FUSED_SMEM_FLOATS (FROWS * PSTR + LL + 64 * 68 + 8)
#define FUSED_SMEM_BYTES (FUSED_SMEM_FLOATS * 4)      // ~122 KB

// ---------------- device scratch ----------------
__device__ float g_Q[BB * HH * LL * HDIM];      // head-major [b,h,l,d]
__device__ float g_K[BB * HH * LL * HDIM];
__device__ float g_V[BB * HH * LL * HDIM];
__device__ float g_attn[BB * LL * PP];          // [b,l,h*64+d]
__device__ float g_S[BB * HH * LL * LL];        // scores

typedef wmma::fragment<wmma::matrix_a, 16, 16, 8, wmma::precision::tf32, wmma::row_major> FragA;
typedef wmma::fragment<wmma::matrix_b, 16, 16, 8, wmma::precision::tf32, wmma::row_major> FragB;
typedef wmma::fragment<wmma::matrix_b, 16, 16, 8, wmma::precision::tf32, wmma::col_major> FragBc;
typedef wmma::fragment<wmma::accumulator, 16, 16, 8, float> FragC;

__device__ __forceinline__ void cvt_a(FragA& f) {
#pragma unroll
    for (int e = 0; e < f.num_elements; e++) f.x[e] = wmma::__float_to_tf32(f.x[e]);
}
__device__ __forceinline__ void cvt_b(FragB& f) {
#pragma unroll
    for (int e = 0; e < f.num_elements; e++) f.x[e] = wmma::__float_to_tf32(f.x[e]);
}
__device__ __forceinline__ void cvt_bc(FragBc& f) {
#pragma unroll
    for (int e = 0; e < f.num_elements; e++) f.x[e] = wmma::__float_to_tf32(f.x[e]);
}

// ---------------- QKV projection, one launch, z selects target ----------------
__global__ __launch_bounds__(256) void qkv_wmma(const float* __restrict__ A,
                                                const float* __restrict__ Wq,
                                                const float* __restrict__ bq,
                                                const float* __restrict__ Wk,
                                                const float* __restrict__ bk,
                                                const float* __restrict__ Wv,
                                                const float* __restrict__ bv) {
    const int zz = blockIdx.z;
    const float* W = (zz == 0) ? Wq : (zz == 1) ? Wk : Wv;
    const float* bias = (zz == 0) ? bq : (zz == 1) ? bk : bv;
    float* C = (zz == 0) ? g_Q : (zz == 1) ? g_K : g_V;

    __shared__ float As[128][36];
    __shared__ float Bs[32][132];
    __shared__ float BiasT[16][132];

    const int m0 = blockIdx.y * 128;
    const int n0 = blockIdx.x * 128;
    const int t = threadIdx.x;
    const int warp = t >> 5;
    const int wm = (warp & 3) * 32;
    const int wn = (warp >> 2) * 64;

#pragma unroll
    for (int r = 0; r < 2; r++) {
        int idx = t + r * 256;
        int row = idx >> 5;
        int col = (idx & 31) << 2;
        *(float4*)&BiasT[row][col] = *(const float4*)(bias + n0 + col);
    }

    FragC c[2][4];
#pragma unroll
    for (int i = 0; i < 2; i++)
#pragma unroll
        for (int j = 0; j < 4; j++) wmma::fill_fragment(c[i][j], 0.f);

    const int arow = t >> 3, acol = (t & 7) << 2;
    const int brow = t >> 5, bcol = (t & 31) << 2;

    float4 apre[4], bpre[4];
#pragma unroll
    for (int r = 0; r < 4; r++) {
        apre[r] = *(const float4*)(A + (size_t)(m0 + arow + r * 32) * DD + acol);
        bpre[r] = *(const float4*)(W + (size_t)(brow + r * 8) * PP + n0 + bcol);
    }

    for (int k0 = 0; k0 < DD; k0 += 32) {
#pragma unroll
        for (int r = 0; r < 4; r++) {
            *(float4*)&As[arow + r * 32][acol] = apre[r];
            *(float4*)&Bs[brow + r * 8][bcol] = bpre[r];
        }
        __syncthreads();
        if (k0 + 32 < DD) {
#pragma unroll
            for (int r = 0; r < 4; r++) {
                apre[r] = *(const float4*)(A + (size_t)(m0 + arow + r * 32) * DD + k0 + 32 + acol);
                bpre[r] = *(const float4*)(W + (size_t)(k0 + 32 + brow + r * 8) * PP + n0 + bcol);
            }
        }
#pragma unroll
        for (int kk = 0; kk < 32; kk += 8) {
            FragA a[2];
            FragB b[4];
#pragma unroll
            for (int i = 0; i < 2; i++) { wmma::load_matrix_sync(a[i], &As[wm + i * 16][kk], 36); cvt_a(a[i]); }
#pragma unroll
            for (int j = 0; j < 4; j++) { wmma::load_matrix_sync(b[j], &Bs[kk][wn + j * 16], 132); cvt_b(b[j]); }
#pragma unroll
            for (int i = 0; i < 2; i++)
#pragma unroll
                for (int j = 0; j < 4; j++) wmma::mma_sync(c[i][j], a[i], b[j], c[i][j]);
        }
        __syncthreads();
    }

#pragma unroll
    for (int i = 0; i < 2; i++)
#pragma unroll
        for (int j = 0; j < 4; j++) {
            FragC bf;
            wmma::load_matrix_sync(bf, &BiasT[0][wn + j * 16], 132, wmma::mem_row_major);
#pragma unroll
            for (int e = 0; e < bf.num_elements; e++) c[i][j].x[e] += bf.x[e];
        }

    const int b = m0 / LL;
    const int l0 = m0 - b * LL;
    const int h = (n0 + wn) >> 6;
    float* base = C + (((size_t)(b * HH + h)) * LL + l0 + wm) * HDIM;
#pragma unroll
    for (int i = 0; i < 2; i++)
#pragma unroll
        for (int j = 0; j < 4; j++)
            wmma::store_matrix_sync(base + (size_t)(i * 16) * HDIM + j * 16, c[i][j],
                                    HDIM, wmma::mem_row_major);
}

// ---------------- output projection: C = g_attn @ Wo + bo ----------------
__global__ __launch_bounds__(256) void oproj_wmma(const float* __restrict__ W,
                                                  const float* __restrict__ bias,
                                                  float* __restrict__ Cout) {
    const float* A = g_attn;

    __shared__ float As[128][36];
    __shared__ float Bs[32][132];
    __shared__ float BiasT[16][132];

    const int m0 = blockIdx.y * 128;
    const int n0 = blockIdx.x * 128;
    const int t = threadIdx.x;
    const int warp = t >> 5;
    const int wm = (warp & 3) * 32;
    const int wn = (warp >> 2) * 64;

#pragma unroll
    for (int r = 0; r < 2; r++) {
        int idx = t + r * 256;
        int row = idx >> 5;
        int col = (idx & 31) << 2;
        *(float4*)&BiasT[row][col] = *(const float4*)(bias + n0 + col);
    }

    FragC c[2][4];
#pragma unroll
    for (int i = 0; i < 2; i++)
#pragma unroll
        for (int j = 0; j < 4; j++) wmma::fill_fragment(c[i][j], 0.f);

    const int arow = t >> 3, acol = (t & 7) << 2;
    const int brow = t >> 5, bcol = (t & 31) << 2;

    float4 apre[4], bpre[4];
#pragma unroll
    for (int r = 0; r < 4; r++) {
        apre[r] = *(const float4*)(A + (size_t)(m0 + arow + r * 32) * DD + acol);
        bpre[r] = *(const float4*)(W + (size_t)(brow + r * 8) * PP + n0 + bcol);
    }

    for (int k0 = 0; k0 < DD; k0 += 32) {
#pragma unroll
        for (int r = 0; r < 4; r++) {
            *(float4*)&As[arow + r * 32][acol] = apre[r];
            *(float4*)&Bs[brow + r * 8][bcol] = bpre[r];
        }
        __syncthreads();
        if (k0 + 32 < DD) {
#pragma unroll
            for (int r = 0; r < 4; r++) {
                apre[r] = *(const float4*)(A + (size_t)(m0 + arow + r * 32) * DD + k0 + 32 + acol);
                bpre[r] = *(const float4*)(W + (size_t)(k0 + 32 + brow + r * 8) * PP + n0 + bcol);
            }
        }
#pragma unroll
        for (int kk = 0; kk < 32; kk += 8) {
            FragA a[2];
            FragB b[4];
#pragma unroll
            for (int i = 0; i < 2; i++) { wmma::load_matrix_sync(a[i], &As[wm + i * 16][kk], 36); cvt_a(a[i]); }
#pragma unroll
            for (int j = 0; j < 4; j++) { wmma::load_matrix_sync(b[j], &Bs[kk][wn + j * 16], 132); cvt_b(b[j]); }
#pragma unroll
            for (int i = 0; i < 2; i++)
#pragma unroll
                for (int j = 0; j < 4; j++) wmma::mma_sync(c[i][j], a[i], b[j], c[i][j]);
        }
        __syncthreads();
    }

#pragma unroll
    for (int i = 0; i < 2; i++)
#pragma unroll
        for (int j = 0; j < 4; j++) {
            FragC bf;
            wmma::load_matrix_sync(bf, &BiasT[0][wn + j * 16], 132, wmma::mem_row_major);
#pragma unroll
            for (int e = 0; e < bf.num_elements; e++) c[i][j].x[e] += bf.x[e];
        }

    float* base = Cout + (size_t)(m0 + wm) * PP + n0 + wn;
#pragma unroll
    for (int i = 0; i < 2; i++)
#pragma unroll
        for (int j = 0; j < 4; j++)
            wmma::store_matrix_sync(base + (size_t)(i * 16) * PP + j * 16, c[i][j],
                                    PP, wmma::mem_row_major);
}

// ---------------- scores: K-dim resident, staged float4 store epilogue ----------------
__global__ __launch_bounds__(256, 2) void scores_wmma() {
    extern __shared__ float sm2[];
    float* As = sm2;              // [128][68]  Q (pre-scaled)
    float* Bs = sm2 + 128 * 68;   // [128][68]  K
    float* Cst = sm2;             // staging [128][132] (reuses As+Bs)

    const int z = blockIdx.z;
    const float* Qb = g_Q + (size_t)z * LL * HDIM;
    const float* Kb = g_K + (size_t)z * LL * HDIM;
    float* Sb = g_S + (size_t)z * LL * LL;
    const int q0 = blockIdx.y * 128;
    const int n0 = blockIdx.x * 128;

    const int t = threadIdx.x;
    const int warp = t >> 5;
    const int wm = (warp & 3) * 32;
    const int wn = (warp >> 2) * 64;

#pragma unroll
    for (int r = 0; r < 8; r++) {
        int idx = t + r * 256;
        int row = idx >> 4;
        int col = (idx & 15) << 2;
        float4 q4 = *(const float4*)(Qb + (size_t)(q0 + row) * HDIM + col);
        q4.x *= 0.125f; q4.y *= 0.125f; q4.z *= 0.125f; q4.w *= 0.125f;
        *(float4*)(As + row * 68 + col) = q4;
        *(float4*)(Bs + row * 68 + col) = *(const float4*)(Kb + (size_t)(n0 + row) * HDIM + col);
    }
    __syncthreads();

    FragC c[2][4];
#pragma unroll
    for (int i = 0; i < 2; i++)
#pragma unroll
        for (int j = 0; j < 4; j++) wmma::fill_fragment(c[i][j], 0.f);

#pragma unroll
    for (int kk = 0; kk < 64; kk += 8) {
        FragA a[2];
        FragBc b[4];
#pragma unroll
        for (int i = 0; i < 2; i++) { wmma::load_matrix_sync(a[i], As + (wm + i * 16) * 68 + kk, 68); cvt_a(a[i]); }
#pragma unroll
        for (int j = 0; j < 4; j++) { wmma::load_matrix_sync(b[j], Bs + (wn + j * 16) * 68 + kk, 68); cvt_bc(b[j]); }
#pragma unroll
        for (int i = 0; i < 2; i++)
#pragma unroll
            for (int j = 0; j < 4; j++) wmma::mma_sync(c[i][j], a[i], b[j], c[i][j]);
    }

    __syncthreads();   // done reading As/Bs -> reuse as staging
#pragma unroll
    for (int i = 0; i < 2; i++)
#pragma unroll
        for (int j = 0; j < 4; j++)
            wmma::store_matrix_sync(Cst + (wm + i * 16) * 132 + wn + j * 16, c[i][j],
                                    132, wmma::mem_row_major);
    __syncthreads();

#pragma unroll
    for (int r = 0; r < 16; r++) {
        int idx = t + r * 256;
        int row = idx >> 5;
        int col = (idx & 31) << 2;
        *(float4*)(Sb + (size_t)(q0 + row) * LL + n0 + col) = *(float4*)(Cst + row * 132 + col);
    }
}

// ---------------- fused: softmax + 3 diffusion steps + p@V -------------------------
// 512 threads / 16 warps / 16 q-rows of one (b,h). Warp-per-row register softmax+
// diffusion, p staged to SMEM, tf32 WMMA p@V with V chunk pipeline, 4-way K-split.
__global__ __launch_bounds__(512) void fused_sda2(const int* __restrict__ mask,
                                                  const float* __restrict__ kw) {
    extern __shared__ float sm[];
    float* Ps = sm;                          // [16][PSTR]
    float* kvs = sm + FROWS * PSTR;          // [1536]
    float* Vs = kvs + LL;                    // [64][68] chunk / later reduce buf [4][16][68]
    float* w5s = Vs + 64 * 68;               // [5]

    const int t = threadIdx.x;
    const int warp = t >> 5, lane = t & 31;
    const size_t row0 = (size_t)blockIdx.x * FROWS;   // global row, 96 blocks per z
    const int z = (int)(row0 / LL);
    const int q0 = (int)(row0 - (size_t)z * LL);
    const int b = z >> 4;
    const int h = z & 15;
    const int* mrow = mask + b * LL;
    const float* Vb = g_V + (size_t)z * LL * HDIM;

    if (t == 0) {
        float mxw = kw[0];
#pragma unroll
        for (int j = 1; j < 5; j++) mxw = fmaxf(mxw, kw[j]);
        float e[5], s = 0.f;
#pragma unroll
        for (int j = 0; j < 5; j++) { e[j] = __expf(kw[j] - mxw); s += e[j]; }
#pragma unroll
        for (int j = 0; j < 5; j++) w5s[j] = e[j] / s;
    }
    if (t < LL / 4) {
        int4 m4 = *(const int4*)(mrow + t * 4);
        *(float4*)(kvs + t * 4) = make_float4(m4.x > 0 ? 1.f : 0.f, m4.y > 0 ? 1.f : 0.f,
                                              m4.z > 0 ? 1.f : 0.f, m4.w > 0 ? 1.f : 0.f);
    }
    __syncthreads();

    const float w0 = w5s[0], w1 = w5s[1], w2 = w5s[2], w3 = w5s[3], w4 = w5s[4];
    const float4* kvs4 = (const float4*)kvs;

    // ---- phase 1: warp-per-row softmax + diffusion (register resident) ----
    {
        const float* prow = g_S + (row0 + warp) * LL;
        float4 p4[12];
        float mx = -3.4e38f;
#pragma unroll
        for (int k = 0; k < 12; k++) {
            int m = lane + 32 * k;
            float4 v = *(const float4*)(prow + (size_t)m * 4);
            float4 kv = kvs4[m];
            v.x += (kv.x > 0.f) ? 0.f : -1e9f;
            v.y += (kv.y > 0.f) ? 0.f : -1e9f;
            v.z += (kv.z > 0.f) ? 0.f : -1e9f;
            v.w += (kv.w > 0.f) ? 0.f : -1e9f;
            p4[k] = v;
            mx = fmaxf(mx, fmaxf(fmaxf(v.x, v.y), fmaxf(v.z, v.w)));
        }
#pragma unroll
        for (int o = 16; o; o >>= 1) mx = fmaxf(mx, __shfl_xor_sync(0xffffffffu, mx, o));

        float s = 0.f;
#pragma unroll
        for (int k = 0; k < 12; k++) {
            float4 v = p4[k];
            v.x = __expf(v.x - mx); v.y = __expf(v.y - mx);
            v.z = __expf(v.z - mx); v.w = __expf(v.w - mx);
            p4[k] = v;
            s += v.x + v.y + v.z + v.w;
        }
#pragma unroll
        for (int o = 16; o; o >>= 1) s += __shfl_xor_sync(0xffffffffu, s, o);
        float inv = 1.f / s;
#pragma unroll
        for (int k = 0; k < 12; k++) {
            p4[k].x *= inv; p4[k].y *= inv; p4[k].z *= inv; p4[k].w *= inv;
        }

#pragma unroll 1
        for (int step = 0; step < 3; step++) {
            float4 c4[12];
            float sa = 0.f;
            float4 prev31 = make_float4(0.f, 0.f, 0.f, 0.f);
#pragma unroll
            for (int k = 0; k < 12; k++) {
                float4 o4 = p4[k];
                float4 h4;
                h4.x = __shfl_up_sync(0xffffffffu, o4.x, 1);
                h4.y = __shfl_up_sync(0xffffffffu, o4.y, 1);
                h4.z = __shfl_up_sync(0xffffffffu, o4.z, 1);
                h4.w = __shfl_up_sync(0xffffffffu, o4.w, 1);
                float4 n31;
                n31.x = __shfl_sync(0xffffffffu, o4.x, 31);
                n31.y = __shfl_sync(0xffffffffu, o4.y, 31);
                n31.z = __shfl_sync(0xffffffffu, o4.z, 31);
                n31.w = __shfl_sync(0xffffffffu, o4.w, 31);
                if (lane == 0) h4 = prev31;
                prev31 = n31;
                float4 kv = kvs4[lane + 32 * k];
                float4 cc;
                cc.x = (w0 * h4.x + w1 * h4.y + w2 * h4.z + w3 * h4.w + w4 * o4.x) * kv.x;
                cc.y = (w0 * h4.y + w1 * h4.z + w2 * h4.w + w3 * o4.x + w4 * o4.y) * kv.y;
                cc.z = (w0 * h4.z + w1 * h4.w + w2 * o4.x + w3 * o4.y + w4 * o4.z) * kv.z;
                cc.w = (w0 * h4.w + w1 * o4.x + w2 * o4.y + w3 * o4.z + w4 * o4.w) * kv.w;
                c4[k] = cc;
                sa += cc.x + cc.y + cc.z + cc.w;
            }
#pragma unroll
            for (int o = 16; o; o >>= 1) sa += __shfl_xor_sync(0xffffffffu, sa, o);
            const float rmul = 0.02f / (sa + 1e-9f);
#pragma unroll
            for (int k = 0; k < 12; k++) {
                p4[k].x = 0.98f * p4[k].x + rmul * c4[k].x;
                p4[k].y = 0.98f * p4[k].y + rmul * c4[k].y;
                p4[k].z = 0.98f * p4[k].z + rmul * c4[k].z;
                p4[k].w = 0.98f * p4[k].w + rmul * c4[k].w;
            }
        }

        // stage p row into SMEM
        float* pr = Ps + warp * PSTR;
#pragma unroll
        for (int k = 0; k < 12; k++)
            *(float4*)(pr + (size_t)(lane + 32 * k) * 4) = p4[k];
    }
    __syncthreads();

    // ---- phase 2: out[16x64] = p[16x1536] @ V[1536x64], tf32 wmma ----
    const int g = warp >> 2;     // k-group (4 groups x 16 rows per 64-row chunk)
    const int j = warp & 3;      // output column tile (16 cols)

    FragC acc;
    wmma::fill_fragment(acc, 0.f);

    // V chunk pipeline: 24 chunks of 64 rows, register prefetch
    const int vrow = t >> 4, vcol = (t & 15) << 2;    // 2 float4 per thread per chunk
    float4 vpre[2];
#pragma unroll
    for (int r = 0; r < 2; r++)
        vpre[r] = *(const float4*)(Vb + (size_t)(vrow + r * 32) * HDIM + vcol);

    for (int c = 0; c < 24; c++) {
#pragma unroll
        for (int r = 0; r < 2; r++)
            *(float4*)(Vs + (vrow + r * 32) * 68 + vcol) = vpre[r];
        __syncthreads();
        if (c + 1 < 24) {
#pragma unroll
            for (int r = 0; r < 2; r++)
                vpre[r] = *(const float4*)(Vb + (size_t)((c + 1) * 64 + vrow + r * 32) * HDIM + vcol);
        }
#pragma unroll
        for (int kk = 0; kk < 16; kk += 8) {
            FragA a;
            FragB bb;
            wmma::load_matrix_sync(a, Ps + c * 64 + g * 16 + kk, PSTR);
            cvt_a(a);
            wmma::load_matrix_sync(bb, Vs + (g * 16 + kk) * 68 + j * 16, 68);
            cvt_b(bb);
            wmma::mma_sync(acc, a, bb, acc);
        }
        __syncthreads();
    }

    // reduce 4 k-groups: stage partials in Vs ([4][16][68])
    wmma::store_matrix_sync(Vs + (g * 16) * 68 + j * 16, acc, 68, wmma::mem_row_major);
    __syncthreads();

    if (t < 128) {
        const int row = t >> 3;
        const int col = (t & 7) << 3;    // 8 floats per thread
        float* o0 = Vs + row * 68 + col;
        float4 s0 = *(float4*)o0;
        float4 s1 = *(float4*)(o0 + 4);
#pragma unroll
        for (int gg = 1; gg < 4; gg++) {
            float* og = Vs + (gg * 16 + row) * 68 + col;
            float4 a0 = *(float4*)og;
            float4 a1 = *(float4*)(og + 4);
            s0.x += a0.x; s0.y += a0.y; s0.z += a0.z; s0.w += a0.w;
            s1.x += a1.x; s1.y += a1.y; s1.z += a1.z; s1.w += a1.w;
        }
        float* out = g_attn + ((size_t)(b * LL + q0 + row)) * PP + h * 64 + col;
        *(float4*)out = s0;
        *(float4*)(out + 4) = s1;
    }
}

// ---------------- launch ----------------
extern "C" void kernel_launch(void* const* d_in, const int* in_sizes, int n_in,
                              void* d_out, int out_size) {
    const float* hs = (const float*)d_in[0];
    const int* mask = (const int*)d_in[1];
    const float* Wq = (const float*)d_in[2];
    const float* bq = (const float*)d_in[3];
    const float* Wk = (const float*)d_in[4];
    const float* bk = (const float*)d_in[5];
    const float* Wv = (const float*)d_in[6];
    const float* bv = (const float*)d_in[7];
    const float* Wo = (const float*)d_in[8];
    const float* bo = (const float*)d_in[9];
    const float* kw = (const float*)d_in[10];

    cudaFuncSetAttribute(scores_wmma, cudaFuncAttributeMaxDynamicSharedMemorySize, SCORES_SMEM_BYTES);
    cudaFuncSetAttribute(fused_sda2, cudaFuncAttributeMaxDynamicSharedMemorySize, FUSED_SMEM_BYTES);

    dim3 gProj(PP / 128, (BB * LL) / 128);           // (8, 24)
    qkv_wmma<<<dim3(PP / 128, (BB * LL) / 128, 3), 256>>>(hs, Wq, bq, Wk, bk, Wv, bv);

    scores_wmma<<<dim3(LL / 128, LL / 128, BB * HH), 256, SCORES_SMEM_BYTES>>>();

    fused_sda2<<<(BB * HH * LL) / FROWS, 512, FUSED_SMEM_BYTES>>>(mask, kw);

    oproj_wmma<<<gProj, 256>>>(Wo, bo, (float*)d_out);
}

// round 6
// speedup vs baseline: 1.3380x; 1.0293x over previous
#include <cuda_runtime.h>
#include <mma.h>
using namespace nvcuda;

#define BB 2
#define LL 1536
#define DD 1024
#define HH 16
#define PP 1024
#define HDIM 64

#define SCORES_SMEM_BYTES (2 * 128 * 68 * 4)          // 69632 (As+Bs; reused as C staging)

// fused kernel smem
#define FROWS 16
#define PSTR 1540
#define FUSED_SMEM_FLOATS (FROWS * PSTR + LL + 64 * 68 + 8)
#define FUSED_SMEM_BYTES (FUSED_SMEM_FLOATS * 4)      // ~122 KB

// ---------------- device scratch ----------------
__device__ float g_Q[BB * HH * LL * HDIM];      // head-major [b,h,l,d], pre-scaled by 0.125
__device__ float g_K[BB * HH * LL * HDIM];
__device__ float g_V[BB * HH * LL * HDIM];
__device__ float g_attn[BB * LL * PP];          // [b,l,h*64+d]
__device__ float g_S[BB * HH * LL * LL];        // scores

typedef wmma::fragment<wmma::matrix_a, 16, 16, 8, wmma::precision::tf32, wmma::row_major> FragA;
typedef wmma::fragment<wmma::matrix_b, 16, 16, 8, wmma::precision::tf32, wmma::row_major> FragB;
typedef wmma::fragment<wmma::matrix_b, 16, 16, 8, wmma::precision::tf32, wmma::col_major> FragBc;
typedef wmma::fragment<wmma::accumulator, 16, 16, 8, float> FragC;

__device__ __forceinline__ void cvt_a(FragA& f) {
#pragma unroll
    for (int e = 0; e < f.num_elements; e++) f.x[e] = wmma::__float_to_tf32(f.x[e]);
}
__device__ __forceinline__ void cvt_b(FragB& f) {
#pragma unroll
    for (int e = 0; e < f.num_elements; e++) f.x[e] = wmma::__float_to_tf32(f.x[e]);
}
__device__ __forceinline__ void cvt_bc(FragBc& f) {
#pragma unroll
    for (int e = 0; e < f.num_elements; e++) f.x[e] = wmma::__float_to_tf32(f.x[e]);
}

// ---------------- 64x128-tile projection GEMM body ----------------
// mode 0: Q (head-major, x0.125)  1: K head-major  2: V head-major  3: flat to Cout
__device__ __forceinline__ void gemm64_body(const float* __restrict__ A,
                                            const float* __restrict__ W,
                                            const float* __restrict__ bias,
                                            float* __restrict__ C, int mode) {
    __shared__ float As[64][36];
    __shared__ float Bs[32][132];
    __shared__ float BiasT[16][132];

    const int m0 = blockIdx.y * 64;
    const int n0 = blockIdx.x * 128;
    const int t = threadIdx.x;
    const int warp = t >> 5;
    const int wm = (warp & 3) * 16;
    const int wn = (warp >> 2) * 64;

#pragma unroll
    for (int r = 0; r < 2; r++) {
        int idx = t + r * 256;
        int row = idx >> 5;
        int col = (idx & 31) << 2;
        *(float4*)&BiasT[row][col] = *(const float4*)(bias + n0 + col);
    }

    FragC c[4];
#pragma unroll
    for (int j = 0; j < 4; j++) wmma::fill_fragment(c[j], 0.f);

    const int arow = t >> 3, acol = (t & 7) << 2;      // A: 512 float4, 2/thread
    const int brow = t >> 5, bcol = (t & 31) << 2;     // B: 1024 float4, 4/thread

    float4 apre[2], bpre[4];
#pragma unroll
    for (int r = 0; r < 2; r++)
        apre[r] = *(const float4*)(A + (size_t)(m0 + arow + r * 32) * DD + acol);
#pragma unroll
    for (int r = 0; r < 4; r++)
        bpre[r] = *(const float4*)(W + (size_t)(brow + r * 8) * PP + n0 + bcol);

    for (int k0 = 0; k0 < DD; k0 += 32) {
#pragma unroll
        for (int r = 0; r < 2; r++) *(float4*)&As[arow + r * 32][acol] = apre[r];
#pragma unroll
        for (int r = 0; r < 4; r++) *(float4*)&Bs[brow + r * 8][bcol] = bpre[r];
        __syncthreads();
        if (k0 + 32 < DD) {
#pragma unroll
            for (int r = 0; r < 2; r++)
                apre[r] = *(const float4*)(A + (size_t)(m0 + arow + r * 32) * DD + k0 + 32 + acol);
#pragma unroll
            for (int r = 0; r < 4; r++)
                bpre[r] = *(const float4*)(W + (size_t)(k0 + 32 + brow + r * 8) * PP + n0 + bcol);
        }
#pragma unroll
        for (int kk = 0; kk < 32; kk += 8) {
            FragA a;
            wmma::load_matrix_sync(a, &As[wm][kk], 36);
            cvt_a(a);
#pragma unroll
            for (int j = 0; j < 4; j++) {
                FragB b;
                wmma::load_matrix_sync(b, &Bs[kk][wn + j * 16], 132);
                cvt_b(b);
                wmma::mma_sync(c[j], a, b, c[j]);
            }
        }
        __syncthreads();
    }

    const float scale = (mode == 0) ? 0.125f : 1.0f;
#pragma unroll
    for (int j = 0; j < 4; j++) {
        FragC bf;
        wmma::load_matrix_sync(bf, &BiasT[0][wn + j * 16], 132, wmma::mem_row_major);
#pragma unroll
        for (int e = 0; e < bf.num_elements; e++) c[j].x[e] = (c[j].x[e] + bf.x[e]) * scale;
    }

    if (mode <= 2) {
        const int b = m0 / LL;
        const int l0 = m0 - b * LL;
        const int h = (n0 + wn) >> 6;
        float* base = C + (((size_t)(b * HH + h)) * LL + l0 + wm) * HDIM;
#pragma unroll
        for (int j = 0; j < 4; j++)
            wmma::store_matrix_sync(base + j * 16, c[j], HDIM, wmma::mem_row_major);
    } else {
        float* base = C + (size_t)(m0 + wm) * PP + n0 + wn;
#pragma unroll
        for (int j = 0; j < 4; j++)
            wmma::store_matrix_sync(base + j * 16, c[j], PP, wmma::mem_row_major);
    }
}

__global__ __launch_bounds__(256, 2) void qkv_wmma(const float* __restrict__ A,
                                                   const float* __restrict__ Wq,
                                                   const float* __restrict__ bq,
                                                   const float* __restrict__ Wk,
                                                   const float* __restrict__ bk,
                                                   const float* __restrict__ Wv,
                                                   const float* __restrict__ bv) {
    const int zz = blockIdx.z;
    const float* W = (zz == 0) ? Wq : (zz == 1) ? Wk : Wv;
    const float* bias = (zz == 0) ? bq : (zz == 1) ? bk : bv;
    float* C = (zz == 0) ? g_Q : (zz == 1) ? g_K : g_V;
    gemm64_body(A, W, bias, C, zz);
}

__global__ __launch_bounds__(256, 2) void oproj_wmma(const float* __restrict__ W,
                                                     const float* __restrict__ bias,
                                                     float* __restrict__ Cout) {
    gemm64_body(g_attn, W, bias, Cout, 3);
}

// ---------------- scores: K-dim resident, staged float4 store epilogue ----------------
// Q is pre-scaled by 0.125 in projection.
__global__ __launch_bounds__(256, 2) void scores_wmma() {
    extern __shared__ float sm2[];
    float* As = sm2;              // [128][68]  Q
    float* Bs = sm2 + 128 * 68;   // [128][68]  K
    float* Cst = sm2;             // staging [128][132] (reuses As+Bs)

    const int z = blockIdx.z;
    const float* Qb = g_Q + (size_t)z * LL * HDIM;
    const float* Kb = g_K + (size_t)z * LL * HDIM;
    float* Sb = g_S + (size_t)z * LL * LL;
    const int q0 = blockIdx.y * 128;
    const int n0 = blockIdx.x * 128;

    const int t = threadIdx.x;
    const int warp = t >> 5;
    const int wm = (warp & 3) * 32;
    const int wn = (warp >> 2) * 64;

#pragma unroll
    for (int r = 0; r < 8; r++) {
        int idx = t + r * 256;
        int row = idx >> 4;
        int col = (idx & 15) << 2;
        *(float4*)(As + row * 68 + col) = *(const float4*)(Qb + (size_t)(q0 + row) * HDIM + col);
        *(float4*)(Bs + row * 68 + col) = *(const float4*)(Kb + (size_t)(n0 + row) * HDIM + col);
    }
    __syncthreads();

    FragC c[2][4];
#pragma unroll
    for (int i = 0; i < 2; i++)
#pragma unroll
        for (int j = 0; j < 4; j++) wmma::fill_fragment(c[i][j], 0.f);

#pragma unroll
    for (int kk = 0; kk < 64; kk += 8) {
        FragA a[2];
        FragBc b[4];
#pragma unroll
        for (int i = 0; i < 2; i++) { wmma::load_matrix_sync(a[i], As + (wm + i * 16) * 68 + kk, 68); cvt_a(a[i]); }
#pragma unroll
        for (int j = 0; j < 4; j++) { wmma::load_matrix_sync(b[j], Bs + (wn + j * 16) * 68 + kk, 68); cvt_bc(b[j]); }
#pragma unroll
        for (int i = 0; i < 2; i++)
#pragma unroll
            for (int j = 0; j < 4; j++) wmma::mma_sync(c[i][j], a[i], b[j], c[i][j]);
    }

    __syncthreads();   // done reading As/Bs -> reuse as staging
#pragma unroll
    for (int i = 0; i < 2; i++)
#pragma unroll
        for (int j = 0; j < 4; j++)
            wmma::store_matrix_sync(Cst + (wm + i * 16) * 132 + wn + j * 16, c[i][j],
                                    132, wmma::mem_row_major);
    __syncthreads();

#pragma unroll
    for (int r = 0; r < 16; r++) {
        int idx = t + r * 256;
        int row = idx >> 5;
        int col = (idx & 31) << 2;
        *(float4*)(Sb + (size_t)(q0 + row) * LL + n0 + col) = *(float4*)(Cst + row * 132 + col);
    }
}

// ---------------- fused: softmax + 3 diffusion steps + p@V -------------------------
__global__ __launch_bounds__(512) void fused_sda2(const int* __restrict__ mask,
                                                  const float* __restrict__ kw) {
    extern __shared__ float sm[];
    float* Ps = sm;                          // [16][PSTR]
    float* kvs = sm + FROWS * PSTR;          // [1536]
    float* Vs = kvs + LL;                    // [64][68] chunk / later reduce buf [4][16][68]
    float* w5s = Vs + 64 * 68;               // [5]

    const int t = threadIdx.x;
    const int warp = t >> 5, lane = t & 31;
    const size_t row0 = (size_t)blockIdx.x * FROWS;
    const int z = (int)(row0 / LL);
    const int q0 = (int)(row0 - (size_t)z * LL);
    const int b = z >> 4;
    const int h = z & 15;
    const int* mrow = mask + b * LL;
    const float* Vb = g_V + (size_t)z * LL * HDIM;

    if (t == 0) {
        float mxw = kw[0];
#pragma unroll
        for (int j = 1; j < 5; j++) mxw = fmaxf(mxw, kw[j]);
        float e[5], s = 0.f;
#pragma unroll
        for (int j = 0; j < 5; j++) { e[j] = __expf(kw[j] - mxw); s += e[j]; }
#pragma unroll
        for (int j = 0; j < 5; j++) w5s[j] = e[j] / s;
    }
    if (t < LL / 4) {
        int4 m4 = *(const int4*)(mrow + t * 4);
        *(float4*)(kvs + t * 4) = make_float4(m4.x > 0 ? 1.f : 0.f, m4.y > 0 ? 1.f : 0.f,
                                              m4.z > 0 ? 1.f : 0.f, m4.w > 0 ? 1.f : 0.f);
    }
    __syncthreads();

    const float w0 = w5s[0], w1 = w5s[1], w2 = w5s[2], w3 = w5s[3], w4 = w5s[4];
    const float4* kvs4 = (const float4*)kvs;

    // ---- phase 1: warp-per-row softmax + diffusion (register resident) ----
    {
        const float* prow = g_S + (row0 + warp) * LL;
        float4 p4[12];
        float mx = -3.4e38f;
#pragma unroll
        for (int k = 0; k < 12; k++) {
            int m = lane + 32 * k;
            float4 v = *(const float4*)(prow + (size_t)m * 4);
            float4 kv = kvs4[m];
            v.x += (kv.x > 0.f) ? 0.f : -1e9f;
            v.y += (kv.y > 0.f) ? 0.f : -1e9f;
            v.z += (kv.z > 0.f) ? 0.f : -1e9f;
            v.w += (kv.w > 0.f) ? 0.f : -1e9f;
            p4[k] = v;
            mx = fmaxf(mx, fmaxf(fmaxf(v.x, v.y), fmaxf(v.z, v.w)));
        }
#pragma unroll
        for (int o = 16; o; o >>= 1) mx = fmaxf(mx, __shfl_xor_sync(0xffffffffu, mx, o));

        float s = 0.f;
#pragma unroll
        for (int k = 0; k < 12; k++) {
            float4 v = p4[k];
            v.x = __expf(v.x - mx); v.y = __expf(v.y - mx);
            v.z = __expf(v.z - mx); v.w = __expf(v.w - mx);
            p4[k] = v;
            s += v.x + v.y + v.z + v.w;
        }
#pragma unroll
        for (int o = 16; o; o >>= 1) s += __shfl_xor_sync(0xffffffffu, s, o);
        float inv = 1.f / s;
#pragma unroll
        for (int k = 0; k < 12; k++) {
            p4[k].x *= inv; p4[k].y *= inv; p4[k].z *= inv; p4[k].w *= inv;
        }

#pragma unroll 1
        for (int step = 0; step < 3; step++) {
            float4 c4[12];
            float sa = 0.f;
            float4 prev31 = make_float4(0.f, 0.f, 0.f, 0.f);
#pragma unroll
            for (int k = 0; k < 12; k++) {
                float4 o4 = p4[k];
                float4 h4;
                h4.x = __shfl_up_sync(0xffffffffu, o4.x, 1);
                h4.y = __shfl_up_sync(0xffffffffu, o4.y, 1);
                h4.z = __shfl_up_sync(0xffffffffu, o4.z, 1);
                h4.w = __shfl_up_sync(0xffffffffu, o4.w, 1);
                float4 n31;
                n31.x = __shfl_sync(0xffffffffu, o4.x, 31);
                n31.y = __shfl_sync(0xffffffffu, o4.y, 31);
                n31.z = __shfl_sync(0xffffffffu, o4.z, 31);
                n31.w = __shfl_sync(0xffffffffu, o4.w, 31);
                if (lane == 0) h4 = prev31;
                prev31 = n31;
                float4 kv = kvs4[lane + 32 * k];
                float4 cc;
                cc.x = (w0 * h4.x + w1 * h4.y + w2 * h4.z + w3 * h4.w + w4 * o4.x) * kv.x;
                cc.y = (w0 * h4.y + w1 * h4.z + w2 * h4.w + w3 * o4.x + w4 * o4.y) * kv.y;
                cc.z = (w0 * h4.z + w1 * h4.w + w2 * o4.x + w3 * o4.y + w4 * o4.z) * kv.z;
                cc.w = (w0 * h4.w + w1 * o4.x + w2 * o4.y + w3 * o4.z + w4 * o4.w) * kv.w;
                c4[k] = cc;
                sa += cc.x + cc.y + cc.z + cc.w;
            }
#pragma unroll
            for (int o = 16; o; o >>= 1) sa += __shfl_xor_sync(0xffffffffu, sa, o);
            const float rmul = 0.02f / (sa + 1e-9f);
#pragma unroll
            for (int k = 0; k < 12; k++) {
                p4[k].x = 0.98f * p4[k].x + rmul * c4[k].x;
                p4[k].y = 0.98f * p4[k].y + rmul * c4[k].y;
                p4[k].z = 0.98f * p4[k].z + rmul * c4[k].z;
                p4[k].w = 0.98f * p4[k].w + rmul * c4[k].w;
            }
        }

        float* pr = Ps + warp * PSTR;
#pragma unroll
        for (int k = 0; k < 12; k++)
            *(float4*)(pr + (size_t)(lane + 32 * k) * 4) = p4[k];
    }
    __syncthreads();

    // ---- phase 2: out[16x64] = p[16x1536] @ V[1536x64], tf32 wmma ----
    const int g = warp >> 2;
    const int j = warp & 3;

    FragC acc;
    wmma::fill_fragment(acc, 0.f);

    const int vrow = t >> 4, vcol = (t & 15) << 2;
    float4 vpre[2];
#pragma unroll
    for (int r = 0; r < 2; r++)
        vpre[r] = *(const float4*)(Vb + (size_t)(vrow + r * 32) * HDIM + vcol);

    for (int c = 0; c < 24; c++) {
#pragma unroll
        for (int r = 0; r < 2; r++)
            *(float4*)(Vs + (vrow + r * 32) * 68 + vcol) = vpre[r];
        __syncthreads();
        if (c + 1 < 24) {
#pragma unroll
            for (int r = 0; r < 2; r++)
                vpre[r] = *(const float4*)(Vb + (size_t)((c + 1) * 64 + vrow + r * 32) * HDIM + vcol);
        }
#pragma unroll
        for (int kk = 0; kk < 16; kk += 8) {
            FragA a;
            FragB bb;
            wmma::load_matrix_sync(a, Ps + c * 64 + g * 16 + kk, PSTR);
            cvt_a(a);
            wmma::load_matrix_sync(bb, Vs + (g * 16 + kk) * 68 + j * 16, 68);
            cvt_b(bb);
            wmma::mma_sync(acc, a, bb, acc);
        }
        __syncthreads();
    }

    wmma::store_matrix_sync(Vs + (g * 16) * 68 + j * 16, acc, 68, wmma::mem_row_major);
    __syncthreads();

    if (t < 128) {
        const int row = t >> 3;
        const int col = (t & 7) << 3;
        float* o0 = Vs + row * 68 + col;
        float4 s0 = *(float4*)o0;
        float4 s1 = *(float4*)(o0 + 4);
#pragma unroll
        for (int gg = 1; gg < 4; gg++) {
            float* og = Vs + (gg * 16 + row) * 68 + col;
            float4 a0 = *(float4*)og;
            float4 a1 = *(float4*)(og + 4);
            s0.x += a0.x; s0.y += a0.y; s0.z += a0.z; s0.w += a0.w;
            s1.x += a1.x; s1.y += a1.y; s1.z += a1.z; s1.w += a1.w;
        }
        float* out = g_attn + ((size_t)(b * LL + q0 + row)) * PP + h * 64 + col;
        *(float4*)out = s0;
        *(float4*)(out + 4) = s1;
    }
}

// ---------------- launch ----------------
extern "C" void kernel_launch(void* const* d_in, const int* in_sizes, int n_in,
                              void* d_out, int out_size) {
    const float* hs = (const float*)d_in[0];
    const int* mask = (const int*)d_in[1];
    const float* Wq = (const float*)d_in[2];
    const float* bq = (const float*)d_in[3];
    const float* Wk = (const float*)d_in[4];
    const float* bk = (const float*)d_in[5];
    const float* Wv = (const float*)d_in[6];
    const float* bv = (const float*)d_in[7];
    const float* Wo = (const float*)d_in[8];
    const float* bo = (const float*)d_in[9];
    const float* kw = (const float*)d_in[10];

    cudaFuncSetAttribute(scores_wmma, cudaFuncAttributeMaxDynamicSharedMemorySize, SCORES_SMEM_BYTES);
    cudaFuncSetAttribute(fused_sda2, cudaFuncAttributeMaxDynamicSharedMemorySize, FUSED_SMEM_BYTES);

    qkv_wmma<<<dim3(PP / 128, (BB * LL) / 64, 3), 256>>>(hs, Wq, bq, Wk, bk, Wv, bv);

    scores_wmma<<<dim3(LL / 128, LL / 128, BB * HH), 256, SCORES_SMEM_BYTES>>>();

    fused_sda2<<<(BB * HH * LL) / FROWS, 512, FUSED_SMEM_BYTES>>>(mask, kw);

    oproj_wmma<<<dim3(PP / 128, (BB * LL) / 64), 256>>>(Wo, bo, (float*)d_out);
}

// round 7
// speedup vs baseline: 1.3399x; 1.0014x over previous
#include <cuda_runtime.h>
#include <mma.h>
using namespace nvcuda;

#define BB 2
#define LL 1536
#define DD 1024
#define HH 16
#define PP 1024
#define HDIM 64

#define SCORES_SMEM_BYTES (2 * 128 * 68 * 4)          // 69632 (As+Bs; reused as C staging)

// fused kernel smem
#define FROWS 16
#define PSTR 1540
#define FUSED_SMEM_FLOATS (FROWS * PSTR + LL + 64 * 68 + 8)
#define FUSED_SMEM_BYTES (FUSED_SMEM_FLOATS * 4)      // ~122 KB

// ---------------- device scratch ----------------
__device__ float g_Q[BB * HH * LL * HDIM];      // head-major [b,h,l,d], pre-scaled by 0.125
__device__ float g_K[BB * HH * LL * HDIM];
__device__ float g_V[BB * HH * LL * HDIM];
__device__ float g_attn[BB * LL * PP];          // [b,l,h*64+d]
__device__ float g_S[BB * HH * LL * LL];        // scores

typedef wmma::fragment<wmma::matrix_a, 16, 16, 8, wmma::precision::tf32, wmma::row_major> FragA;
typedef wmma::fragment<wmma::matrix_b, 16, 16, 8, wmma::precision::tf32, wmma::row_major> FragB;
typedef wmma::fragment<wmma::matrix_b, 16, 16, 8, wmma::precision::tf32, wmma::col_major> FragBc;
typedef wmma::fragment<wmma::accumulator, 16, 16, 8, float> FragC;

// convert a float4 to tf32 bit-pattern floats (RN) — done ONCE at SMEM staging
__device__ __forceinline__ float4 tf4(float4 v) {
    v.x = wmma::__float_to_tf32(v.x);
    v.y = wmma::__float_to_tf32(v.y);
    v.z = wmma::__float_to_tf32(v.z);
    v.w = wmma::__float_to_tf32(v.w);
    return v;
}

// ---------------- 64x128-tile projection GEMM body (tf32 staged in SMEM) ----------------
// mode 0: Q (head-major, x0.125)  1: K head-major  2: V head-major  3: flat to Cout
__device__ __forceinline__ void gemm64_body(const float* __restrict__ A,
                                            const float* __restrict__ W,
                                            const float* __restrict__ bias,
                                            float* __restrict__ C, int mode) {
    __shared__ float As[64][36];
    __shared__ float Bs[32][132];
    __shared__ float BiasT[16][132];

    const int m0 = blockIdx.y * 64;
    const int n0 = blockIdx.x * 128;
    const int t = threadIdx.x;
    const int warp = t >> 5;
    const int wm = (warp & 3) * 16;
    const int wn = (warp >> 2) * 64;

#pragma unroll
    for (int r = 0; r < 2; r++) {
        int idx = t + r * 256;
        int row = idx >> 5;
        int col = (idx & 31) << 2;
        *(float4*)&BiasT[row][col] = *(const float4*)(bias + n0 + col);
    }

    FragC c[4];
#pragma unroll
    for (int j = 0; j < 4; j++) wmma::fill_fragment(c[j], 0.f);

    const int arow = t >> 3, acol = (t & 7) << 2;      // A: 512 float4, 2/thread
    const int brow = t >> 5, bcol = (t & 31) << 2;     // B: 1024 float4, 4/thread

    float4 apre[2], bpre[4];
#pragma unroll
    for (int r = 0; r < 2; r++)
        apre[r] = *(const float4*)(A + (size_t)(m0 + arow + r * 32) * DD + acol);
#pragma unroll
    for (int r = 0; r < 4; r++)
        bpre[r] = *(const float4*)(W + (size_t)(brow + r * 8) * PP + n0 + bcol);

    for (int k0 = 0; k0 < DD; k0 += 32) {
#pragma unroll
        for (int r = 0; r < 2; r++) *(float4*)&As[arow + r * 32][acol] = tf4(apre[r]);
#pragma unroll
        for (int r = 0; r < 4; r++) *(float4*)&Bs[brow + r * 8][bcol] = tf4(bpre[r]);
        __syncthreads();
        if (k0 + 32 < DD) {
#pragma unroll
            for (int r = 0; r < 2; r++)
                apre[r] = *(const float4*)(A + (size_t)(m0 + arow + r * 32) * DD + k0 + 32 + acol);
#pragma unroll
            for (int r = 0; r < 4; r++)
                bpre[r] = *(const float4*)(W + (size_t)(k0 + 32 + brow + r * 8) * PP + n0 + bcol);
        }
#pragma unroll
        for (int kk = 0; kk < 32; kk += 8) {
            FragA a;
            wmma::load_matrix_sync(a, &As[wm][kk], 36);
#pragma unroll
            for (int j = 0; j < 4; j++) {
                FragB b;
                wmma::load_matrix_sync(b, &Bs[kk][wn + j * 16], 132);
                wmma::mma_sync(c[j], a, b, c[j]);
            }
        }
        __syncthreads();
    }

    const float scale = (mode == 0) ? 0.125f : 1.0f;
#pragma unroll
    for (int j = 0; j < 4; j++) {
        FragC bf;
        wmma::load_matrix_sync(bf, &BiasT[0][wn + j * 16], 132, wmma::mem_row_major);
#pragma unroll
        for (int e = 0; e < bf.num_elements; e++) c[j].x[e] = (c[j].x[e] + bf.x[e]) * scale;
    }

    if (mode <= 2) {
        const int b = m0 / LL;
        const int l0 = m0 - b * LL;
        const int h = (n0 + wn) >> 6;
        float* base = C + (((size_t)(b * HH + h)) * LL + l0 + wm) * HDIM;
#pragma unroll
        for (int j = 0; j < 4; j++)
            wmma::store_matrix_sync(base + j * 16, c[j], HDIM, wmma::mem_row_major);
    } else {
        float* base = C + (size_t)(m0 + wm) * PP + n0 + wn;
#pragma unroll
        for (int j = 0; j < 4; j++)
            wmma::store_matrix_sync(base + j * 16, c[j], PP, wmma::mem_row_major);
    }
}

__global__ __launch_bounds__(256, 2) void qkv_wmma(const float* __restrict__ A,
                                                   const float* __restrict__ Wq,
                                                   const float* __restrict__ bq,
                                                   const float* __restrict__ Wk,
                                                   const float* __restrict__ bk,
                                                   const float* __restrict__ Wv,
                                                   const float* __restrict__ bv) {
    const int zz = blockIdx.z;
    const float* W = (zz == 0) ? Wq : (zz == 1) ? Wk : Wv;
    const float* bias = (zz == 0) ? bq : (zz == 1) ? bk : bv;
    float* C = (zz == 0) ? g_Q : (zz == 1) ? g_K : g_V;
    gemm64_body(A, W, bias, C, zz);
}

__global__ __launch_bounds__(256, 2) void oproj_wmma(const float* __restrict__ W,
                                                     const float* __restrict__ bias,
                                                     float* __restrict__ Cout) {
    gemm64_body(g_attn, W, bias, Cout, 3);
}

// ---------------- scores: K-dim resident (tf32 staged), staged float4 store ----------------
// Q is pre-scaled by 0.125 in projection.
__global__ __launch_bounds__(256, 2) void scores_wmma() {
    extern __shared__ float sm2[];
    float* As = sm2;              // [128][68]  Q (tf32)
    float* Bs = sm2 + 128 * 68;   // [128][68]  K (tf32)
    float* Cst = sm2;             // staging [128][132] (reuses As+Bs)

    const int z = blockIdx.z;
    const float* Qb = g_Q + (size_t)z * LL * HDIM;
    const float* Kb = g_K + (size_t)z * LL * HDIM;
    float* Sb = g_S + (size_t)z * LL * LL;
    const int q0 = blockIdx.y * 128;
    const int n0 = blockIdx.x * 128;

    const int t = threadIdx.x;
    const int warp = t >> 5;
    const int wm = (warp & 3) * 32;
    const int wn = (warp >> 2) * 64;

#pragma unroll
    for (int r = 0; r < 8; r++) {
        int idx = t + r * 256;
        int row = idx >> 4;
        int col = (idx & 15) << 2;
        *(float4*)(As + row * 68 + col) = tf4(*(const float4*)(Qb + (size_t)(q0 + row) * HDIM + col));
        *(float4*)(Bs + row * 68 + col) = tf4(*(const float4*)(Kb + (size_t)(n0 + row) * HDIM + col));
    }
    __syncthreads();

    FragC c[2][4];
#pragma unroll
    for (int i = 0; i < 2; i++)
#pragma unroll
        for (int j = 0; j < 4; j++) wmma::fill_fragment(c[i][j], 0.f);

#pragma unroll
    for (int kk = 0; kk < 64; kk += 8) {
        FragA a[2];
        FragBc b[4];
#pragma unroll
        for (int i = 0; i < 2; i++) wmma::load_matrix_sync(a[i], As + (wm + i * 16) * 68 + kk, 68);
#pragma unroll
        for (int j = 0; j < 4; j++) wmma::load_matrix_sync(b[j], Bs + (wn + j * 16) * 68 + kk, 68);
#pragma unroll
        for (int i = 0; i < 2; i++)
#pragma unroll
            for (int j = 0; j < 4; j++) wmma::mma_sync(c[i][j], a[i], b[j], c[i][j]);
    }

    __syncthreads();   // done reading As/Bs -> reuse as staging
#pragma unroll
    for (int i = 0; i < 2; i++)
#pragma unroll
        for (int j = 0; j < 4; j++)
            wmma::store_matrix_sync(Cst + (wm + i * 16) * 132 + wn + j * 16, c[i][j],
                                    132, wmma::mem_row_major);
    __syncthreads();

#pragma unroll
    for (int r = 0; r < 16; r++) {
        int idx = t + r * 256;
        int row = idx >> 5;
        int col = (idx & 31) << 2;
        *(float4*)(Sb + (size_t)(q0 + row) * LL + n0 + col) = *(float4*)(Cst + row * 132 + col);
    }
}

// ---------------- fused: softmax + 3 diffusion steps + p@V -------------------------
__global__ __launch_bounds__(512) void fused_sda2(const int* __restrict__ mask,
                                                  const float* __restrict__ kw) {
    extern __shared__ float sm[];
    float* Ps = sm;                          // [16][PSTR] (tf32 after phase 1)
    float* kvs = sm + FROWS * PSTR;          // [1536]
    float* Vs = kvs + LL;                    // [64][68] chunk (tf32) / reduce buf [4][16][68]
    float* w5s = Vs + 64 * 68;               // [5]

    const int t = threadIdx.x;
    const int warp = t >> 5, lane = t & 31;
    const size_t row0 = (size_t)blockIdx.x * FROWS;
    const int z = (int)(row0 / LL);
    const int q0 = (int)(row0 - (size_t)z * LL);
    const int b = z >> 4;
    const int h = z & 15;
    const int* mrow = mask + b * LL;
    const float* Vb = g_V + (size_t)z * LL * HDIM;

    if (t == 0) {
        float mxw = kw[0];
#pragma unroll
        for (int j = 1; j < 5; j++) mxw = fmaxf(mxw, kw[j]);
        float e[5], s = 0.f;
#pragma unroll
        for (int j = 0; j < 5; j++) { e[j] = __expf(kw[j] - mxw); s += e[j]; }
#pragma unroll
        for (int j = 0; j < 5; j++) w5s[j] = e[j] / s;
    }
    if (t < LL / 4) {
        int4 m4 = *(const int4*)(mrow + t * 4);
        *(float4*)(kvs + t * 4) = make_float4(m4.x > 0 ? 1.f : 0.f, m4.y > 0 ? 1.f : 0.f,
                                              m4.z > 0 ? 1.f : 0.f, m4.w > 0 ? 1.f : 0.f);
    }
    __syncthreads();

    const float w0 = w5s[0], w1 = w5s[1], w2 = w5s[2], w3 = w5s[3], w4 = w5s[4];
    const float4* kvs4 = (const float4*)kvs;

    // ---- phase 1: warp-per-row softmax + diffusion (register resident) ----
    {
        const float* prow = g_S + (row0 + warp) * LL;
        float4 p4[12];
        float mx = -3.4e38f;
#pragma unroll
        for (int k = 0; k < 12; k++) {
            int m = lane + 32 * k;
            float4 v = *(const float4*)(prow + (size_t)m * 4);
            float4 kv = kvs4[m];
            v.x += (kv.x > 0.f) ? 0.f : -1e9f;
            v.y += (kv.y > 0.f) ? 0.f : -1e9f;
            v.z += (kv.z > 0.f) ? 0.f : -1e9f;
            v.w += (kv.w > 0.f) ? 0.f : -1e9f;
            p4[k] = v;
            mx = fmaxf(mx, fmaxf(fmaxf(v.x, v.y), fmaxf(v.z, v.w)));
        }
#pragma unroll
        for (int o = 16; o; o >>= 1) mx = fmaxf(mx, __shfl_xor_sync(0xffffffffu, mx, o));

        float s = 0.f;
#pragma unroll
        for (int k = 0; k < 12; k++) {
            float4 v = p4[k];
            v.x = __expf(v.x - mx); v.y = __expf(v.y - mx);
            v.z = __expf(v.z - mx); v.w = __expf(v.w - mx);
            p4[k] = v;
            s += v.x + v.y + v.z + v.w;
        }
#pragma unroll
        for (int o = 16; o; o >>= 1) s += __shfl_xor_sync(0xffffffffu, s, o);
        float inv = 1.f / s;
#pragma unroll
        for (int k = 0; k < 12; k++) {
            p4[k].x *= inv; p4[k].y *= inv; p4[k].z *= inv; p4[k].w *= inv;
        }

#pragma unroll 1
        for (int step = 0; step < 3; step++) {
            float4 c4[12];
            float sa = 0.f;
            float4 prev31 = make_float4(0.f, 0.f, 0.f, 0.f);
#pragma unroll
            for (int k = 0; k < 12; k++) {
                float4 o4 = p4[k];
                float4 h4;
                h4.x = __shfl_up_sync(0xffffffffu, o4.x, 1);
                h4.y = __shfl_up_sync(0xffffffffu, o4.y, 1);
                h4.z = __shfl_up_sync(0xffffffffu, o4.z, 1);
                h4.w = __shfl_up_sync(0xffffffffu, o4.w, 1);
                float4 n31;
                n31.x = __shfl_sync(0xffffffffu, o4.x, 31);
                n31.y = __shfl_sync(0xffffffffu, o4.y, 31);
                n31.z = __shfl_sync(0xffffffffu, o4.z, 31);
                n31.w = __shfl_sync(0xffffffffu, o4.w, 31);
                if (lane == 0) h4 = prev31;
                prev31 = n31;
                float4 kv = kvs4[lane + 32 * k];
                float4 cc;
                cc.x = (w0 * h4.x + w1 * h4.y + w2 * h4.z + w3 * h4.w + w4 * o4.x) * kv.x;
                cc.y = (w0 * h4.y + w1 * h4.z + w2 * h4.w + w3 * o4.x + w4 * o4.y) * kv.y;
                cc.z = (w0 * h4.z + w1 * h4.w + w2 * o4.x + w3 * o4.y + w4 * o4.z) * kv.z;
                cc.w = (w0 * h4.w + w1 * o4.x + w2 * o4.y + w3 * o4.z + w4 * o4.w) * kv.w;
                c4[k] = cc;
                sa += cc.x + cc.y + cc.z + cc.w;
            }
#pragma unroll
            for (int o = 16; o; o >>= 1) sa += __shfl_xor_sync(0xffffffffu, sa, o);
            const float rmul = 0.02f / (sa + 1e-9f);
#pragma unroll
            for (int k = 0; k < 12; k++) {
                p4[k].x = 0.98f * p4[k].x + rmul * c4[k].x;
                p4[k].y = 0.98f * p4[k].y + rmul * c4[k].y;
                p4[k].z = 0.98f * p4[k].z + rmul * c4[k].z;
                p4[k].w = 0.98f * p4[k].w + rmul * c4[k].w;
            }
        }

        // stage p row into SMEM, tf32-converted for phase 2 MMA
        float* pr = Ps + warp * PSTR;
#pragma unroll
        for (int k = 0; k < 12; k++)
            *(float4*)(pr + (size_t)(lane + 32 * k) * 4) = tf4(p4[k]);
    }
    __syncthreads();

    // ---- phase 2: out[16x64] = p[16x1536] @ V[1536x64], tf32 wmma ----
    const int g = warp >> 2;
    const int j = warp & 3;

    FragC acc;
    wmma::fill_fragment(acc, 0.f);

    const int vrow = t >> 4, vcol = (t & 15) << 2;
    float4 vpre[2];
#pragma unroll
    for (int r = 0; r < 2; r++)
        vpre[r] = *(const float4*)(Vb + (size_t)(vrow + r * 32) * HDIM + vcol);

    for (int c = 0; c < 24; c++) {
#pragma unroll
        for (int r = 0; r < 2; r++)
            *(float4*)(Vs + (vrow + r * 32) * 68 + vcol) = tf4(vpre[r]);
        __syncthreads();
        if (c + 1 < 24) {
#pragma unroll
            for (int r = 0; r < 2; r++)
                vpre[r] = *(const float4*)(Vb + (size_t)((c + 1) * 64 + vrow + r * 32) * HDIM + vcol);
        }
#pragma unroll
        for (int kk = 0; kk < 16; kk += 8) {
            FragA a;
            FragB bb;
            wmma::load_matrix_sync(a, Ps + c * 64 + g * 16 + kk, PSTR);
            wmma::load_matrix_sync(bb, Vs + (g * 16 + kk) * 68 + j * 16, 68);
            wmma::mma_sync(acc, a, bb, acc);
        }
        __syncthreads();
    }

    wmma::store_matrix_sync(Vs + (g * 16) * 68 + j * 16, acc, 68, wmma::mem_row_major);
    __syncthreads();

    if (t < 128) {
        const int row = t >> 3;
        const int col = (t & 7) << 3;
        float* o0 = Vs + row * 68 + col;
        float4 s0 = *(float4*)o0;
        float4 s1 = *(float4*)(o0 + 4);
#pragma unroll
        for (int gg = 1; gg < 4; gg++) {
            float* og = Vs + (gg * 16 + row) * 68 + col;
            float4 a0 = *(float4*)og;
            float4 a1 = *(float4*)(og + 4);
            s0.x += a0.x; s0.y += a0.y; s0.z += a0.z; s0.w += a0.w;
            s1.x += a1.x; s1.y += a1.y; s1.z += a1.z; s1.w += a1.w;
        }
        float* out = g_attn + ((size_t)(b * LL + q0 + row)) * PP + h * 64 + col;
        *(float4*)out = s0;
        *(float4*)(out + 4) = s1;
    }
}

// ---------------- launch ----------------
extern "C" void kernel_launch(void* const* d_in, const int* in_sizes, int n_in,
                              void* d_out, int out_size) {
    const float* hs = (const float*)d_in[0];
    const int* mask = (const int*)d_in[1];
    const float* Wq = (const float*)d_in[2];
    const float* bq = (const float*)d_in[3];
    const float* Wk = (const float*)d_in[4];
    const float* bk = (const float*)d_in[5];
    const float* Wv = (const float*)d_in[6];
    const float* bv = (const float*)d_in[7];
    const float* Wo = (const float*)d_in[8];
    const float* bo = (const float*)d_in[9];
    const float* kw = (const float*)d_in[10];

    cudaFuncSetAttribute(scores_wmma, cudaFuncAttributeMaxDynamicSharedMemorySize, SCORES_SMEM_BYTES);
    cudaFuncSetAttribute(fused_sda2, cudaFuncAttributeMaxDynamicSharedMemorySize, FUSED_SMEM_BYTES);

    qkv_wmma<<<dim3(PP / 128, (BB * LL) / 64, 3), 256>>>(hs, Wq, bq, Wk, bk, Wv, bv);

    scores_wmma<<<dim3(LL / 128, LL / 128, BB * HH), 256, SCORES_SMEM_BYTES>>>();

    fused_sda2<<<(BB * HH * LL) / FROWS, 512, FUSED_SMEM_BYTES>>>(mask, kw);

    oproj_wmma<<<dim3(PP / 128, (BB * LL) / 64), 256>>>(Wo, bo, (float*)d_out);
}

// round 8
// speedup vs baseline: 1.9664x; 1.4676x over previous
#include <cuda_runtime.h>
#include <cuda_fp16.h>
#include <mma.h>
using namespace nvcuda;

#define BB 2
#define LL 1536
#define DD 1024
#define HH 16
#define PP 1024
#define HDIM 64

#define SCORES_SMEM_BYTES 69632        // max(half tiles 36864, float staging 67584)

// fused kernel smem layout (bytes)
#define FROWS 16
#define PSTR_H 1544                    // halves per p row (3088 B, 16B aligned)
#define F_PS_BYTES (FROWS * PSTR_H * 2)        // 49408
#define F_KVS_OFF  F_PS_BYTES                  // float kvs[1536] -> 6144 B
#define F_VS_OFF   (F_KVS_OFF + LL * 4)        // V chunk (half 64x72=9216B) / reduce (float 4*16*68=17408B)
#define FUSED_SMEM_BYTES (F_VS_OFF + 17408 + 32)

// ---------------- device scratch ----------------
__device__ float g_Q[BB * HH * LL * HDIM];      // head-major [b,h,l,d], pre-scaled by 0.125
__device__ float g_K[BB * HH * LL * HDIM];
__device__ float g_V[BB * HH * LL * HDIM];
__device__ float g_attn[BB * LL * PP];          // [b,l,h*64+d]
__device__ float g_S[BB * HH * LL * LL];        // scores

typedef wmma::fragment<wmma::matrix_a, 16, 16, 16, __half, wmma::row_major> HFragA;
typedef wmma::fragment<wmma::matrix_b, 16, 16, 16, __half, wmma::row_major> HFragB;
typedef wmma::fragment<wmma::matrix_b, 16, 16, 16, __half, wmma::col_major> HFragBc;
typedef wmma::fragment<wmma::accumulator, 16, 16, 16, float> FragC;

// float4 -> 4 halves (RN), packed as uint2 for an 8-byte SMEM store
__device__ __forceinline__ uint2 h4(float4 v) {
    __half2 a = __floats2half2_rn(v.x, v.y);
    __half2 b = __floats2half2_rn(v.z, v.w);
    uint2 r;
    r.x = *(unsigned*)&a;
    r.y = *(unsigned*)&b;
    return r;
}

// ---------------- 64x128-tile projection GEMM body (fp16 staged in SMEM) ----------------
// mode 0: Q (head-major, x0.125)  1: K head-major  2: V head-major  3: flat to Cout
__device__ __forceinline__ void gemm64_body(const float* __restrict__ A,
                                            const float* __restrict__ W,
                                            const float* __restrict__ bias,
                                            float* __restrict__ C, int mode) {
    __shared__ __half As[64][40];
    __shared__ __half Bs[32][136];
    __shared__ float BiasT[16][132];

    const int m0 = blockIdx.y * 64;
    const int n0 = blockIdx.x * 128;
    const int t = threadIdx.x;
    const int warp = t >> 5;
    const int wm = (warp & 3) * 16;
    const int wn = (warp >> 2) * 64;

#pragma unroll
    for (int r = 0; r < 2; r++) {
        int idx = t + r * 256;
        int row = idx >> 5;
        int col = (idx & 31) << 2;
        *(float4*)&BiasT[row][col] = *(const float4*)(bias + n0 + col);
    }

    FragC c[4];
#pragma unroll
    for (int j = 0; j < 4; j++) wmma::fill_fragment(c[j], 0.f);

    const int arow = t >> 3, acol = (t & 7) << 2;      // A: 512 float4, 2/thread
    const int brow = t >> 5, bcol = (t & 31) << 2;     // B: 1024 float4, 4/thread

    float4 apre[2], bpre[4];
#pragma unroll
    for (int r = 0; r < 2; r++)
        apre[r] = *(const float4*)(A + (size_t)(m0 + arow + r * 32) * DD + acol);
#pragma unroll
    for (int r = 0; r < 4; r++)
        bpre[r] = *(const float4*)(W + (size_t)(brow + r * 8) * PP + n0 + bcol);

    for (int k0 = 0; k0 < DD; k0 += 32) {
#pragma unroll
        for (int r = 0; r < 2; r++) *(uint2*)&As[arow + r * 32][acol] = h4(apre[r]);
#pragma unroll
        for (int r = 0; r < 4; r++) *(uint2*)&Bs[brow + r * 8][bcol] = h4(bpre[r]);
        __syncthreads();
        if (k0 + 32 < DD) {
#pragma unroll
            for (int r = 0; r < 2; r++)
                apre[r] = *(const float4*)(A + (size_t)(m0 + arow + r * 32) * DD + k0 + 32 + acol);
#pragma unroll
            for (int r = 0; r < 4; r++)
                bpre[r] = *(const float4*)(W + (size_t)(k0 + 32 + brow + r * 8) * PP + n0 + bcol);
        }
#pragma unroll
        for (int kk = 0; kk < 32; kk += 16) {
            HFragA a;
            wmma::load_matrix_sync(a, &As[wm][kk], 40);
#pragma unroll
            for (int j = 0; j < 4; j++) {
                HFragB b;
                wmma::load_matrix_sync(b, &Bs[kk][wn + j * 16], 136);
                wmma::mma_sync(c[j], a, b, c[j]);
            }
        }
        __syncthreads();
    }

    const float scale = (mode == 0) ? 0.125f : 1.0f;
#pragma unroll
    for (int j = 0; j < 4; j++) {
        FragC bf;
        wmma::load_matrix_sync(bf, &BiasT[0][wn + j * 16], 132, wmma::mem_row_major);
#pragma unroll
        for (int e = 0; e < bf.num_elements; e++) c[j].x[e] = (c[j].x[e] + bf.x[e]) * scale;
    }

    if (mode <= 2) {
        const int b = m0 / LL;
        const int l0 = m0 - b * LL;
        const int h = (n0 + wn) >> 6;
        float* base = C + (((size_t)(b * HH + h)) * LL + l0 + wm) * HDIM;
#pragma unroll
        for (int j = 0; j < 4; j++)
            wmma::store_matrix_sync(base + j * 16, c[j], HDIM, wmma::mem_row_major);
    } else {
        float* base = C + (size_t)(m0 + wm) * PP + n0 + wn;
#pragma unroll
        for (int j = 0; j < 4; j++)
            wmma::store_matrix_sync(base + j * 16, c[j], PP, wmma::mem_row_major);
    }
}

__global__ __launch_bounds__(256, 2) void qkv_wmma(const float* __restrict__ A,
                                                   const float* __restrict__ Wq,
                                                   const float* __restrict__ bq,
                                                   const float* __restrict__ Wk,
                                                   const float* __restrict__ bk,
                                                   const float* __restrict__ Wv,
                                                   const float* __restrict__ bv) {
    const int zz = blockIdx.z;
    const float* W = (zz == 0) ? Wq : (zz == 1) ? Wk : Wv;
    const float* bias = (zz == 0) ? bq : (zz == 1) ? bk : bv;
    float* C = (zz == 0) ? g_Q : (zz == 1) ? g_K : g_V;
    gemm64_body(A, W, bias, C, zz);
}

__global__ __launch_bounds__(256, 2) void oproj_wmma(const float* __restrict__ W,
                                                     const float* __restrict__ bias,
                                                     float* __restrict__ Cout) {
    gemm64_body(g_attn, W, bias, Cout, 3);
}

// ---------------- scores: K-dim resident (fp16 staged), staged float4 store ----------------
// Q is pre-scaled by 0.125 in projection.
__global__ __launch_bounds__(256, 2) void scores_wmma() {
    extern __shared__ char sm2raw[];
    __half* As = (__half*)sm2raw;              // [128][72]  Q (half)
    __half* Bs = As + 128 * 72;                // [128][72]  K (half)
    float* Cst = (float*)sm2raw;               // staging [128][132] (reuses all)

    const int z = blockIdx.z;
    const float* Qb = g_Q + (size_t)z * LL * HDIM;
    const float* Kb = g_K + (size_t)z * LL * HDIM;
    float* Sb = g_S + (size_t)z * LL * LL;
    const int q0 = blockIdx.y * 128;
    const int n0 = blockIdx.x * 128;

    const int t = threadIdx.x;
    const int warp = t >> 5;
    const int wm = (warp & 3) * 32;
    const int wn = (warp >> 2) * 64;

#pragma unroll
    for (int r = 0; r < 8; r++) {
        int idx = t + r * 256;
        int row = idx >> 4;
        int col = (idx & 15) << 2;
        *(uint2*)(As + row * 72 + col) = h4(*(const float4*)(Qb + (size_t)(q0 + row) * HDIM + col));
        *(uint2*)(Bs + row * 72 + col) = h4(*(const float4*)(Kb + (size_t)(n0 + row) * HDIM + col));
    }
    __syncthreads();

    FragC c[2][4];
#pragma unroll
    for (int i = 0; i < 2; i++)
#pragma unroll
        for (int j = 0; j < 4; j++) wmma::fill_fragment(c[i][j], 0.f);

#pragma unroll
    for (int kk = 0; kk < 64; kk += 16) {
        HFragA a[2];
        HFragBc b[4];
#pragma unroll
        for (int i = 0; i < 2; i++) wmma::load_matrix_sync(a[i], As + (wm + i * 16) * 72 + kk, 72);
#pragma unroll
        for (int j = 0; j < 4; j++) wmma::load_matrix_sync(b[j], Bs + (wn + j * 16) * 72 + kk, 72);
#pragma unroll
        for (int i = 0; i < 2; i++)
#pragma unroll
            for (int j = 0; j < 4; j++) wmma::mma_sync(c[i][j], a[i], b[j], c[i][j]);
    }

    __syncthreads();   // done reading As/Bs -> reuse as float staging
#pragma unroll
    for (int i = 0; i < 2; i++)
#pragma unroll
        for (int j = 0; j < 4; j++)
            wmma::store_matrix_sync(Cst + (wm + i * 16) * 132 + wn + j * 16, c[i][j],
                                    132, wmma::mem_row_major);
    __syncthreads();

#pragma unroll
    for (int r = 0; r < 16; r++) {
        int idx = t + r * 256;
        int row = idx >> 5;
        int col = (idx & 31) << 2;
        *(float4*)(Sb + (size_t)(q0 + row) * LL + n0 + col) = *(float4*)(Cst + row * 132 + col);
    }
}

// ---------------- fused: softmax + 3 diffusion steps + p@V (fp16 phase 2) ------------
__global__ __launch_bounds__(512, 2) void fused_sda2(const int* __restrict__ mask,
                                                     const float* __restrict__ kw) {
    extern __shared__ char smraw[];
    __half* Ps = (__half*)smraw;                       // [16][PSTR_H] halves
    float* kvs = (float*)(smraw + F_KVS_OFF);          // [1536]
    __half* Vs = (__half*)(smraw + F_VS_OFF);          // [64][72] halves (V chunk)
    float* Vred = (float*)(smraw + F_VS_OFF);          // [4][16][68] floats (reduce)
    float* w5s = (float*)(smraw + F_VS_OFF + 17408);   // [5]

    const int t = threadIdx.x;
    const int warp = t >> 5, lane = t & 31;
    const size_t row0 = (size_t)blockIdx.x * FROWS;
    const int z = (int)(row0 / LL);
    const int q0 = (int)(row0 - (size_t)z * LL);
    const int b = z >> 4;
    const int h = z & 15;
    const int* mrow = mask + b * LL;
    const float* Vb = g_V + (size_t)z * LL * HDIM;

    if (t == 0) {
        float mxw = kw[0];
#pragma unroll
        for (int j = 1; j < 5; j++) mxw = fmaxf(mxw, kw[j]);
        float e[5], s = 0.f;
#pragma unroll
        for (int j = 0; j < 5; j++) { e[j] = __expf(kw[j] - mxw); s += e[j]; }
#pragma unroll
        for (int j = 0; j < 5; j++) w5s[j] = e[j] / s;
    }
    if (t < LL / 4) {
        int4 m4 = *(const int4*)(mrow + t * 4);
        *(float4*)(kvs + t * 4) = make_float4(m4.x > 0 ? 1.f : 0.f, m4.y > 0 ? 1.f : 0.f,
                                              m4.z > 0 ? 1.f : 0.f, m4.w > 0 ? 1.f : 0.f);
    }
    __syncthreads();

    const float w0 = w5s[0], w1 = w5s[1], w2 = w5s[2], w3 = w5s[3], w4 = w5s[4];
    const float4* kvs4 = (const float4*)kvs;

    // ---- phase 1: warp-per-row softmax + diffusion (register resident) ----
    {
        const float* prow = g_S + (row0 + warp) * LL;
        float4 p4[12];
        float mx = -3.4e38f;
#pragma unroll
        for (int k = 0; k < 12; k++) {
            int m = lane + 32 * k;
            float4 v = *(const float4*)(prow + (size_t)m * 4);
            float4 kv = kvs4[m];
            v.x += (kv.x > 0.f) ? 0.f : -1e9f;
            v.y += (kv.y > 0.f) ? 0.f : -1e9f;
            v.z += (kv.z > 0.f) ? 0.f : -1e9f;
            v.w += (kv.w > 0.f) ? 0.f : -1e9f;
            p4[k] = v;
            mx = fmaxf(mx, fmaxf(fmaxf(v.x, v.y), fmaxf(v.z, v.w)));
        }
#pragma unroll
        for (int o = 16; o; o >>= 1) mx = fmaxf(mx, __shfl_xor_sync(0xffffffffu, mx, o));

        float s = 0.f;
#pragma unroll
        for (int k = 0; k < 12; k++) {
            float4 v = p4[k];
            v.x = __expf(v.x - mx); v.y = __expf(v.y - mx);
            v.z = __expf(v.z - mx); v.w = __expf(v.w - mx);
            p4[k] = v;
            s += v.x + v.y + v.z + v.w;
        }
#pragma unroll
        for (int o = 16; o; o >>= 1) s += __shfl_xor_sync(0xffffffffu, s, o);
        float inv = 1.f / s;
#pragma unroll
        for (int k = 0; k < 12; k++) {
            p4[k].x *= inv; p4[k].y *= inv; p4[k].z *= inv; p4[k].w *= inv;
        }

#pragma unroll 1
        for (int step = 0; step < 3; step++) {
            float4 c4[12];
            float sa = 0.f;
            float4 prev31 = make_float4(0.f, 0.f, 0.f, 0.f);
#pragma unroll
            for (int k = 0; k < 12; k++) {
                float4 o4 = p4[k];
                float4 h4v;
                h4v.x = __shfl_up_sync(0xffffffffu, o4.x, 1);
                h4v.y = __shfl_up_sync(0xffffffffu, o4.y, 1);
                h4v.z = __shfl_up_sync(0xffffffffu, o4.z, 1);
                h4v.w = __shfl_up_sync(0xffffffffu, o4.w, 1);
                float4 n31;
                n31.x = __shfl_sync(0xffffffffu, o4.x, 31);
                n31.y = __shfl_sync(0xffffffffu, o4.y, 31);
                n31.z = __shfl_sync(0xffffffffu, o4.z, 31);
                n31.w = __shfl_sync(0xffffffffu, o4.w, 31);
                if (lane == 0) h4v = prev31;
                prev31 = n31;
                float4 kv = kvs4[lane + 32 * k];
                float4 cc;
                cc.x = (w0 * h4v.x + w1 * h4v.y + w2 * h4v.z + w3 * h4v.w + w4 * o4.x) * kv.x;
                cc.y = (w0 * h4v.y + w1 * h4v.z + w2 * h4v.w + w3 * o4.x + w4 * o4.y) * kv.y;
                cc.z = (w0 * h4v.z + w1 * h4v.w + w2 * o4.x + w3 * o4.y + w4 * o4.z) * kv.z;
                cc.w = (w0 * h4v.w + w1 * o4.x + w2 * o4.y + w3 * o4.z + w4 * o4.w) * kv.w;
                c4[k] = cc;
                sa += cc.x + cc.y + cc.z + cc.w;
            }
#pragma unroll
            for (int o = 16; o; o >>= 1) sa += __shfl_xor_sync(0xffffffffu, sa, o);
            const float rmul = 0.02f / (sa + 1e-9f);
#pragma unroll
            for (int k = 0; k < 12; k++) {
                p4[k].x = 0.98f * p4[k].x + rmul * c4[k].x;
                p4[k].y = 0.98f * p4[k].y + rmul * c4[k].y;
                p4[k].z = 0.98f * p4[k].z + rmul * c4[k].z;
                p4[k].w = 0.98f * p4[k].w + rmul * c4[k].w;
            }
        }

        // stage p row into SMEM as fp16 for phase-2 MMA
        __half* pr = Ps + (size_t)warp * PSTR_H;
#pragma unroll
        for (int k = 0; k < 12; k++)
            *(uint2*)(pr + (size_t)(lane + 32 * k) * 4) = h4(p4[k]);
    }
    __syncthreads();

    // ---- phase 2: out[16x64] = p[16x1536] @ V[1536x64], fp16 wmma ----
    const int g = warp >> 2;     // k-group
    const int j = warp & 3;      // output column tile

    FragC acc;
    wmma::fill_fragment(acc, 0.f);

    const int vrow = t >> 4, vcol = (t & 15) << 2;
    float4 vpre[2];
#pragma unroll
    for (int r = 0; r < 2; r++)
        vpre[r] = *(const float4*)(Vb + (size_t)(vrow + r * 32) * HDIM + vcol);

    for (int c = 0; c < 24; c++) {
#pragma unroll
        for (int r = 0; r < 2; r++)
            *(uint2*)(Vs + (vrow + r * 32) * 72 + vcol) = h4(vpre[r]);
        __syncthreads();
        if (c + 1 < 24) {
#pragma unroll
            for (int r = 0; r < 2; r++)
                vpre[r] = *(const float4*)(Vb + (size_t)((c + 1) * 64 + vrow + r * 32) * HDIM + vcol);
        }
        HFragA a;
        HFragB bb;
        wmma::load_matrix_sync(a, Ps + c * 64 + g * 16, PSTR_H);
        wmma::load_matrix_sync(bb, Vs + (g * 16) * 72 + j * 16, 72);
        wmma::mma_sync(acc, a, bb, acc);
        __syncthreads();
    }

    wmma::store_matrix_sync(Vred + (g * 16) * 68 + j * 16, acc, 68, wmma::mem_row_major);
    __syncthreads();

    if (t < 128) {
        const int row = t >> 3;
        const int col = (t & 7) << 3;
        float* o0 = Vred + row * 68 + col;
        float4 s0 = *(float4*)o0;
        float4 s1 = *(float4*)(o0 + 4);
#pragma unroll
        for (int gg = 1; gg < 4; gg++) {
            float* og = Vred + (gg * 16 + row) * 68 + col;
            float4 a0 = *(float4*)og;
            float4 a1 = *(float4*)(og + 4);
            s0.x += a0.x; s0.y += a0.y; s0.z += a0.z; s0.w += a0.w;
            s1.x += a1.x; s1.y += a1.y; s1.z += a1.z; s1.w += a1.w;
        }
        float* out = g_attn + ((size_t)(b * LL + q0 + row)) * PP + h * 64 + col;
        *(float4*)out = s0;
        *(float4*)(out + 4) = s1;
    }
}

// ---------------- launch ----------------
extern "C" void kernel_launch(void* const* d_in, const int* in_sizes, int n_in,
                              void* d_out, int out_size) {
    const float* hs = (const float*)d_in[0];
    const int* mask = (const int*)d_in[1];
    const float* Wq = (const float*)d_in[2];
    const float* bq = (const float*)d_in[3];
    const float* Wk = (const float*)d_in[4];
    const float* bk = (const float*)d_in[5];
    const float* Wv = (const float*)d_in[6];
    const float* bv = (const float*)d_in[7];
    const float* Wo = (const float*)d_in[8];
    const float* bo = (const float*)d_in[9];
    const float* kw = (const float*)d_in[10];

    cudaFuncSetAttribute(scores_wmma, cudaFuncAttributeMaxDynamicSharedMemorySize, SCORES_SMEM_BYTES);
    cudaFuncSetAttribute(fused_sda2, cudaFuncAttributeMaxDynamicSharedMemorySize, FUSED_SMEM_BYTES);

    qkv_wmma<<<dim3(PP / 128, (BB * LL) / 64, 3), 256>>>(hs, Wq, bq, Wk, bk, Wv, bv);

    scores_wmma<<<dim3(LL / 128, LL / 128, BB * HH), 256, SCORES_SMEM_BYTES>>>();

    fused_sda2<<<(BB * HH * LL) / FROWS, 512, FUSED_SMEM_BYTES>>>(mask, kw);

    oproj_wmma<<<dim3(PP / 128, (BB * LL) / 64), 256>>>(Wo, bo, (float*)d_out);
}

// round 9
// speedup vs baseline: 2.8316x; 1.4400x over previous
#include <cuda_runtime.h>
#include <cuda_fp16.h>
#include <mma.h>
using namespace nvcuda;

#define BB 2
#define LL 1536
#define DD 1024
#define HH 16
#define PP 1024
#define HDIM 64

// qkv dynamic smem layout (bytes)
#define QKV_TILE_OFF 8448                       // BiasT float[16][132] = 8448 at 0
#define QKV_SMEM_BYTES (8448 + 33792)           // tiles (As/Bs half, 13824) union Cst float[64][132] 33792

#define SCORES_SMEM_BYTES 69632                 // max(half tiles 36864, float staging 67584)

// fused smem layout (bytes): 8 rows per block, 256 threads
#define FROWS 8
#define PSTR_H 1544
#define F_PS_BYTES (FROWS * PSTR_H * 2)         // 24704
#define F_KVS_OFF  F_PS_BYTES                   // float kvs[1536] -> 6144
#define F_VS_OFF   (F_KVS_OFF + LL * 4)         // V chunk half[128][72]=18432 / reduce float[4][8][68]=8704
#define FUSED_SMEM_BYTES (F_VS_OFF + 18432 + 32)

// ---------------- device scratch ----------------
__device__ __half g_Q[BB * HH * LL * HDIM];     // head-major [b,h,l,d], pre-scaled by 0.125
__device__ __half g_K[BB * HH * LL * HDIM];
__device__ __half g_V[BB * HH * LL * HDIM];
__device__ __half g_attn[BB * LL * PP];         // [b,l,h*64+d]
__device__ float g_S[BB * HH * LL * LL];        // scores (fp32)

typedef wmma::fragment<wmma::matrix_a, 16, 16, 16, __half, wmma::row_major> HFragA;
typedef wmma::fragment<wmma::matrix_b, 16, 16, 16, __half, wmma::row_major> HFragB;
typedef wmma::fragment<wmma::matrix_b, 16, 16, 16, __half, wmma::col_major> HFragBc;
typedef wmma::fragment<wmma::accumulator, 16, 16, 16, float> FragC;

typedef wmma::fragment<wmma::matrix_a, 8, 32, 16, __half, wmma::row_major> PFragA;
typedef wmma::fragment<wmma::matrix_b, 8, 32, 16, __half, wmma::row_major> PFragB;
typedef wmma::fragment<wmma::accumulator, 8, 32, 16, float> PFragC;

// float4 -> 4 halves (RN), packed as uint2
__device__ __forceinline__ uint2 h4(float4 v) {
    __half2 a = __floats2half2_rn(v.x, v.y);
    __half2 b = __floats2half2_rn(v.z, v.w);
    uint2 r;
    r.x = *(unsigned*)&a;
    r.y = *(unsigned*)&b;
    return r;
}

// ---------------- QKV projection: fp32 in, HALF out (head-major) ----------------
__global__ __launch_bounds__(256, 2) void qkv_wmma(const float* __restrict__ A,
                                                   const float* __restrict__ Wq,
                                                   const float* __restrict__ bq,
                                                   const float* __restrict__ Wk,
                                                   const float* __restrict__ bk,
                                                   const float* __restrict__ Wv,
                                                   const float* __restrict__ bv) {
    const int zz = blockIdx.z;
    const float* W = (zz == 0) ? Wq : (zz == 1) ? Wk : Wv;
    const float* bias = (zz == 0) ? bq : (zz == 1) ? bk : bv;
    __half* C = (zz == 0) ? g_Q : (zz == 1) ? g_K : g_V;

    extern __shared__ char dsm[];
    float* BiasT = (float*)dsm;                      // [16][132]
    __half* As = (__half*)(dsm + QKV_TILE_OFF);      // [64][40]
    __half* Bs = As + 64 * 40;                       // [32][136]
    float* Cst = (float*)(dsm + QKV_TILE_OFF);       // [64][132] (reuses As/Bs after loop)

    const int m0 = blockIdx.y * 64;
    const int n0 = blockIdx.x * 128;
    const int t = threadIdx.x;
    const int warp = t >> 5;
    const int wm = (warp & 3) * 16;
    const int wn = (warp >> 2) * 64;

#pragma unroll
    for (int r = 0; r < 2; r++) {
        int idx = t + r * 256;
        int row = idx >> 5;
        int col = (idx & 31) << 2;
        *(float4*)(BiasT + row * 132 + col) = *(const float4*)(bias + n0 + col);
    }

    FragC c[4];
#pragma unroll
    for (int j = 0; j < 4; j++) wmma::fill_fragment(c[j], 0.f);

    const int arow = t >> 3, acol = (t & 7) << 2;
    const int brow = t >> 5, bcol = (t & 31) << 2;

    float4 apre[2], bpre[4];
#pragma unroll
    for (int r = 0; r < 2; r++)
        apre[r] = *(const float4*)(A + (size_t)(m0 + arow + r * 32) * DD + acol);
#pragma unroll
    for (int r = 0; r < 4; r++)
        bpre[r] = *(const float4*)(W + (size_t)(brow + r * 8) * PP + n0 + bcol);

    for (int k0 = 0; k0 < DD; k0 += 32) {
#pragma unroll
        for (int r = 0; r < 2; r++) *(uint2*)(As + (arow + r * 32) * 40 + acol) = h4(apre[r]);
#pragma unroll
        for (int r = 0; r < 4; r++) *(uint2*)(Bs + (brow + r * 8) * 136 + bcol) = h4(bpre[r]);
        __syncthreads();
        if (k0 + 32 < DD) {
#pragma unroll
            for (int r = 0; r < 2; r++)
                apre[r] = *(const float4*)(A + (size_t)(m0 + arow + r * 32) * DD + k0 + 32 + acol);
#pragma unroll
            for (int r = 0; r < 4; r++)
                bpre[r] = *(const float4*)(W + (size_t)(k0 + 32 + brow + r * 8) * PP + n0 + bcol);
        }
#pragma unroll
        for (int kk = 0; kk < 32; kk += 16) {
            HFragA a;
            wmma::load_matrix_sync(a, As + wm * 40 + kk, 40);
#pragma unroll
            for (int j = 0; j < 4; j++) {
                HFragB b;
                wmma::load_matrix_sync(b, Bs + kk * 136 + wn + j * 16, 136);
                wmma::mma_sync(c[j], a, b, c[j]);
            }
        }
        __syncthreads();
    }

    const float scale = (zz == 0) ? 0.125f : 1.0f;
#pragma unroll
    for (int j = 0; j < 4; j++) {
        FragC bf;
        wmma::load_matrix_sync(bf, BiasT + wn + j * 16, 132, wmma::mem_row_major);
#pragma unroll
        for (int e = 0; e < bf.num_elements; e++) c[j].x[e] = (c[j].x[e] + bf.x[e]) * scale;
    }

    // stage fp32 tile, then convert -> half global (head-major)
#pragma unroll
    for (int j = 0; j < 4; j++)
        wmma::store_matrix_sync(Cst + wm * 132 + wn + j * 16, c[j], 132, wmma::mem_row_major);
    __syncthreads();

    const int b = m0 / LL;
    const int l0 = m0 - b * LL;
    const int hbase = n0 >> 6;
#pragma unroll
    for (int r = 0; r < 8; r++) {
        int idx = t + r * 256;
        int row = idx >> 5;
        int col = (idx & 31) << 2;
        uint2 hv = h4(*(float4*)(Cst + row * 132 + col));
        int h = hbase + (col >> 6);
        int d = col & 63;
        __half* out = C + (((size_t)(b * HH + h)) * LL + l0 + row) * HDIM + d;
        *(uint2*)out = hv;
    }
}

// ---------------- output projection: HALF A (g_attn), fp32 out ----------------
__global__ __launch_bounds__(256, 2) void oproj_wmma(const float* __restrict__ W,
                                                     const float* __restrict__ bias,
                                                     float* __restrict__ Cout) {
    __shared__ __half As[64][40];
    __shared__ __half Bs[32][136];
    __shared__ float BiasT[16][132];

    const __half* A = g_attn;
    const int m0 = blockIdx.y * 64;
    const int n0 = blockIdx.x * 128;
    const int t = threadIdx.x;
    const int warp = t >> 5;
    const int wm = (warp & 3) * 16;
    const int wn = (warp >> 2) * 64;

#pragma unroll
    for (int r = 0; r < 2; r++) {
        int idx = t + r * 256;
        int row = idx >> 5;
        int col = (idx & 31) << 2;
        *(float4*)&BiasT[row][col] = *(const float4*)(bias + n0 + col);
    }

    FragC c[4];
#pragma unroll
    for (int j = 0; j < 4; j++) wmma::fill_fragment(c[j], 0.f);

    const int arow = t >> 3, acol = (t & 7) << 2;
    const int brow = t >> 5, bcol = (t & 31) << 2;

    uint2 apre[2];
    float4 bpre[4];
#pragma unroll
    for (int r = 0; r < 2; r++)
        apre[r] = *(const uint2*)(A + (size_t)(m0 + arow + r * 32) * DD + acol);
#pragma unroll
    for (int r = 0; r < 4; r++)
        bpre[r] = *(const float4*)(W + (size_t)(brow + r * 8) * PP + n0 + bcol);

    for (int k0 = 0; k0 < DD; k0 += 32) {
#pragma unroll
        for (int r = 0; r < 2; r++) *(uint2*)&As[arow + r * 32][acol] = apre[r];
#pragma unroll
        for (int r = 0; r < 4; r++) *(uint2*)&Bs[brow + r * 8][bcol] = h4(bpre[r]);
        __syncthreads();
        if (k0 + 32 < DD) {
#pragma unroll
            for (int r = 0; r < 2; r++)
                apre[r] = *(const uint2*)(A + (size_t)(m0 + arow + r * 32) * DD + k0 + 32 + acol);
#pragma unroll
            for (int r = 0; r < 4; r++)
                bpre[r] = *(const float4*)(W + (size_t)(k0 + 32 + brow + r * 8) * PP + n0 + bcol);
        }
#pragma unroll
        for (int kk = 0; kk < 32; kk += 16) {
            HFragA a;
            wmma::load_matrix_sync(a, &As[wm][kk], 40);
#pragma unroll
            for (int j = 0; j < 4; j++) {
                HFragB b;
                wmma::load_matrix_sync(b, &Bs[kk][wn + j * 16], 136);
                wmma::mma_sync(c[j], a, b, c[j]);
            }
        }
        __syncthreads();
    }

#pragma unroll
    for (int j = 0; j < 4; j++) {
        FragC bf;
        wmma::load_matrix_sync(bf, &BiasT[0][wn + j * 16], 132, wmma::mem_row_major);
#pragma unroll
        for (int e = 0; e < bf.num_elements; e++) c[j].x[e] += bf.x[e];
    }

    float* base = Cout + (size_t)(m0 + wm) * PP + n0 + wn;
#pragma unroll
    for (int j = 0; j < 4; j++)
        wmma::store_matrix_sync(base + j * 16, c[j], PP, wmma::mem_row_major);
}

// ---------------- scores: half Q/K in, fp32 S out ----------------
__global__ __launch_bounds__(256, 2) void scores_wmma() {
    extern __shared__ char sm2raw[];
    __half* As = (__half*)sm2raw;              // [128][72]
    __half* Bs = As + 128 * 72;                // [128][72]
    float* Cst = (float*)sm2raw;               // staging [128][132]

    const int z = blockIdx.z;
    const __half* Qb = g_Q + (size_t)z * LL * HDIM;
    const __half* Kb = g_K + (size_t)z * LL * HDIM;
    float* Sb = g_S + (size_t)z * LL * LL;
    const int q0 = blockIdx.y * 128;
    const int n0 = blockIdx.x * 128;

    const int t = threadIdx.x;
    const int warp = t >> 5;
    const int wm = (warp & 3) * 32;
    const int wn = (warp >> 2) * 64;

#pragma unroll
    for (int r = 0; r < 8; r++) {
        int idx = t + r * 256;
        int row = idx >> 4;
        int col = (idx & 15) << 2;
        *(uint2*)(As + row * 72 + col) = *(const uint2*)(Qb + (size_t)(q0 + row) * HDIM + col);
        *(uint2*)(Bs + row * 72 + col) = *(const uint2*)(Kb + (size_t)(n0 + row) * HDIM + col);
    }
    __syncthreads();

    FragC c[2][4];
#pragma unroll
    for (int i = 0; i < 2; i++)
#pragma unroll
        for (int j = 0; j < 4; j++) wmma::fill_fragment(c[i][j], 0.f);

#pragma unroll
    for (int kk = 0; kk < 64; kk += 16) {
        HFragA a[2];
        HFragBc b[4];
#pragma unroll
        for (int i = 0; i < 2; i++) wmma::load_matrix_sync(a[i], As + (wm + i * 16) * 72 + kk, 72);
#pragma unroll
        for (int j = 0; j < 4; j++) wmma::load_matrix_sync(b[j], Bs + (wn + j * 16) * 72 + kk, 72);
#pragma unroll
        for (int i = 0; i < 2; i++)
#pragma unroll
            for (int j = 0; j < 4; j++) wmma::mma_sync(c[i][j], a[i], b[j], c[i][j]);
    }

    __syncthreads();
#pragma unroll
    for (int i = 0; i < 2; i++)
#pragma unroll
        for (int j = 0; j < 4; j++)
            wmma::store_matrix_sync(Cst + (wm + i * 16) * 132 + wn + j * 16, c[i][j],
                                    132, wmma::mem_row_major);
    __syncthreads();

#pragma unroll
    for (int r = 0; r < 16; r++) {
        int idx = t + r * 256;
        int row = idx >> 5;
        int col = (idx & 31) << 2;
        *(float4*)(Sb + (size_t)(q0 + row) * LL + n0 + col) = *(float4*)(Cst + row * 132 + col);
    }
}

// ---------------- fused: softmax + diffusion + p@V (256 thr, 8 rows, no spill) ------
__global__ __launch_bounds__(256, 2) void fused_sda2(const int* __restrict__ mask,
                                                     const float* __restrict__ kw) {
    extern __shared__ char smraw[];
    __half* Ps = (__half*)smraw;                       // [8][PSTR_H]
    float* kvs = (float*)(smraw + F_KVS_OFF);          // [1536]
    __half* Vs = (__half*)(smraw + F_VS_OFF);          // [128][72] V chunk
    float* Vred = (float*)(smraw + F_VS_OFF);          // [4][8][68] reduce
    float* w5s = (float*)(smraw + F_VS_OFF + 18432);   // [5]

    const int t = threadIdx.x;
    const int warp = t >> 5, lane = t & 31;
    const size_t row0 = (size_t)blockIdx.x * FROWS;
    const int z = (int)(row0 / LL);
    const int q0 = (int)(row0 - (size_t)z * LL);
    const int b = z >> 4;
    const int h = z & 15;
    const int* mrow = mask + b * LL;
    const __half* Vb = g_V + (size_t)z * LL * HDIM;

    if (t == 0) {
        float mxw = kw[0];
#pragma unroll
        for (int j = 1; j < 5; j++) mxw = fmaxf(mxw, kw[j]);
        float e[5], s = 0.f;
#pragma unroll
        for (int j = 0; j < 5; j++) { e[j] = __expf(kw[j] - mxw); s += e[j]; }
#pragma unroll
        for (int j = 0; j < 5; j++) w5s[j] = e[j] / s;
    }
    for (int i = t; i < LL / 4; i += 256) {
        int4 m4 = *(const int4*)(mrow + i * 4);
        *(float4*)(kvs + i * 4) = make_float4(m4.x > 0 ? 1.f : 0.f, m4.y > 0 ? 1.f : 0.f,
                                              m4.z > 0 ? 1.f : 0.f, m4.w > 0 ? 1.f : 0.f);
    }
    __syncthreads();

    const float w0 = w5s[0], w1 = w5s[1], w2 = w5s[2], w3 = w5s[3], w4 = w5s[4];
    const float4* kvs4 = (const float4*)kvs;

    // ---- phase 1: warp-per-row softmax + diffusion (register resident, 8 warps) ----
    {
        const float* prow = g_S + (row0 + warp) * LL;
        float4 p4[12];
        float mx = -3.4e38f;
#pragma unroll
        for (int k = 0; k < 12; k++) {
            int m = lane + 32 * k;
            float4 v = *(const float4*)(prow + (size_t)m * 4);
            float4 kv = kvs4[m];
            v.x += (kv.x > 0.f) ? 0.f : -1e9f;
            v.y += (kv.y > 0.f) ? 0.f : -1e9f;
            v.z += (kv.z > 0.f) ? 0.f : -1e9f;
            v.w += (kv.w > 0.f) ? 0.f : -1e9f;
            p4[k] = v;
            mx = fmaxf(mx, fmaxf(fmaxf(v.x, v.y), fmaxf(v.z, v.w)));
        }
#pragma unroll
        for (int o = 16; o; o >>= 1) mx = fmaxf(mx, __shfl_xor_sync(0xffffffffu, mx, o));

        float s = 0.f;
#pragma unroll
        for (int k = 0; k < 12; k++) {
            float4 v = p4[k];
            v.x = __expf(v.x - mx); v.y = __expf(v.y - mx);
            v.z = __expf(v.z - mx); v.w = __expf(v.w - mx);
            p4[k] = v;
            s += v.x + v.y + v.z + v.w;
        }
#pragma unroll
        for (int o = 16; o; o >>= 1) s += __shfl_xor_sync(0xffffffffu, s, o);
        float inv = 1.f / s;
#pragma unroll
        for (int k = 0; k < 12; k++) {
            p4[k].x *= inv; p4[k].y *= inv; p4[k].z *= inv; p4[k].w *= inv;
        }

#pragma unroll 1
        for (int step = 0; step < 3; step++) {
            float4 c4[12];
            float sa = 0.f;
            float4 prev31 = make_float4(0.f, 0.f, 0.f, 0.f);
#pragma unroll
            for (int k = 0; k < 12; k++) {
                float4 o4 = p4[k];
                float4 h4v;
                h4v.x = __shfl_up_sync(0xffffffffu, o4.x, 1);
                h4v.y = __shfl_up_sync(0xffffffffu, o4.y, 1);
                h4v.z = __shfl_up_sync(0xffffffffu, o4.z, 1);
                h4v.w = __shfl_up_sync(0xffffffffu, o4.w, 1);
                float4 n31;
                n31.x = __shfl_sync(0xffffffffu, o4.x, 31);
                n31.y = __shfl_sync(0xffffffffu, o4.y, 31);
                n31.z = __shfl_sync(0xffffffffu, o4.z, 31);
                n31.w = __shfl_sync(0xffffffffu, o4.w, 31);
                if (lane == 0) h4v = prev31;
                prev31 = n31;
                float4 kv = kvs4[lane + 32 * k];
                float4 cc;
                cc.x = (w0 * h4v.x + w1 * h4v.y + w2 * h4v.z + w3 * h4v.w + w4 * o4.x) * kv.x;
                cc.y = (w0 * h4v.y + w1 * h4v.z + w2 * h4v.w + w3 * o4.x + w4 * o4.y) * kv.y;
                cc.z = (w0 * h4v.z + w1 * h4v.w + w2 * o4.x + w3 * o4.y + w4 * o4.z) * kv.z;
                cc.w = (w0 * h4v.w + w1 * o4.x + w2 * o4.y + w3 * o4.z + w4 * o4.w) * kv.w;
                c4[k] = cc;
                sa += cc.x + cc.y + cc.z + cc.w;
            }
#pragma unroll
            for (int o = 16; o; o >>= 1) sa += __shfl_xor_sync(0xffffffffu, sa, o);
            const float rmul = 0.02f / (sa + 1e-9f);
#pragma unroll
            for (int k = 0; k < 12; k++) {
                p4[k].x = 0.98f * p4[k].x + rmul * c4[k].x;
                p4[k].y = 0.98f * p4[k].y + rmul * c4[k].y;
                p4[k].z = 0.98f * p4[k].z + rmul * c4[k].z;
                p4[k].w = 0.98f * p4[k].w + rmul * c4[k].w;
            }
        }

        __half* pr = Ps + (size_t)warp * PSTR_H;
#pragma unroll
        for (int k = 0; k < 12; k++)
            *(uint2*)(pr + (size_t)(lane + 32 * k) * 4) = h4(p4[k]);
    }
    __syncthreads();

    // ---- phase 2: out[8x64] = p[8x1536] @ V[1536x64], m8n32k16, 128-row V chunks ----
    const int g = warp >> 1;     // 0..3: k-group (32 rows within 128-chunk)
    const int j = warp & 1;      // 0..1: 32-col output tile

    PFragC acc;
    wmma::fill_fragment(acc, 0.f);

    uint2 vpre[8];
#pragma unroll
    for (int r = 0; r < 8; r++) {
        int u = t + r * 256;
        int row = u >> 4, col = (u & 15) << 2;
        vpre[r] = *(const uint2*)(Vb + (size_t)row * HDIM + col);
    }

    for (int c = 0; c < 12; c++) {
#pragma unroll
        for (int r = 0; r < 8; r++) {
            int u = t + r * 256;
            int row = u >> 4, col = (u & 15) << 2;
            *(uint2*)(Vs + row * 72 + col) = vpre[r];
        }
        __syncthreads();
        if (c + 1 < 12) {
#pragma unroll
            for (int r = 0; r < 8; r++) {
                int u = t + r * 256;
                int row = u >> 4, col = (u & 15) << 2;
                vpre[r] = *(const uint2*)(Vb + (size_t)((c + 1) * 128 + row) * HDIM + col);
            }
        }
#pragma unroll
        for (int kk = 0; kk < 32; kk += 16) {
            PFragA a;
            PFragB bb;
            wmma::load_matrix_sync(a, Ps + c * 128 + g * 32 + kk, PSTR_H);
            wmma::load_matrix_sync(bb, Vs + (g * 32 + kk) * 72 + j * 32, 72);
            wmma::mma_sync(acc, a, bb, acc);
        }
        __syncthreads();
    }

    wmma::store_matrix_sync(Vred + (g * 8) * 68 + j * 32, acc, 68, wmma::mem_row_major);
    __syncthreads();

    if (t < 128) {
        const int row = t >> 4;          // 0..7
        const int col = (t & 15) << 2;   // 0..60
        float4 s0 = *(float4*)(Vred + row * 68 + col);
#pragma unroll
        for (int gg = 1; gg < 4; gg++) {
            float4 a0 = *(float4*)(Vred + (gg * 8 + row) * 68 + col);
            s0.x += a0.x; s0.y += a0.y; s0.z += a0.z; s0.w += a0.w;
        }
        __half* out = g_attn + ((size_t)(b * LL + q0 + row)) * PP + h * 64 + col;
        *(uint2*)out = h4(s0);
    }
}

// ---------------- launch ----------------
extern "C" void kernel_launch(void* const* d_in, const int* in_sizes, int n_in,
                              void* d_out, int out_size) {
    const float* hs = (const float*)d_in[0];
    const int* mask = (const int*)d_in[1];
    const float* Wq = (const float*)d_in[2];
    const float* bq = (const float*)d_in[3];
    const float* Wk = (const float*)d_in[4];
    const float* bk = (const float*)d_in[5];
    const float* Wv = (const float*)d_in[6];
    const float* bv = (const float*)d_in[7];
    const float* Wo = (const float*)d_in[8];
    const float* bo = (const float*)d_in[9];
    const float* kw = (const float*)d_in[10];

    cudaFuncSetAttribute(scores_wmma, cudaFuncAttributeMaxDynamicSharedMemorySize, SCORES_SMEM_BYTES);
    cudaFuncSetAttribute(fused_sda2, cudaFuncAttributeMaxDynamicSharedMemorySize, FUSED_SMEM_BYTES);

    qkv_wmma<<<dim3(PP / 128, (BB * LL) / 64, 3), 256, QKV_SMEM_BYTES>>>(hs, Wq, bq, Wk, bk, Wv, bv);

    scores_wmma<<<dim3(LL / 128, LL / 128, BB * HH), 256, SCORES_SMEM_BYTES>>>();

    fused_sda2<<<(BB * HH * LL) / FROWS, 256, FUSED_SMEM_BYTES>>>(mask, kw);

    oproj_wmma<<<dim3(PP / 128, (BB * LL) / 64), 256>>>(Wo, bo, (float*)d_out);
}

// round 10
// speedup vs baseline: 2.8846x; 1.0187x over previous
#include <cuda_runtime.h>
#include <cuda_fp16.h>
#include <mma.h>
using namespace nvcuda;

#define BB 2
#define LL 1536
#define DD 1024
#define HH 16
#define PP 1024
#define HDIM 64

// qkv dynamic smem layout (bytes): BiasT(8448) + union(tiles 27648 double-buffered, Cst 33792)
#define QKV_TILE_OFF 8448
#define QKV_SMEM_BYTES (8448 + 33792)

#define SCORES_SMEM_BYTES 69632                 // max(half tiles 36864, float staging 67584)

// fused smem layout (bytes): 8 rows per block, 256 threads, double-buffered V
#define FROWS 8
#define PSTR_H 1544
#define F_PS_BYTES (FROWS * PSTR_H * 2)         // 24704
#define F_KVS_OFF  F_PS_BYTES                   // float kvs[1536] -> 6144
#define F_VS_OFF   (F_KVS_OFF + LL * 4)         // V chunks half[2][128][72]=36864 / reduce float[4][8][68]=8704
#define FUSED_SMEM_BYTES (F_VS_OFF + 36864 + 32)

// ---------------- device scratch ----------------
__device__ __half g_Q[BB * HH * LL * HDIM];     // head-major [b,h,l,d], pre-scaled by 0.125
__device__ __half g_K[BB * HH * LL * HDIM];
__device__ __half g_V[BB * HH * LL * HDIM];
__device__ __half g_attn[BB * LL * PP];         // [b,l,h*64+d]
__device__ __half g_S[BB * HH * LL * LL];       // scores (fp16, 151 MB)

typedef wmma::fragment<wmma::matrix_a, 16, 16, 16, __half, wmma::row_major> HFragA;
typedef wmma::fragment<wmma::matrix_b, 16, 16, 16, __half, wmma::row_major> HFragB;
typedef wmma::fragment<wmma::matrix_b, 16, 16, 16, __half, wmma::col_major> HFragBc;
typedef wmma::fragment<wmma::accumulator, 16, 16, 16, float> FragC;

typedef wmma::fragment<wmma::matrix_a, 8, 32, 16, __half, wmma::row_major> PFragA;
typedef wmma::fragment<wmma::matrix_b, 8, 32, 16, __half, wmma::row_major> PFragB;
typedef wmma::fragment<wmma::accumulator, 8, 32, 16, float> PFragC;

// float4 -> 4 halves (RN), packed as uint2
__device__ __forceinline__ uint2 h4(float4 v) {
    __half2 a = __floats2half2_rn(v.x, v.y);
    __half2 b = __floats2half2_rn(v.z, v.w);
    uint2 r;
    r.x = *(unsigned*)&a;
    r.y = *(unsigned*)&b;
    return r;
}
// uint2 (4 halves) -> float4
__device__ __forceinline__ float4 f4(uint2 u) {
    float2 a = __half22float2(*(__half2*)&u.x);
    float2 b = __half22float2(*(__half2*)&u.y);
    return make_float4(a.x, a.y, b.x, b.y);
}

// ---------------- QKV projection: fp32 in, HALF out (head-major), double-buffered ----
__global__ __launch_bounds__(256, 2) void qkv_wmma(const float* __restrict__ A,
                                                   const float* __restrict__ Wq,
                                                   const float* __restrict__ bq,
                                                   const float* __restrict__ Wk,
                                                   const float* __restrict__ bk,
                                                   const float* __restrict__ Wv,
                                                   const float* __restrict__ bv) {
    const int zz = blockIdx.z;
    const float* W = (zz == 0) ? Wq : (zz == 1) ? Wk : Wv;
    const float* bias = (zz == 0) ? bq : (zz == 1) ? bk : bv;
    __half* C = (zz == 0) ? g_Q : (zz == 1) ? g_K : g_V;

    extern __shared__ char dsm[];
    float* BiasT = (float*)dsm;                       // [16][132]
    __half* AsB = (__half*)(dsm + QKV_TILE_OFF);      // [2][64][40]
    __half* BsB = AsB + 2 * 64 * 40;                  // [2][32][136]
    float* Cst = (float*)(dsm + QKV_TILE_OFF);        // [64][132] (reuses tiles after loop)

    const int m0 = blockIdx.y * 64;
    const int n0 = blockIdx.x * 128;
    const int t = threadIdx.x;
    const int warp = t >> 5;
    const int wm = (warp & 3) * 16;
    const int wn = (warp >> 2) * 64;

#pragma unroll
    for (int r = 0; r < 2; r++) {
        int idx = t + r * 256;
        int row = idx >> 5;
        int col = (idx & 31) << 2;
        *(float4*)(BiasT + row * 132 + col) = *(const float4*)(bias + n0 + col);
    }

    FragC c[4];
#pragma unroll
    for (int j = 0; j < 4; j++) wmma::fill_fragment(c[j], 0.f);

    const int arow = t >> 3, acol = (t & 7) << 2;
    const int brow = t >> 5, bcol = (t & 31) << 2;

    float4 apre[2], bpre[4];
#pragma unroll
    for (int r = 0; r < 2; r++)
        apre[r] = *(const float4*)(A + (size_t)(m0 + arow + r * 32) * DD + acol);
#pragma unroll
    for (int r = 0; r < 4; r++)
        bpre[r] = *(const float4*)(W + (size_t)(brow + r * 8) * PP + n0 + bcol);
#pragma unroll
    for (int r = 0; r < 2; r++) *(uint2*)(AsB + (arow + r * 32) * 40 + acol) = h4(apre[r]);
#pragma unroll
    for (int r = 0; r < 4; r++) *(uint2*)(BsB + (brow + r * 8) * 136 + bcol) = h4(bpre[r]);
    __syncthreads();

    for (int k0 = 0; k0 < DD; k0 += 32) {
        const int cur = (k0 >> 5) & 1, nxt = cur ^ 1;
        const bool more = (k0 + 32 < DD);
        if (more) {
#pragma unroll
            for (int r = 0; r < 2; r++)
                apre[r] = *(const float4*)(A + (size_t)(m0 + arow + r * 32) * DD + k0 + 32 + acol);
#pragma unroll
            for (int r = 0; r < 4; r++)
                bpre[r] = *(const float4*)(W + (size_t)(k0 + 32 + brow + r * 8) * PP + n0 + bcol);
        }
        const __half* Asc = AsB + cur * 64 * 40;
        const __half* Bsc = BsB + cur * 32 * 136;
#pragma unroll
        for (int kk = 0; kk < 32; kk += 16) {
            HFragA a;
            wmma::load_matrix_sync(a, Asc + wm * 40 + kk, 40);
#pragma unroll
            for (int j = 0; j < 4; j++) {
                HFragB b;
                wmma::load_matrix_sync(b, Bsc + kk * 136 + wn + j * 16, 136);
                wmma::mma_sync(c[j], a, b, c[j]);
            }
        }
        if (more) {
#pragma unroll
            for (int r = 0; r < 2; r++) *(uint2*)(AsB + nxt * 64 * 40 + (arow + r * 32) * 40 + acol) = h4(apre[r]);
#pragma unroll
            for (int r = 0; r < 4; r++) *(uint2*)(BsB + nxt * 32 * 136 + (brow + r * 8) * 136 + bcol) = h4(bpre[r]);
        }
        __syncthreads();
    }

    const float scale = (zz == 0) ? 0.125f : 1.0f;
#pragma unroll
    for (int j = 0; j < 4; j++) {
        FragC bf;
        wmma::load_matrix_sync(bf, BiasT + wn + j * 16, 132, wmma::mem_row_major);
#pragma unroll
        for (int e = 0; e < bf.num_elements; e++) c[j].x[e] = (c[j].x[e] + bf.x[e]) * scale;
    }

#pragma unroll
    for (int j = 0; j < 4; j++)
        wmma::store_matrix_sync(Cst + wm * 132 + wn + j * 16, c[j], 132, wmma::mem_row_major);
    __syncthreads();

    const int b = m0 / LL;
    const int l0 = m0 - b * LL;
    const int hbase = n0 >> 6;
#pragma unroll
    for (int r = 0; r < 8; r++) {
        int idx = t + r * 256;
        int row = idx >> 5;
        int col = (idx & 31) << 2;
        uint2 hv = h4(*(float4*)(Cst + row * 132 + col));
        int h = hbase + (col >> 6);
        int d = col & 63;
        __half* out = C + (((size_t)(b * HH + h)) * LL + l0 + row) * HDIM + d;
        *(uint2*)out = hv;
    }
}

// ---------------- output projection: HALF A (g_attn), fp32 out, double-buffered ------
__global__ __launch_bounds__(256, 2) void oproj_wmma(const float* __restrict__ W,
                                                     const float* __restrict__ bias,
                                                     float* __restrict__ Cout) {
    __shared__ __half As[2][64][40];
    __shared__ __half Bs[2][32][136];
    __shared__ float BiasT[16][132];

    const __half* A = g_attn;
    const int m0 = blockIdx.y * 64;
    const int n0 = blockIdx.x * 128;
    const int t = threadIdx.x;
    const int warp = t >> 5;
    const int wm = (warp & 3) * 16;
    const int wn = (warp >> 2) * 64;

#pragma unroll
    for (int r = 0; r < 2; r++) {
        int idx = t + r * 256;
        int row = idx >> 5;
        int col = (idx & 31) << 2;
        *(float4*)&BiasT[row][col] = *(const float4*)(bias + n0 + col);
    }

    FragC c[4];
#pragma unroll
    for (int j = 0; j < 4; j++) wmma::fill_fragment(c[j], 0.f);

    const int arow = t >> 3, acol = (t & 7) << 2;
    const int brow = t >> 5, bcol = (t & 31) << 2;

    uint2 apre[2];
    float4 bpre[4];
#pragma unroll
    for (int r = 0; r < 2; r++)
        apre[r] = *(const uint2*)(A + (size_t)(m0 + arow + r * 32) * DD + acol);
#pragma unroll
    for (int r = 0; r < 4; r++)
        bpre[r] = *(const float4*)(W + (size_t)(brow + r * 8) * PP + n0 + bcol);
#pragma unroll
    for (int r = 0; r < 2; r++) *(uint2*)&As[0][arow + r * 32][acol] = apre[r];
#pragma unroll
    for (int r = 0; r < 4; r++) *(uint2*)&Bs[0][brow + r * 8][bcol] = h4(bpre[r]);
    __syncthreads();

    for (int k0 = 0; k0 < DD; k0 += 32) {
        const int cur = (k0 >> 5) & 1, nxt = cur ^ 1;
        const bool more = (k0 + 32 < DD);
        if (more) {
#pragma unroll
            for (int r = 0; r < 2; r++)
                apre[r] = *(const uint2*)(A + (size_t)(m0 + arow + r * 32) * DD + k0 + 32 + acol);
#pragma unroll
            for (int r = 0; r < 4; r++)
                bpre[r] = *(const float4*)(W + (size_t)(k0 + 32 + brow + r * 8) * PP + n0 + bcol);
        }
#pragma unroll
        for (int kk = 0; kk < 32; kk += 16) {
            HFragA a;
            wmma::load_matrix_sync(a, &As[cur][wm][kk], 40);
#pragma unroll
            for (int j = 0; j < 4; j++) {
                HFragB b;
                wmma::load_matrix_sync(b, &Bs[cur][kk][wn + j * 16], 136);
                wmma::mma_sync(c[j], a, b, c[j]);
            }
        }
        if (more) {
#pragma unroll
            for (int r = 0; r < 2; r++) *(uint2*)&As[nxt][arow + r * 32][acol] = apre[r];
#pragma unroll
            for (int r = 0; r < 4; r++) *(uint2*)&Bs[nxt][brow + r * 8][bcol] = h4(bpre[r]);
        }
        __syncthreads();
    }

#pragma unroll
    for (int j = 0; j < 4; j++) {
        FragC bf;
        wmma::load_matrix_sync(bf, &BiasT[0][wn + j * 16], 132, wmma::mem_row_major);
#pragma unroll
        for (int e = 0; e < bf.num_elements; e++) c[j].x[e] += bf.x[e];
    }

    float* base = Cout + (size_t)(m0 + wm) * PP + n0 + wn;
#pragma unroll
    for (int j = 0; j < 4; j++)
        wmma::store_matrix_sync(base + j * 16, c[j], PP, wmma::mem_row_major);
}

// ---------------- scores: half Q/K in, HALF S out ----------------
__global__ __launch_bounds__(256, 2) void scores_wmma() {
    extern __shared__ char sm2raw[];
    __half* As = (__half*)sm2raw;              // [128][72]
    __half* Bs = As + 128 * 72;                // [128][72]
    float* Cst = (float*)sm2raw;               // staging [128][132]

    const int z = blockIdx.z;
    const __half* Qb = g_Q + (size_t)z * LL * HDIM;
    const __half* Kb = g_K + (size_t)z * LL * HDIM;
    __half* Sb = g_S + (size_t)z * LL * LL;
    const int q0 = blockIdx.y * 128;
    const int n0 = blockIdx.x * 128;

    const int t = threadIdx.x;
    const int warp = t >> 5;
    const int wm = (warp & 3) * 32;
    const int wn = (warp >> 2) * 64;

#pragma unroll
    for (int r = 0; r < 8; r++) {
        int idx = t + r * 256;
        int row = idx >> 4;
        int col = (idx & 15) << 2;
        *(uint2*)(As + row * 72 + col) = *(const uint2*)(Qb + (size_t)(q0 + row) * HDIM + col);
        *(uint2*)(Bs + row * 72 + col) = *(const uint2*)(Kb + (size_t)(n0 + row) * HDIM + col);
    }
    __syncthreads();

    FragC c[2][4];
#pragma unroll
    for (int i = 0; i < 2; i++)
#pragma unroll
        for (int j = 0; j < 4; j++) wmma::fill_fragment(c[i][j], 0.f);

#pragma unroll
    for (int kk = 0; kk < 64; kk += 16) {
        HFragA a[2];
        HFragBc b[4];
#pragma unroll
        for (int i = 0; i < 2; i++) wmma::load_matrix_sync(a[i], As + (wm + i * 16) * 72 + kk, 72);
#pragma unroll
        for (int j = 0; j < 4; j++) wmma::load_matrix_sync(b[j], Bs + (wn + j * 16) * 72 + kk, 72);
#pragma unroll
        for (int i = 0; i < 2; i++)
#pragma unroll
            for (int j = 0; j < 4; j++) wmma::mma_sync(c[i][j], a[i], b[j], c[i][j]);
    }

    __syncthreads();
#pragma unroll
    for (int i = 0; i < 2; i++)
#pragma unroll
        for (int j = 0; j < 4; j++)
            wmma::store_matrix_sync(Cst + (wm + i * 16) * 132 + wn + j * 16, c[i][j],
                                    132, wmma::mem_row_major);
    __syncthreads();

#pragma unroll
    for (int r = 0; r < 16; r++) {
        int idx = t + r * 256;
        int row = idx >> 5;
        int col = (idx & 31) << 2;
        *(uint2*)(Sb + (size_t)(q0 + row) * LL + n0 + col) = h4(*(float4*)(Cst + row * 132 + col));
    }
}

// ---------------- fused: softmax + diffusion + p@V (half S in, double-buffered V) ----
__global__ __launch_bounds__(256, 2) void fused_sda2(const int* __restrict__ mask,
                                                     const float* __restrict__ kw) {
    extern __shared__ char smraw[];
    __half* Ps = (__half*)smraw;                       // [8][PSTR_H]
    float* kvs = (float*)(smraw + F_KVS_OFF);          // [1536]
    __half* VsB = (__half*)(smraw + F_VS_OFF);         // [2][128][72]
    float* Vred = (float*)(smraw + F_VS_OFF);          // [4][8][68] reduce (reuses VsB)
    float* w5s = (float*)(smraw + F_VS_OFF + 36864);   // [5]

    const int t = threadIdx.x;
    const int warp = t >> 5, lane = t & 31;
    const size_t row0 = (size_t)blockIdx.x * FROWS;
    const int z = (int)(row0 / LL);
    const int q0 = (int)(row0 - (size_t)z * LL);
    const int b = z >> 4;
    const int h = z & 15;
    const int* mrow = mask + b * LL;
    const __half* Vb = g_V + (size_t)z * LL * HDIM;

    if (t == 0) {
        float mxw = kw[0];
#pragma unroll
        for (int j = 1; j < 5; j++) mxw = fmaxf(mxw, kw[j]);
        float e[5], s = 0.f;
#pragma unroll
        for (int j = 0; j < 5; j++) { e[j] = __expf(kw[j] - mxw); s += e[j]; }
#pragma unroll
        for (int j = 0; j < 5; j++) w5s[j] = e[j] / s;
    }
    for (int i = t; i < LL / 4; i += 256) {
        int4 m4 = *(const int4*)(mrow + i * 4);
        *(float4*)(kvs + i * 4) = make_float4(m4.x > 0 ? 1.f : 0.f, m4.y > 0 ? 1.f : 0.f,
                                              m4.z > 0 ? 1.f : 0.f, m4.w > 0 ? 1.f : 0.f);
    }
    __syncthreads();

    const float w0 = w5s[0], w1 = w5s[1], w2 = w5s[2], w3 = w5s[3], w4 = w5s[4];
    const float4* kvs4 = (const float4*)kvs;

    // ---- phase 1: warp-per-row softmax + diffusion (register resident) ----
    {
        const __half* prow = g_S + (row0 + warp) * LL;
        float4 p4[12];
        float mx = -3.4e38f;
#pragma unroll
        for (int k = 0; k < 12; k++) {
            int m = lane + 32 * k;
            float4 v = f4(*(const uint2*)(prow + (size_t)m * 4));
            float4 kv = kvs4[m];
            v.x += (kv.x > 0.f) ? 0.f : -1e9f;
            v.y += (kv.y > 0.f) ? 0.f : -1e9f;
            v.z += (kv.z > 0.f) ? 0.f : -1e9f;
            v.w += (kv.w > 0.f) ? 0.f : -1e9f;
            p4[k] = v;
            mx = fmaxf(mx, fmaxf(fmaxf(v.x, v.y), fmaxf(v.z, v.w)));
        }
#pragma unroll
        for (int o = 16; o; o >>= 1) mx = fmaxf(mx, __shfl_xor_sync(0xffffffffu, mx, o));

        float s = 0.f;
#pragma unroll
        for (int k = 0; k < 12; k++) {
            float4 v = p4[k];
            v.x = __expf(v.x - mx); v.y = __expf(v.y - mx);
            v.z = __expf(v.z - mx); v.w = __expf(v.w - mx);
            p4[k] = v;
            s += v.x + v.y + v.z + v.w;
        }
#pragma unroll
        for (int o = 16; o; o >>= 1) s += __shfl_xor_sync(0xffffffffu, s, o);
        float inv = 1.f / s;
#pragma unroll
        for (int k = 0; k < 12; k++) {
            p4[k].x *= inv; p4[k].y *= inv; p4[k].z *= inv; p4[k].w *= inv;
        }

#pragma unroll 1
        for (int step = 0; step < 3; step++) {
            float4 c4[12];
            float sa = 0.f;
            float4 prev31 = make_float4(0.f, 0.f, 0.f, 0.f);
#pragma unroll
            for (int k = 0; k < 12; k++) {
                float4 o4 = p4[k];
                float4 h4v;
                h4v.x = __shfl_up_sync(0xffffffffu, o4.x, 1);
                h4v.y = __shfl_up_sync(0xffffffffu, o4.y, 1);
                h4v.z = __shfl_up_sync(0xffffffffu, o4.z, 1);
                h4v.w = __shfl_up_sync(0xffffffffu, o4.w, 1);
                float4 n31;
                n31.x = __shfl_sync(0xffffffffu, o4.x, 31);
                n31.y = __shfl_sync(0xffffffffu, o4.y, 31);
                n31.z = __shfl_sync(0xffffffffu, o4.z, 31);
                n31.w = __shfl_sync(0xffffffffu, o4.w, 31);
                if (lane == 0) h4v = prev31;
                prev31 = n31;
                float4 kv = kvs4[lane + 32 * k];
                float4 cc;
                cc.x = (w0 * h4v.x + w1 * h4v.y + w2 * h4v.z + w3 * h4v.w + w4 * o4.x) * kv.x;
                cc.y = (w0 * h4v.y + w1 * h4v.z + w2 * h4v.w + w3 * o4.x + w4 * o4.y) * kv.y;
                cc.z = (w0 * h4v.z + w1 * h4v.w + w2 * o4.x + w3 * o4.y + w4 * o4.z) * kv.z;
                cc.w = (w0 * h4v.w + w1 * o4.x + w2 * o4.y + w3 * o4.z + w4 * o4.w) * kv.w;
                c4[k] = cc;
                sa += cc.x + cc.y + cc.z + cc.w;
            }
#pragma unroll
            for (int o = 16; o; o >>= 1) sa += __shfl_xor_sync(0xffffffffu, sa, o);
            const float rmul = 0.02f / (sa + 1e-9f);
#pragma unroll
            for (int k = 0; k < 12; k++) {
                p4[k].x = 0.98f * p4[k].x + rmul * c4[k].x;
                p4[k].y = 0.98f * p4[k].y + rmul * c4[k].y;
                p4[k].z = 0.98f * p4[k].z + rmul * c4[k].z;
                p4[k].w = 0.98f * p4[k].w + rmul * c4[k].w;
            }
        }

        __half* pr = Ps + (size_t)warp * PSTR_H;
#pragma unroll
        for (int k = 0; k < 12; k++)
            *(uint2*)(pr + (size_t)(lane + 32 * k) * 4) = h4(p4[k]);
    }
    __syncthreads();

    // ---- phase 2: out[8x64] = p[8x1536] @ V[1536x64], m8n32k16, double-buffered ----
    const int g = warp >> 1;     // 0..3: k-group (32 rows within 128-chunk)
    const int j = warp & 1;      // 0..1: 32-col output tile

    PFragC acc;
    wmma::fill_fragment(acc, 0.f);

    uint2 vpre[8];
#pragma unroll
    for (int r = 0; r < 8; r++) {
        int u = t + r * 256;
        int row = u >> 4, col = (u & 15) << 2;
        vpre[r] = *(const uint2*)(Vb + (size_t)row * HDIM + col);
    }
#pragma unroll
    for (int r = 0; r < 8; r++) {
        int u = t + r * 256;
        int row = u >> 4, col = (u & 15) << 2;
        *(uint2*)(VsB + row * 72 + col) = vpre[r];
    }
    __syncthreads();

    for (int c = 0; c < 12; c++) {
        const int cur = c & 1, nxt = cur ^ 1;
        const bool more = (c + 1 < 12);
        if (more) {
#pragma unroll
            for (int r = 0; r < 8; r++) {
                int u = t + r * 256;
                int row = u >> 4, col = (u & 15) << 2;
                vpre[r] = *(const uint2*)(Vb + (size_t)((c + 1) * 128 + row) * HDIM + col);
            }
        }
        const __half* Vsc = VsB + cur * 128 * 72;
#pragma unroll
        for (int kk = 0; kk < 32; kk += 16) {
            PFragA a;
            PFragB bb;
            wmma::load_matrix_sync(a, Ps + c * 128 + g * 32 + kk, PSTR_H);
            wmma::load_matrix_sync(bb, Vsc + (g * 32 + kk) * 72 + j * 32, 72);
            wmma::mma_sync(acc, a, bb, acc);
        }
        if (more) {
#pragma unroll
            for (int r = 0; r < 8; r++) {
                int u = t + r * 256;
                int row = u >> 4, col = (u & 15) << 2;
                *(uint2*)(VsB + nxt * 128 * 72 + row * 72 + col) = vpre[r];
            }
        }
        __syncthreads();
    }

    wmma::store_matrix_sync(Vred + (g * 8) * 68 + j * 32, acc, 68, wmma::mem_row_major);
    __syncthreads();

    if (t < 128) {
        const int row = t >> 4;          // 0..7
        const int col = (t & 15) << 2;   // 0..60
        float4 s0 = *(float4*)(Vred + row * 68 + col);
#pragma unroll
        for (int gg = 1; gg < 4; gg++) {
            float4 a0 = *(float4*)(Vred + (gg * 8 + row) * 68 + col);
            s0.x += a0.x; s0.y += a0.y; s0.z += a0.z; s0.w += a0.w;
        }
        __half* out = g_attn + ((size_t)(b * LL + q0 + row)) * PP + h * 64 + col;
        *(uint2*)out = h4(s0);
    }
}

// ---------------- launch ----------------
extern "C" void kernel_launch(void* const* d_in, const int* in_sizes, int n_in,
                              void* d_out, int out_size) {
    const float* hs = (const float*)d_in[0];
    const int* mask = (const int*)d_in[1];
    const float* Wq = (const float*)d_in[2];
    const float* bq = (const float*)d_in[3];
    const float* Wk = (const float*)d_in[4];
    const float* bk = (const float*)d_in[5];
    const float* Wv = (const float*)d_in[6];
    const float* bv = (const float*)d_in[7];
    const float* Wo = (const float*)d_in[8];
    const float* bo = (const float*)d_in[9];
    const float* kw = (const float*)d_in[10];

    cudaFuncSetAttribute(scores_wmma, cudaFuncAttributeMaxDynamicSharedMemorySize, SCORES_SMEM_BYTES);
    cudaFuncSetAttribute(fused_sda2, cudaFuncAttributeMaxDynamicSharedMemorySize, FUSED_SMEM_BYTES);

    qkv_wmma<<<dim3(PP / 128, (BB * LL) / 64, 3), 256, QKV_SMEM_BYTES>>>(hs, Wq, bq, Wk, bk, Wv, bv);

    scores_wmma<<<dim3(LL / 128, LL / 128, BB * HH), 256, SCORES_SMEM_BYTES>>>();

    fused_sda2<<<(BB * HH * LL) / FROWS, 256, FUSED_SMEM_BYTES>>>(mask, kw);

    oproj_wmma<<<dim3(PP / 128, (BB * LL) / 64), 256>>>(Wo, bo, (float*)d_out);
}

// round 11
// speedup vs baseline: 2.9195x; 1.0121x over previous
#include <cuda_runtime.h>
#include <cuda_fp16.h>
#include <mma.h>
using namespace nvcuda;

#define BB 2
#define LL 1536
#define DD 1024
#define HH 16
#define PP 1024
#define HDIM 64

// qkv dynamic smem layout (bytes): BiasT(8448) + union(tiles double-buffered, Cst 33792)
#define QKV_TILE_OFF 8448
#define QKV_SMEM_BYTES (8448 + 33792)

// ---------------- fused_all smem layout (bytes) ----------------
#define FROWS 16
#define PSTRF 1544                              // Sf row stride (floats); also Ps stride (halves)
#define SF_OFF   0                              // float Sf[16][1544] = 98816  (Ps half[16][1544]=49408 aliases at 0)
#define VRED_OFF 65536                          // float Vred[4][16][68] = 17408 (inside Sf, above Ps)
#define KVS_OFF  98816                          // float kvs[1536] = 6144
#define W5_OFF   104960                         // float w5[5] (+pad)
#define Q_OFF    104992                         // half Qs[16][72] = 2304
#define KV_OFF   107328                         // half KVb[2][256][72] = 73728
#define FUSED_SMEM_BYTES (KV_OFF + 73728 + 32)  // ~181 KB

// ---------------- device scratch ----------------
__device__ __half g_Q[BB * HH * LL * HDIM];     // head-major [b,h,l,d], pre-scaled by 0.125
__device__ __half g_K[BB * HH * LL * HDIM];
__device__ __half g_V[BB * HH * LL * HDIM];
__device__ __half g_attn[BB * LL * PP];         // [b,l,h*64+d]

typedef wmma::fragment<wmma::matrix_a, 16, 16, 16, __half, wmma::row_major> HFragA;
typedef wmma::fragment<wmma::matrix_b, 16, 16, 16, __half, wmma::row_major> HFragB;
typedef wmma::fragment<wmma::accumulator, 16, 16, 16, float> FragC;

typedef wmma::fragment<wmma::matrix_a, 8, 32, 16, __half, wmma::row_major> PFragA;
typedef wmma::fragment<wmma::matrix_b, 8, 32, 16, __half, wmma::row_major> PFragB;
typedef wmma::fragment<wmma::matrix_b, 8, 32, 16, __half, wmma::col_major> PFragBc;
typedef wmma::fragment<wmma::accumulator, 8, 32, 16, float> PFragC;

// float4 -> 4 halves (RN), packed as uint2
__device__ __forceinline__ uint2 h4(float4 v) {
    __half2 a = __floats2half2_rn(v.x, v.y);
    __half2 b = __floats2half2_rn(v.z, v.w);
    uint2 r;
    r.x = *(unsigned*)&a;
    r.y = *(unsigned*)&b;
    return r;
}

// ---------------- QKV projection: fp32 in, HALF out (head-major), double-buffered ----
__global__ __launch_bounds__(256, 2) void qkv_wmma(const float* __restrict__ A,
                                                   const float* __restrict__ Wq,
                                                   const float* __restrict__ bq,
                                                   const float* __restrict__ Wk,
                                                   const float* __restrict__ bk,
                                                   const float* __restrict__ Wv,
                                                   const float* __restrict__ bv) {
    const int zz = blockIdx.z;
    const float* W = (zz == 0) ? Wq : (zz == 1) ? Wk : Wv;
    const float* bias = (zz == 0) ? bq : (zz == 1) ? bk : bv;
    __half* C = (zz == 0) ? g_Q : (zz == 1) ? g_K : g_V;

    extern __shared__ char dsm[];
    float* BiasT = (float*)dsm;                       // [16][132]
    __half* AsB = (__half*)(dsm + QKV_TILE_OFF);      // [2][64][40]
    __half* BsB = AsB + 2 * 64 * 40;                  // [2][32][136]
    float* Cst = (float*)(dsm + QKV_TILE_OFF);        // [64][132] (reuses tiles after loop)

    const int m0 = blockIdx.y * 64;
    const int n0 = blockIdx.x * 128;
    const int t = threadIdx.x;
    const int warp = t >> 5;
    const int wm = (warp & 3) * 16;
    const int wn = (warp >> 2) * 64;

#pragma unroll
    for (int r = 0; r < 2; r++) {
        int idx = t + r * 256;
        int row = idx >> 5;
        int col = (idx & 31) << 2;
        *(float4*)(BiasT + row * 132 + col) = *(const float4*)(bias + n0 + col);
    }

    FragC c[4];
#pragma unroll
    for (int j = 0; j < 4; j++) wmma::fill_fragment(c[j], 0.f);

    const int arow = t >> 3, acol = (t & 7) << 2;
    const int brow = t >> 5, bcol = (t & 31) << 2;

    float4 apre[2], bpre[4];
#pragma unroll
    for (int r = 0; r < 2; r++)
        apre[r] = *(const float4*)(A + (size_t)(m0 + arow + r * 32) * DD + acol);
#pragma unroll
    for (int r = 0; r < 4; r++)
        bpre[r] = *(const float4*)(W + (size_t)(brow + r * 8) * PP + n0 + bcol);
#pragma unroll
    for (int r = 0; r < 2; r++) *(uint2*)(AsB + (arow + r * 32) * 40 + acol) = h4(apre[r]);
#pragma unroll
    for (int r = 0; r < 4; r++) *(uint2*)(BsB + (brow + r * 8) * 136 + bcol) = h4(bpre[r]);
    __syncthreads();

    for (int k0 = 0; k0 < DD; k0 += 32) {
        const int cur = (k0 >> 5) & 1, nxt = cur ^ 1;
        const bool more = (k0 + 32 < DD);
        if (more) {
#pragma unroll
            for (int r = 0; r < 2; r++)
                apre[r] = *(const float4*)(A + (size_t)(m0 + arow + r * 32) * DD + k0 + 32 + acol);
#pragma unroll
            for (int r = 0; r < 4; r++)
                bpre[r] = *(const float4*)(W + (size_t)(k0 + 32 + brow + r * 8) * PP + n0 + bcol);
        }
        const __half* Asc = AsB + cur * 64 * 40;
        const __half* Bsc = BsB + cur * 32 * 136;
#pragma unroll
        for (int kk = 0; kk < 32; kk += 16) {
            HFragA a;
            wmma::load_matrix_sync(a, Asc + wm * 40 + kk, 40);
#pragma unroll
            for (int j = 0; j < 4; j++) {
                HFragB b;
                wmma::load_matrix_sync(b, Bsc + kk * 136 + wn + j * 16, 136);
                wmma::mma_sync(c[j], a, b, c[j]);
            }
        }
        if (more) {
#pragma unroll
            for (int r = 0; r < 2; r++) *(uint2*)(AsB + nxt * 64 * 40 + (arow + r * 32) * 40 + acol) = h4(apre[r]);
#pragma unroll
            for (int r = 0; r < 4; r++) *(uint2*)(BsB + nxt * 32 * 136 + (brow + r * 8) * 136 + bcol) = h4(bpre[r]);
        }
        __syncthreads();
    }

    const float scale = (zz == 0) ? 0.125f : 1.0f;
#pragma unroll
    for (int j = 0; j < 4; j++) {
        FragC bf;
        wmma::load_matrix_sync(bf, BiasT + wn + j * 16, 132, wmma::mem_row_major);
#pragma unroll
        for (int e = 0; e < bf.num_elements; e++) c[j].x[e] = (c[j].x[e] + bf.x[e]) * scale;
    }

#pragma unroll
    for (int j = 0; j < 4; j++)
        wmma::store_matrix_sync(Cst + wm * 132 + wn + j * 16, c[j], 132, wmma::mem_row_major);
    __syncthreads();

    const int b = m0 / LL;
    const int l0 = m0 - b * LL;
    const int hbase = n0 >> 6;
#pragma unroll
    for (int r = 0; r < 8; r++) {
        int idx = t + r * 256;
        int row = idx >> 5;
        int col = (idx & 31) << 2;
        uint2 hv = h4(*(float4*)(Cst + row * 132 + col));
        int h = hbase + (col >> 6);
        int d = col & 63;
        __half* out = C + (((size_t)(b * HH + h)) * LL + l0 + row) * HDIM + d;
        *(uint2*)out = hv;
    }
}

// ---------------- output projection: HALF A (g_attn), fp32 out, double-buffered ------
__global__ __launch_bounds__(256, 2) void oproj_wmma(const float* __restrict__ W,
                                                     const float* __restrict__ bias,
                                                     float* __restrict__ Cout) {
    __shared__ __half As[2][64][40];
    __shared__ __half Bs[2][32][136];
    __shared__ float BiasT[16][132];

    const __half* A = g_attn;
    const int m0 = blockIdx.y * 64;
    const int n0 = blockIdx.x * 128;
    const int t = threadIdx.x;
    const int warp = t >> 5;
    const int wm = (warp & 3) * 16;
    const int wn = (warp >> 2) * 64;

#pragma unroll
    for (int r = 0; r < 2; r++) {
        int idx = t + r * 256;
        int row = idx >> 5;
        int col = (idx & 31) << 2;
        *(float4*)&BiasT[row][col] = *(const float4*)(bias + n0 + col);
    }

    FragC c[4];
#pragma unroll
    for (int j = 0; j < 4; j++) wmma::fill_fragment(c[j], 0.f);

    const int arow = t >> 3, acol = (t & 7) << 2;
    const int brow = t >> 5, bcol = (t & 31) << 2;

    uint2 apre[2];
    float4 bpre[4];
#pragma unroll
    for (int r = 0; r < 2; r++)
        apre[r] = *(const uint2*)(A + (size_t)(m0 + arow + r * 32) * DD + acol);
#pragma unroll
    for (int r = 0; r < 4; r++)
        bpre[r] = *(const float4*)(W + (size_t)(brow + r * 8) * PP + n0 + bcol);
#pragma unroll
    for (int r = 0; r < 2; r++) *(uint2*)&As[0][arow + r * 32][acol] = apre[r];
#pragma unroll
    for (int r = 0; r < 4; r++) *(uint2*)&Bs[0][brow + r * 8][bcol] = h4(bpre[r]);
    __syncthreads();

    for (int k0 = 0; k0 < DD; k0 += 32) {
        const int cur = (k0 >> 5) & 1, nxt = cur ^ 1;
        const bool more = (k0 + 32 < DD);
        if (more) {
#pragma unroll
            for (int r = 0; r < 2; r++)
                apre[r] = *(const uint2*)(A + (size_t)(m0 + arow + r * 32) * DD + k0 + 32 + acol);
#pragma unroll
            for (int r = 0; r < 4; r++)
                bpre[r] = *(const float4*)(W + (size_t)(k0 + 32 + brow + r * 8) * PP + n0 + bcol);
        }
#pragma unroll
        for (int kk = 0; kk < 32; kk += 16) {
            HFragA a;
            wmma::load_matrix_sync(a, &As[cur][wm][kk], 40);
#pragma unroll
            for (int j = 0; j < 4; j++) {
                HFragB b;
                wmma::load_matrix_sync(b, &Bs[cur][kk][wn + j * 16], 136);
                wmma::mma_sync(c[j], a, b, c[j]);
            }
        }
        if (more) {
#pragma unroll
            for (int r = 0; r < 2; r++) *(uint2*)&As[nxt][arow + r * 32][acol] = apre[r];
#pragma unroll
            for (int r = 0; r < 4; r++) *(uint2*)&Bs[nxt][brow + r * 8][bcol] = h4(bpre[r]);
        }
        __syncthreads();
    }

#pragma unroll
    for (int j = 0; j < 4; j++) {
        FragC bf;
        wmma::load_matrix_sync(bf, &BiasT[0][wn + j * 16], 132, wmma::mem_row_major);
#pragma unroll
        for (int e = 0; e < bf.num_elements; e++) c[j].x[e] += bf.x[e];
    }

    float* base = Cout + (size_t)(m0 + wm) * PP + n0 + wn;
#pragma unroll
    for (int j = 0; j < 4; j++)
        wmma::store_matrix_sync(base + j * 16, c[j], PP, wmma::mem_row_major);
}

// ---------------- fused_all: S = Q@K^T (SMEM) + softmax + diffusion + p@V -------------
// One block = 16 q-rows of one (b,h). 512 threads / 16 warps. S never touches DRAM.
__global__ __launch_bounds__(512, 1) void fused_all(const int* __restrict__ mask,
                                                    const float* __restrict__ kw) {
    extern __shared__ char smraw[];
    float* Sf = (float*)smraw;                         // [16][PSTRF] fp32 scores
    __half* Ps = (__half*)smraw;                       // [16][PSTRF] half p (aliases Sf)
    float* Vred = (float*)(smraw + VRED_OFF);          // [4][16][68]
    float* kvs = (float*)(smraw + KVS_OFF);            // [1536]
    float* w5s = (float*)(smraw + W5_OFF);             // [5]
    __half* Qs = (__half*)(smraw + Q_OFF);             // [16][72]
    __half* KVb = (__half*)(smraw + KV_OFF);           // [2][256][72]

    const int t = threadIdx.x;
    const int warp = t >> 5, lane = t & 31;
    const int row0 = blockIdx.x * FROWS;
    const int z = row0 / LL;
    const int q0 = row0 - z * LL;
    const int b = z >> 4;
    const int h = z & 15;
    const int* mrow = mask + b * LL;
    const __half* Qg = g_Q + ((size_t)z * LL + q0) * HDIM;
    const __half* Kg = g_K + (size_t)z * LL * HDIM;
    const __half* Vg = g_V + (size_t)z * LL * HDIM;

    // ---- init: w5, kvs, Q tile ----
    if (t == 0) {
        float mxw = kw[0];
#pragma unroll
        for (int j = 1; j < 5; j++) mxw = fmaxf(mxw, kw[j]);
        float e[5], s = 0.f;
#pragma unroll
        for (int j = 0; j < 5; j++) { e[j] = __expf(kw[j] - mxw); s += e[j]; }
#pragma unroll
        for (int j = 0; j < 5; j++) w5s[j] = e[j] / s;
    }
    if (t < LL / 4) {
        int4 m4 = *(const int4*)(mrow + t * 4);
        *(float4*)(kvs + t * 4) = make_float4(m4.x > 0 ? 1.f : 0.f, m4.y > 0 ? 1.f : 0.f,
                                              m4.z > 0 ? 1.f : 0.f, m4.w > 0 ? 1.f : 0.f);
    }
    if (t < 256) {
        int row = t >> 4, col = (t & 15) << 2;
        *(uint2*)(Qs + row * 72 + col) = *(const uint2*)(Qg + (size_t)row * HDIM + col);
    }

    // ---- S-compute: 6 slabs of 256 key-rows, double-buffered K ----
    uint2 kpre[8];
#pragma unroll
    for (int r = 0; r < 8; r++) {
        int u = t + r * 512;
        int row = u >> 4, col = (u & 15) << 2;
        kpre[r] = *(const uint2*)(Kg + (size_t)row * HDIM + col);
    }
#pragma unroll
    for (int r = 0; r < 8; r++) {
        int u = t + r * 512;
        int row = u >> 4, col = (u & 15) << 2;
        *(uint2*)(KVb + row * 72 + col) = kpre[r];
    }
    __syncthreads();

    const int si = warp >> 3;     // 0..1 row-group (8 rows)
    const int sj = warp & 7;      // 0..7 col tile (32 keys)

    for (int s = 0; s < 6; s++) {
        const int cur = s & 1, nxt = cur ^ 1;
        const bool more = (s + 1 < 6);
        if (more) {
#pragma unroll
            for (int r = 0; r < 8; r++) {
                int u = t + r * 512;
                int row = u >> 4, col = (u & 15) << 2;
                kpre[r] = *(const uint2*)(Kg + (size_t)((s + 1) * 256 + row) * HDIM + col);
            }
        }
        const __half* Kc = KVb + cur * 256 * 72;
        PFragC sacc;
        wmma::fill_fragment(sacc, 0.f);
#pragma unroll
        for (int kk = 0; kk < 64; kk += 16) {
            PFragA a;
            PFragBc bb;
            wmma::load_matrix_sync(a, Qs + (si * 8) * 72 + kk, 72);
            wmma::load_matrix_sync(bb, Kc + (sj * 32) * 72 + kk, 72);
            wmma::mma_sync(sacc, a, bb, sacc);
        }
        wmma::store_matrix_sync(Sf + (size_t)(si * 8) * PSTRF + s * 256 + sj * 32, sacc,
                                PSTRF, wmma::mem_row_major);
        if (more) {
#pragma unroll
            for (int r = 0; r < 8; r++) {
                int u = t + r * 512;
                int row = u >> 4, col = (u & 15) << 2;
                *(uint2*)(KVb + nxt * 256 * 72 + row * 72 + col) = kpre[r];
            }
        }
        __syncthreads();
    }

    const float w0 = w5s[0], w1 = w5s[1], w2 = w5s[2], w3 = w5s[3], w4 = w5s[4];
    const float4* kvs4 = (const float4*)kvs;

    // ---- phase 1: warp-per-row softmax + diffusion (register resident) ----
    {
        const float* srow = Sf + (size_t)warp * PSTRF;
        float4 p4[12];
        float mx = -3.4e38f;
#pragma unroll
        for (int k = 0; k < 12; k++) {
            int m = lane + 32 * k;
            float4 v = *(const float4*)(srow + (size_t)m * 4);
            float4 kv = kvs4[m];
            v.x += (kv.x > 0.f) ? 0.f : -1e9f;
            v.y += (kv.y > 0.f) ? 0.f : -1e9f;
            v.z += (kv.z > 0.f) ? 0.f : -1e9f;
            v.w += (kv.w > 0.f) ? 0.f : -1e9f;
            p4[k] = v;
            mx = fmaxf(mx, fmaxf(fmaxf(v.x, v.y), fmaxf(v.z, v.w)));
        }
        __syncthreads();   // all warps have their S row in registers; Sf may now be overwritten
#pragma unroll
        for (int o = 16; o; o >>= 1) mx = fmaxf(mx, __shfl_xor_sync(0xffffffffu, mx, o));

        float s = 0.f;
#pragma unroll
        for (int k = 0; k < 12; k++) {
            float4 v = p4[k];
            v.x = __expf(v.x - mx); v.y = __expf(v.y - mx);
            v.z = __expf(v.z - mx); v.w = __expf(v.w - mx);
            p4[k] = v;
            s += v.x + v.y + v.z + v.w;
        }
#pragma unroll
        for (int o = 16; o; o >>= 1) s += __shfl_xor_sync(0xffffffffu, s, o);
        float inv = 1.f / s;
#pragma unroll
        for (int k = 0; k < 12; k++) {
            p4[k].x *= inv; p4[k].y *= inv; p4[k].z *= inv; p4[k].w *= inv;
        }

#pragma unroll 1
        for (int step = 0; step < 3; step++) {
            float4 c4[12];
            float sa = 0.f;
            float4 prev31 = make_float4(0.f, 0.f, 0.f, 0.f);
#pragma unroll
            for (int k = 0; k < 12; k++) {
                float4 o4 = p4[k];
                float4 h4v;
                h4v.x = __shfl_up_sync(0xffffffffu, o4.x, 1);
                h4v.y = __shfl_up_sync(0xffffffffu, o4.y, 1);
                h4v.z = __shfl_up_sync(0xffffffffu, o4.z, 1);
                h4v.w = __shfl_up_sync(0xffffffffu, o4.w, 1);
                float4 n31;
                n31.x = __shfl_sync(0xffffffffu, o4.x, 31);
                n31.y = __shfl_sync(0xffffffffu, o4.y, 31);
                n31.z = __shfl_sync(0xffffffffu, o4.z, 31);
                n31.w = __shfl_sync(0xffffffffu, o4.w, 31);
                if (lane == 0) h4v = prev31;
                prev31 = n31;
                float4 kv = kvs4[lane + 32 * k];
                float4 cc;
                cc.x = (w0 * h4v.x + w1 * h4v.y + w2 * h4v.z + w3 * h4v.w + w4 * o4.x) * kv.x;
                cc.y = (w0 * h4v.y + w1 * h4v.z + w2 * h4v.w + w3 * o4.x + w4 * o4.y) * kv.y;
                cc.z = (w0 * h4v.z + w1 * h4v.w + w2 * o4.x + w3 * o4.y + w4 * o4.z) * kv.z;
                cc.w = (w0 * h4v.w + w1 * o4.x + w2 * o4.y + w3 * o4.z + w4 * o4.w) * kv.w;
                c4[k] = cc;
                sa += cc.x + cc.y + cc.z + cc.w;
            }
#pragma unroll
            for (int o = 16; o; o >>= 1) sa += __shfl_xor_sync(0xffffffffu, sa, o);
            const float rmul = 0.02f / (sa + 1e-9f);
#pragma unroll
            for (int k = 0; k < 12; k++) {
                p4[k].x = 0.98f * p4[k].x + rmul * c4[k].x;
                p4[k].y = 0.98f * p4[k].y + rmul * c4[k].y;
                p4[k].z = 0.98f * p4[k].z + rmul * c4[k].z;
                p4[k].w = 0.98f * p4[k].w + rmul * c4[k].w;
            }
        }

        __half* pr = Ps + (size_t)warp * PSTRF;
#pragma unroll
        for (int k = 0; k < 12; k++)
            *(uint2*)(pr + (size_t)(lane + 32 * k) * 4) = h4(p4[k]);
    }
    __syncthreads();

    // ---- phase 2: out[16x64] = p[16x1536] @ V[1536x64], m8n32k16, double-buffered ----
    const int pi = warp >> 3;            // 0..1 row-group
    const int pg = (warp >> 1) & 3;      // 0..3 k-group (32 rows within 128-chunk)
    const int pj = warp & 1;             // 0..1 32-col output tile

    PFragC acc;
    wmma::fill_fragment(acc, 0.f);

    uint2 vpre[4];
#pragma unroll
    for (int r = 0; r < 4; r++) {
        int u = t + r * 512;
        int row = u >> 4, col = (u & 15) << 2;
        vpre[r] = *(const uint2*)(Vg + (size_t)row * HDIM + col);
    }
#pragma unroll
    for (int r = 0; r < 4; r++) {
        int u = t + r * 512;
        int row = u >> 4, col = (u & 15) << 2;
        *(uint2*)(KVb + row * 72 + col) = vpre[r];
    }
    __syncthreads();

    for (int c = 0; c < 12; c++) {
        const int cur = c & 1, nxt = cur ^ 1;
        const bool more = (c + 1 < 12);
        if (more) {
#pragma unroll
            for (int r = 0; r < 4; r++) {
                int u = t + r * 512;
                int row = u >> 4, col = (u & 15) << 2;
                vpre[r] = *(const uint2*)(Vg + (size_t)((c + 1) * 128 + row) * HDIM + col);
            }
        }
        const __half* Vc = KVb + cur * 128 * 72;
#pragma unroll
        for (int kk = 0; kk < 32; kk += 16) {
            PFragA a;
            PFragB bb;
            wmma::load_matrix_sync(a, Ps + (size_t)(pi * 8) * PSTRF + c * 128 + pg * 32 + kk, PSTRF);
            wmma::load_matrix_sync(bb, Vc + (pg * 32 + kk) * 72 + pj * 32, 72);
            wmma::mma_sync(acc, a, bb, acc);
        }
        if (more) {
#pragma unroll
            for (int r = 0; r < 4; r++) {
                int u = t + r * 512;
                int row = u >> 4, col = (u & 15) << 2;
                *(uint2*)(KVb + nxt * 128 * 72 + row * 72 + col) = vpre[r];
            }
        }
        __syncthreads();
    }

    wmma::store_matrix_sync(Vred + (size_t)(pg * 16 + pi * 8) * 68 + pj * 32, acc,
                            68, wmma::mem_row_major);
    __syncthreads();

    if (t < 256) {
        const int row = t >> 4;          // 0..15
        const int col = (t & 15) << 2;   // 0..60
        float4 s0 = *(float4*)(Vred + (size_t)row * 68 + col);
#pragma unroll
        for (int gg = 1; gg < 4; gg++) {
            float4 a0 = *(float4*)(Vred + (size_t)(gg * 16 + row) * 68 + col);
            s0.x += a0.x; s0.y += a0.y; s0.z += a0.z; s0.w += a0.w;
        }
        __half* out = g_attn + ((size_t)(b * LL + q0 + row)) * PP + h * 64 + col;
        *(uint2*)out = h4(s0);
    }
}

// ---------------- launch ----------------
extern "C" void kernel_launch(void* const* d_in, const int* in_sizes, int n_in,
                              void* d_out, int out_size) {
    const float* hs = (const float*)d_in[0];
    const int* mask = (const int*)d_in[1];
    const float* Wq = (const float*)d_in[2];
    const float* bq = (const float*)d_in[3];
    const float* Wk = (const float*)d_in[4];
    const float* bk = (const float*)d_in[5];
    const float* Wv = (const float*)d_in[6];
    const float* bv = (const float*)d_in[7];
    const float* Wo = (const float*)d_in[8];
    const float* bo = (const float*)d_in[9];
    const float* kw = (const float*)d_in[10];

    cudaFuncSetAttribute(fused_all, cudaFuncAttributeMaxDynamicSharedMemorySize, FUSED_SMEM_BYTES);

    qkv_wmma<<<dim3(PP / 128, (BB * LL) / 64, 3), 256, QKV_SMEM_BYTES>>>(hs, Wq, bq, Wk, bk, Wv, bv);

    fused_all<<<(BB * HH * LL) / FROWS, 512, FUSED_SMEM_BYTES>>>(mask, kw);

    oproj_wmma<<<dim3(PP / 128, (BB * LL) / 64), 256>>>(Wo, bo, (float*)d_out);
}

// round 12
// speedup vs baseline: 2.9196x; 1.0001x over previous
#include <cuda_runtime.h>
#include <cuda_fp16.h>
#include <mma.h>
using namespace nvcuda;

#define BB 2
#define LL 1536
#define DD 1024
#define HH 16
#define PP 1024
#define HDIM 64

// qkv dynamic smem layout (bytes): BiasT(8448) + union(tiles double-buffered, Cst 33792)
#define QKV_TILE_OFF 8448
#define QKV_SMEM_BYTES (8448 + 33792)

// ---------------- fused_all smem layout (bytes) ----------------
#define FROWS 16
#define PSTRF 1544                              // Sf row stride (floats); also Ps stride (halves)
// Sf rows: [8-float zero pad][1536 data] = 1544 floats exactly.
#define SF_OFF   0                              // float Sf[16][1544] = 98816 (Ps half[16][1544]=49408 aliases at 0)
#define VRED_OFF 65536                          // float Vred[4][16][68] = 17408 (above Ps, used only in phase 2)
#define KVS_OFF  98816                          // float kvs[1536] = 6144
#define W5_OFF   104960                         // float w5[5] (+pad)
#define Q_OFF    104992                         // half Qs[16][72] = 2304
#define KV_OFF   107328                         // half KVb[2][256][72] = 73728
#define FUSED_SMEM_BYTES (KV_OFF + 73728 + 32)  // ~181 KB

// ---------------- device scratch ----------------
__device__ __half g_Q[BB * HH * LL * HDIM];     // head-major [b,h,l,d], pre-scaled by 0.125
__device__ __half g_K[BB * HH * LL * HDIM];
__device__ __half g_V[BB * HH * LL * HDIM];
__device__ __half g_attn[BB * LL * PP];         // [b,l,h*64+d]

typedef wmma::fragment<wmma::matrix_a, 16, 16, 16, __half, wmma::row_major> HFragA;
typedef wmma::fragment<wmma::matrix_b, 16, 16, 16, __half, wmma::row_major> HFragB;
typedef wmma::fragment<wmma::accumulator, 16, 16, 16, float> FragC;

typedef wmma::fragment<wmma::matrix_a, 8, 32, 16, __half, wmma::row_major> PFragA;
typedef wmma::fragment<wmma::matrix_b, 8, 32, 16, __half, wmma::row_major> PFragB;
typedef wmma::fragment<wmma::matrix_b, 8, 32, 16, __half, wmma::col_major> PFragBc;
typedef wmma::fragment<wmma::accumulator, 8, 32, 16, float> PFragC;

// float4 -> 4 halves (RN), packed as uint2
__device__ __forceinline__ uint2 h4(float4 v) {
    __half2 a = __floats2half2_rn(v.x, v.y);
    __half2 b = __floats2half2_rn(v.z, v.w);
    uint2 r;
    r.x = *(unsigned*)&a;
    r.y = *(unsigned*)&b;
    return r;
}

// ---------------- QKV projection: fp32 in, HALF out (head-major), double-buffered ----
__global__ __launch_bounds__(256, 2) void qkv_wmma(const float* __restrict__ A,
                                                   const float* __restrict__ Wq,
                                                   const float* __restrict__ bq,
                                                   const float* __restrict__ Wk,
                                                   const float* __restrict__ bk,
                                                   const float* __restrict__ Wv,
                                                   const float* __restrict__ bv) {
    const int zz = blockIdx.z;
    const float* W = (zz == 0) ? Wq : (zz == 1) ? Wk : Wv;
    const float* bias = (zz == 0) ? bq : (zz == 1) ? bk : bv;
    __half* C = (zz == 0) ? g_Q : (zz == 1) ? g_K : g_V;

    extern __shared__ char dsm[];
    float* BiasT = (float*)dsm;                       // [16][132]
    __half* AsB = (__half*)(dsm + QKV_TILE_OFF);      // [2][64][40]
    __half* BsB = AsB + 2 * 64 * 40;                  // [2][32][136]
    float* Cst = (float*)(dsm + QKV_TILE_OFF);        // [64][132] (reuses tiles after loop)

    const int m0 = blockIdx.y * 64;
    const int n0 = blockIdx.x * 128;
    const int t = threadIdx.x;
    const int warp = t >> 5;
    const int wm = (warp & 3) * 16;
    const int wn = (warp >> 2) * 64;

#pragma unroll
    for (int r = 0; r < 2; r++) {
        int idx = t + r * 256;
        int row = idx >> 5;
        int col = (idx & 31) << 2;
        *(float4*)(BiasT + row * 132 + col) = *(const float4*)(bias + n0 + col);
    }

    FragC c[4];
#pragma unroll
    for (int j = 0; j < 4; j++) wmma::fill_fragment(c[j], 0.f);

    const int arow = t >> 3, acol = (t & 7) << 2;
    const int brow = t >> 5, bcol = (t & 31) << 2;

    float4 apre[2], bpre[4];
#pragma unroll
    for (int r = 0; r < 2; r++)
        apre[r] = *(const float4*)(A + (size_t)(m0 + arow + r * 32) * DD + acol);
#pragma unroll
    for (int r = 0; r < 4; r++)
        bpre[r] = *(const float4*)(W + (size_t)(brow + r * 8) * PP + n0 + bcol);
#pragma unroll
    for (int r = 0; r < 2; r++) *(uint2*)(AsB + (arow + r * 32) * 40 + acol) = h4(apre[r]);
#pragma unroll
    for (int r = 0; r < 4; r++) *(uint2*)(BsB + (brow + r * 8) * 136 + bcol) = h4(bpre[r]);
    __syncthreads();

    for (int k0 = 0; k0 < DD; k0 += 32) {
        const int cur = (k0 >> 5) & 1, nxt = cur ^ 1;
        const bool more = (k0 + 32 < DD);
        if (more) {
#pragma unroll
            for (int r = 0; r < 2; r++)
                apre[r] = *(const float4*)(A + (size_t)(m0 + arow + r * 32) * DD + k0 + 32 + acol);
#pragma unroll
            for (int r = 0; r < 4; r++)
                bpre[r] = *(const float4*)(W + (size_t)(k0 + 32 + brow + r * 8) * PP + n0 + bcol);
        }
        const __half* Asc = AsB + cur * 64 * 40;
        const __half* Bsc = BsB + cur * 32 * 136;
#pragma unroll
        for (int kk = 0; kk < 32; kk += 16) {
            HFragA a;
            wmma::load_matrix_sync(a, Asc + wm * 40 + kk, 40);
#pragma unroll
            for (int j = 0; j < 4; j++) {
                HFragB b;
                wmma::load_matrix_sync(b, Bsc + kk * 136 + wn + j * 16, 136);
                wmma::mma_sync(c[j], a, b, c[j]);
            }
        }
        if (more) {
#pragma unroll
            for (int r = 0; r < 2; r++) *(uint2*)(AsB + nxt * 64 * 40 + (arow + r * 32) * 40 + acol) = h4(apre[r]);
#pragma unroll
            for (int r = 0; r < 4; r++) *(uint2*)(BsB + nxt * 32 * 136 + (brow + r * 8) * 136 + bcol) = h4(bpre[r]);
        }
        __syncthreads();
    }

    const float scale = (zz == 0) ? 0.125f : 1.0f;
#pragma unroll
    for (int j = 0; j < 4; j++) {
        FragC bf;
        wmma::load_matrix_sync(bf, BiasT + wn + j * 16, 132, wmma::mem_row_major);
#pragma unroll
        for (int e = 0; e < bf.num_elements; e++) c[j].x[e] = (c[j].x[e] + bf.x[e]) * scale;
    }

#pragma unroll
    for (int j = 0; j < 4; j++)
        wmma::store_matrix_sync(Cst + wm * 132 + wn + j * 16, c[j], 132, wmma::mem_row_major);
    __syncthreads();

    const int b = m0 / LL;
    const int l0 = m0 - b * LL;
    const int hbase = n0 >> 6;
#pragma unroll
    for (int r = 0; r < 8; r++) {
        int idx = t + r * 256;
        int row = idx >> 5;
        int col = (idx & 31) << 2;
        uint2 hv = h4(*(float4*)(Cst + row * 132 + col));
        int h = hbase + (col >> 6);
        int d = col & 63;
        __half* out = C + (((size_t)(b * HH + h)) * LL + l0 + row) * HDIM + d;
        *(uint2*)out = hv;
    }
}

// ---------------- output projection: HALF A (g_attn), fp32 out, double-buffered ------
__global__ __launch_bounds__(256, 2) void oproj_wmma(const float* __restrict__ W,
                                                     const float* __restrict__ bias,
                                                     float* __restrict__ Cout) {
    __shared__ __half As[2][64][40];
    __shared__ __half Bs[2][32][136];
    __shared__ float BiasT[16][132];

    const __half* A = g_attn;
    const int m0 = blockIdx.y * 64;
    const int n0 = blockIdx.x * 128;
    const int t = threadIdx.x;
    const int warp = t >> 5;
    const int wm = (warp & 3) * 16;
    const int wn = (warp >> 2) * 64;

#pragma unroll
    for (int r = 0; r < 2; r++) {
        int idx = t + r * 256;
        int row = idx >> 5;
        int col = (idx & 31) << 2;
        *(float4*)&BiasT[row][col] = *(const float4*)(bias + n0 + col);
    }

    FragC c[4];
#pragma unroll
    for (int j = 0; j < 4; j++) wmma::fill_fragment(c[j], 0.f);

    const int arow = t >> 3, acol = (t & 7) << 2;
    const int brow = t >> 5, bcol = (t & 31) << 2;

    uint2 apre[2];
    float4 bpre[4];
#pragma unroll
    for (int r = 0; r < 2; r++)
        apre[r] = *(const uint2*)(A + (size_t)(m0 + arow + r * 32) * DD + acol);
#pragma unroll
    for (int r = 0; r < 4; r++)
        bpre[r] = *(const float4*)(W + (size_t)(brow + r * 8) * PP + n0 + bcol);
#pragma unroll
    for (int r = 0; r < 2; r++) *(uint2*)&As[0][arow + r * 32][acol] = apre[r];
#pragma unroll
    for (int r = 0; r < 4; r++) *(uint2*)&Bs[0][brow + r * 8][bcol] = h4(bpre[r]);
    __syncthreads();

    for (int k0 = 0; k0 < DD; k0 += 32) {
        const int cur = (k0 >> 5) & 1, nxt = cur ^ 1;
        const bool more = (k0 + 32 < DD);
        if (more) {
#pragma unroll
            for (int r = 0; r < 2; r++)
                apre[r] = *(const uint2*)(A + (size_t)(m0 + arow + r * 32) * DD + k0 + 32 + acol);
#pragma unroll
            for (int r = 0; r < 4; r++)
                bpre[r] = *(const float4*)(W + (size_t)(k0 + 32 + brow + r * 8) * PP + n0 + bcol);
        }
#pragma unroll
        for (int kk = 0; kk < 32; kk += 16) {
            HFragA a;
            wmma::load_matrix_sync(a, &As[cur][wm][kk], 40);
#pragma unroll
            for (int j = 0; j < 4; j++) {
                HFragB b;
                wmma::load_matrix_sync(b, &Bs[cur][kk][wn + j * 16], 136);
                wmma::mma_sync(c[j], a, b, c[j]);
            }
        }
        if (more) {
#pragma unroll
            for (int r = 0; r < 2; r++) *(uint2*)&As[nxt][arow + r * 32][acol] = apre[r];
#pragma unroll
            for (int r = 0; r < 4; r++) *(uint2*)&Bs[nxt][brow + r * 8][bcol] = h4(bpre[r]);
        }
        __syncthreads();
    }

#pragma unroll
    for (int j = 0; j < 4; j++) {
        FragC bf;
        wmma::load_matrix_sync(bf, &BiasT[0][wn + j * 16], 132, wmma::mem_row_major);
#pragma unroll
        for (int e = 0; e < bf.num_elements; e++) c[j].x[e] += bf.x[e];
    }

    float* base = Cout + (size_t)(m0 + wm) * PP + n0 + wn;
#pragma unroll
    for (int j = 0; j < 4; j++)
        wmma::store_matrix_sync(base + j * 16, c[j], PP, wmma::mem_row_major);
}

// ---------------- fused_all: S = Q@K^T (SMEM) + softmax + diffusion + p@V -------------
// One block = 16 q-rows of one (b,h). 512 threads / 16 warps. S never touches DRAM.
// Diffusion halo comes from an SMEM float mirror of p (no cross-lane shfl).
__global__ __launch_bounds__(512, 1) void fused_all(const int* __restrict__ mask,
                                                    const float* __restrict__ kw) {
    extern __shared__ char smraw[];
    float* Sf = (float*)smraw;                         // [16][PSTRF] fp32: [8 pad][1536 data]
    __half* Ps = (__half*)smraw;                       // [16][PSTRF] half p (aliases Sf)
    float* Vred = (float*)(smraw + VRED_OFF);          // [4][16][68]
    float* kvs = (float*)(smraw + KVS_OFF);            // [1536]
    float* w5s = (float*)(smraw + W5_OFF);             // [5]
    __half* Qs = (__half*)(smraw + Q_OFF);             // [16][72]
    __half* KVb = (__half*)(smraw + KV_OFF);           // [2][256][72]

    const int t = threadIdx.x;
    const int warp = t >> 5, lane = t & 31;
    const int row0 = blockIdx.x * FROWS;
    const int z = row0 / LL;
    const int q0 = row0 - z * LL;
    const int b = z >> 4;
    const int h = z & 15;
    const int* mrow = mask + b * LL;
    const __half* Qg = g_Q + ((size_t)z * LL + q0) * HDIM;
    const __half* Kg = g_K + (size_t)z * LL * HDIM;
    const __half* Vg = g_V + (size_t)z * LL * HDIM;

    // ---- init: w5, kvs, Q tile ----
    if (t == 0) {
        float mxw = kw[0];
#pragma unroll
        for (int j = 1; j < 5; j++) mxw = fmaxf(mxw, kw[j]);
        float e[5], s = 0.f;
#pragma unroll
        for (int j = 0; j < 5; j++) { e[j] = __expf(kw[j] - mxw); s += e[j]; }
#pragma unroll
        for (int j = 0; j < 5; j++) w5s[j] = e[j] / s;
    }
    if (t < LL / 4) {
        int4 m4 = *(const int4*)(mrow + t * 4);
        *(float4*)(kvs + t * 4) = make_float4(m4.x > 0 ? 1.f : 0.f, m4.y > 0 ? 1.f : 0.f,
                                              m4.z > 0 ? 1.f : 0.f, m4.w > 0 ? 1.f : 0.f);
    }
    if (t < 256) {
        int row = t >> 4, col = (t & 15) << 2;
        *(uint2*)(Qs + row * 72 + col) = *(const uint2*)(Qg + (size_t)row * HDIM + col);
    }

    // ---- S-compute: 6 slabs of 256 key-rows, double-buffered K ----
    uint2 kpre[8];
#pragma unroll
    for (int r = 0; r < 8; r++) {
        int u = t + r * 512;
        int row = u >> 4, col = (u & 15) << 2;
        kpre[r] = *(const uint2*)(Kg + (size_t)row * HDIM + col);
    }
#pragma unroll
    for (int r = 0; r < 8; r++) {
        int u = t + r * 512;
        int row = u >> 4, col = (u & 15) << 2;
        *(uint2*)(KVb + row * 72 + col) = kpre[r];
    }
    __syncthreads();

    const int si = warp >> 3;     // 0..1 row-group (8 rows)
    const int sj = warp & 7;      // 0..7 col tile (32 keys)

    for (int s = 0; s < 6; s++) {
        const int cur = s & 1, nxt = cur ^ 1;
        const bool more = (s + 1 < 6);
        if (more) {
#pragma unroll
            for (int r = 0; r < 8; r++) {
                int u = t + r * 512;
                int row = u >> 4, col = (u & 15) << 2;
                kpre[r] = *(const uint2*)(Kg + (size_t)((s + 1) * 256 + row) * HDIM + col);
            }
        }
        const __half* Kc = KVb + cur * 256 * 72;
        PFragC sacc;
        wmma::fill_fragment(sacc, 0.f);
#pragma unroll
        for (int kk = 0; kk < 64; kk += 16) {
            PFragA a;
            PFragBc bb;
            wmma::load_matrix_sync(a, Qs + (si * 8) * 72 + kk, 72);
            wmma::load_matrix_sync(bb, Kc + (sj * 32) * 72 + kk, 72);
            wmma::mma_sync(sacc, a, bb, sacc);
        }
        // data region starts at +8 floats (32B-aligned)
        wmma::store_matrix_sync(Sf + (size_t)(si * 8) * PSTRF + 8 + s * 256 + sj * 32, sacc,
                                PSTRF, wmma::mem_row_major);
        if (more) {
#pragma unroll
            for (int r = 0; r < 8; r++) {
                int u = t + r * 512;
                int row = u >> 4, col = (u & 15) << 2;
                *(uint2*)(KVb + nxt * 256 * 72 + row * 72 + col) = kpre[r];
            }
        }
        __syncthreads();
    }

    const float w0 = w5s[0], w1 = w5s[1], w2 = w5s[2], w3 = w5s[3], w4 = w5s[4];
    const float4* kvs4 = (const float4*)kvs;

    // ---- phase 1: warp-per-row softmax + diffusion; halo via SMEM mirror, no shfl ----
    {
        float* rowF = Sf + (size_t)warp * PSTRF;   // [0..7]=pad, data at +8
        float4 p4[12];
        float mx = -3.4e38f;
#pragma unroll
        for (int k = 0; k < 12; k++) {
            int m = lane + 32 * k;
            float4 v = *(const float4*)(rowF + 8 + 4 * m);
            float4 kv = kvs4[m];
            v.x += (kv.x > 0.f) ? 0.f : -1e9f;
            v.y += (kv.y > 0.f) ? 0.f : -1e9f;
            v.z += (kv.z > 0.f) ? 0.f : -1e9f;
            v.w += (kv.w > 0.f) ? 0.f : -1e9f;
            p4[k] = v;
            mx = fmaxf(mx, fmaxf(fmaxf(v.x, v.y), fmaxf(v.z, v.w)));
        }
        if (lane < 2) *(float4*)(rowF + lane * 4) = make_float4(0.f, 0.f, 0.f, 0.f);
#pragma unroll
        for (int o = 16; o; o >>= 1) mx = fmaxf(mx, __shfl_xor_sync(0xffffffffu, mx, o));

        float s = 0.f;
#pragma unroll
        for (int k = 0; k < 12; k++) {
            float4 v = p4[k];
            v.x = __expf(v.x - mx); v.y = __expf(v.y - mx);
            v.z = __expf(v.z - mx); v.w = __expf(v.w - mx);
            p4[k] = v;
            s += v.x + v.y + v.z + v.w;
        }
#pragma unroll
        for (int o = 16; o; o >>= 1) s += __shfl_xor_sync(0xffffffffu, s, o);
        float inv = 1.f / s;
#pragma unroll
        for (int k = 0; k < 12; k++) {
            p4[k].x *= inv; p4[k].y *= inv; p4[k].z *= inv; p4[k].w *= inv;
            *(float4*)(rowF + 8 + 4 * (lane + 32 * k)) = p4[k];   // mirror to SMEM
        }
        __syncwarp();

#pragma unroll 1
        for (int step = 0; step < 3; step++) {
            float4 c4[12];
            float sa = 0.f;
            // pass A: read halo (group m-1) from SMEM mirror; own group from regs
#pragma unroll
            for (int k = 0; k < 12; k++) {
                int m = lane + 32 * k;
                float4 o4 = p4[k];
                float4 h4v = *(const float4*)(rowF + 4 + 4 * m);   // elements 4m-4..4m-1
                float4 kv = kvs4[m];
                float4 cc;
                cc.x = (w0 * h4v.x + w1 * h4v.y + w2 * h4v.z + w3 * h4v.w + w4 * o4.x) * kv.x;
                cc.y = (w0 * h4v.y + w1 * h4v.z + w2 * h4v.w + w3 * o4.x + w4 * o4.y) * kv.y;
                cc.z = (w0 * h4v.z + w1 * h4v.w + w2 * o4.x + w3 * o4.y + w4 * o4.z) * kv.z;
                cc.w = (w0 * h4v.w + w1 * o4.x + w2 * o4.y + w3 * o4.z + w4 * o4.w) * kv.w;
                c4[k] = cc;
                sa += cc.x + cc.y + cc.z + cc.w;
            }
#pragma unroll
            for (int o = 16; o; o >>= 1) sa += __shfl_xor_sync(0xffffffffu, sa, o);
            const float rmul = 0.02f / (sa + 1e-9f);
            __syncwarp();   // all halo reads done before mirror rewrite
            // pass B: update regs + mirror
#pragma unroll
            for (int k = 0; k < 12; k++) {
                p4[k].x = 0.98f * p4[k].x + rmul * c4[k].x;
                p4[k].y = 0.98f * p4[k].y + rmul * c4[k].y;
                p4[k].z = 0.98f * p4[k].z + rmul * c4[k].z;
                p4[k].w = 0.98f * p4[k].w + rmul * c4[k].w;
                *(float4*)(rowF + 8 + 4 * (lane + 32 * k)) = p4[k];
            }
            __syncwarp();
        }

        __syncthreads();   // all warps done with float mirrors; Sf may be overwritten by Ps
        __half* pr = Ps + (size_t)warp * PSTRF;
#pragma unroll
        for (int k = 0; k < 12; k++)
            *(uint2*)(pr + (size_t)(lane + 32 * k) * 4) = h4(p4[k]);
    }
    __syncthreads();

    // ---- phase 2: out[16x64] = p[16x1536] @ V[1536x64], m8n32k16, double-buffered ----
    const int pi = warp >> 3;            // 0..1 row-group
    const int pg = (warp >> 1) & 3;      // 0..3 k-group (32 rows within 128-chunk)
    const int pj = warp & 1;             // 0..1 32-col output tile

    PFragC acc;
    wmma::fill_fragment(acc, 0.f);

    uint2 vpre[4];
#pragma unroll
    for (int r = 0; r < 4; r++) {
        int u = t + r * 512;
        int row = u >> 4, col = (u & 15) << 2;
        vpre[r] = *(const uint2*)(Vg + (size_t)row * HDIM + col);
    }
#pragma unroll
    for (int r = 0; r < 4; r++) {
        int u = t + r * 512;
        int row = u >> 4, col = (u & 15) << 2;
        *(uint2*)(KVb + row * 72 + col) = vpre[r];
    }
    __syncthreads();

    for (int c = 0; c < 12; c++) {
        const int cur = c & 1, nxt = cur ^ 1;
        const bool more = (c + 1 < 12);
        if (more) {
#pragma unroll
            for (int r = 0; r < 4; r++) {
                int u = t + r * 512;
                int row = u >> 4, col = (u & 15) << 2;
                vpre[r] = *(const uint2*)(Vg + (size_t)((c + 1) * 128 + row) * HDIM + col);
            }
        }
        const __half* Vc = KVb + cur * 128 * 72;
#pragma unroll
        for (int kk = 0; kk < 32; kk += 16) {
            PFragA a;
            PFragB bb;
            wmma::load_matrix_sync(a, Ps + (size_t)(pi * 8) * PSTRF + c * 128 + pg * 32 + kk, PSTRF);
            wmma::load_matrix_sync(bb, Vc + (pg * 32 + kk) * 72 + pj * 32, 72);
            wmma::mma_sync(acc, a, bb, acc);
        }
        if (more) {
#pragma unroll
            for (int r = 0; r < 4; r++) {
                int u = t + r * 512;
                int row = u >> 4, col = (u & 15) << 2;
                *(uint2*)(KVb + nxt * 128 * 72 + row * 72 + col) = vpre[r];
            }
        }
        __syncthreads();
    }

    wmma::store_matrix_sync(Vred + (size_t)(pg * 16 + pi * 8) * 68 + pj * 32, acc,
                            68, wmma::mem_row_major);
    __syncthreads();

    if (t < 256) {
        const int row = t >> 4;          // 0..15
        const int col = (t & 15) << 2;   // 0..60
        float4 s0 = *(float4*)(Vred + (size_t)row * 68 + col);
#pragma unroll
        for (int gg = 1; gg < 4; gg++) {
            float4 a0 = *(float4*)(Vred + (size_t)(gg * 16 + row) * 68 + col);
            s0.x += a0.x; s0.y += a0.y; s0.z += a0.z; s0.w += a0.w;
        }
        __half* out = g_attn + ((size_t)(b * LL + q0 + row)) * PP + h * 64 + col;
        *(uint2*)out = h4(s0);
    }
}

// ---------------- launch ----------------
extern "C" void kernel_launch(void* const* d_in, const int* in_sizes, int n_in,
                              void* d_out, int out_size) {
    const float* hs = (const float*)d_in[0];
    const int* mask = (const int*)d_in[1];
    const float* Wq = (const float*)d_in[2];
    const float* bq = (const float*)d_in[3];
    const float* Wk = (const float*)d_in[4];
    const float* bk = (const float*)d_in[5];
    const float* Wv = (const float*)d_in[6];
    const float* bv = (const float*)d_in[7];
    const float* Wo = (const float*)d_in[8];
    const float* bo = (const float*)d_in[9];
    const float* kw = (const float*)d_in[10];

    cudaFuncSetAttribute(fused_all, cudaFuncAttributeMaxDynamicSharedMemorySize, FUSED_SMEM_BYTES);

    qkv_wmma<<<dim3(PP / 128, (BB * LL) / 64, 3), 256, QKV_SMEM_BYTES>>>(hs, Wq, bq, Wk, bk, Wv, bv);

    fused_all<<<(BB * HH * LL) / FROWS, 512, FUSED_SMEM_BYTES>>>(mask, kw);

    oproj_wmma<<<dim3(PP / 128, (BB * LL) / 64), 256>>>(Wo, bo, (float*)d_out);
}

// round 13
// speedup vs baseline: 3.2227x; 1.1038x over previous
#include <cuda_runtime.h>
#include <cuda_fp16.h>
#include <mma.h>
using namespace nvcuda;

#define BB 2
#define LL 1536
#define DD 1024
#define HH 16
#define PP 1024
#define HDIM 64

// gemm128 dynamic smem (bytes): BiasT(8448) + union(tiles 37888, Cst 67584)
#define G_TILE_OFF 8448
#define G_SMEM_BYTES (8448 + 67584)

// ---------------- fused_all smem layout (bytes) ----------------
#define FROWS 16
#define PSTRF 1544
#define SF_OFF   0
#define VRED_OFF 65536
#define KVS_OFF  98816
#define W5_OFF   104960
#define Q_OFF    104992
#define KV_OFF   107328
#define FUSED_SMEM_BYTES (KV_OFF + 73728 + 32)

// half arena: hs | Wq | Wk | Wv | Wo
#define AH_OFF  0
#define WQ_OFF  3145728
#define WK_OFF  4194304
#define WV_OFF  5242880
#define WO_OFF  6291456
__device__ __half g_H[7340032];

// ---------------- device scratch ----------------
__device__ __half g_Q[BB * HH * LL * HDIM];     // head-major, pre-scaled by 0.125
__device__ __half g_K[BB * HH * LL * HDIM];
__device__ __half g_V[BB * HH * LL * HDIM];
__device__ __half g_attn[BB * LL * PP];         // [b,l,h*64+d]

typedef wmma::fragment<wmma::matrix_a, 16, 16, 16, __half, wmma::row_major> HFragA;
typedef wmma::fragment<wmma::matrix_b, 16, 16, 16, __half, wmma::row_major> HFragB;
typedef wmma::fragment<wmma::accumulator, 16, 16, 16, float> FragC;

typedef wmma::fragment<wmma::matrix_a, 8, 32, 16, __half, wmma::row_major> PFragA;
typedef wmma::fragment<wmma::matrix_b, 8, 32, 16, __half, wmma::row_major> PFragB;
typedef wmma::fragment<wmma::matrix_b, 8, 32, 16, __half, wmma::col_major> PFragBc;
typedef wmma::fragment<wmma::accumulator, 8, 32, 16, float> PFragC;

__device__ __forceinline__ uint2 h4(float4 v) {
    __half2 a = __floats2half2_rn(v.x, v.y);
    __half2 b = __floats2half2_rn(v.z, v.w);
    uint2 r;
    r.x = *(unsigned*)&a;
    r.y = *(unsigned*)&b;
    return r;
}

// ---------------- one-time fp32 -> fp16 conversion of hs + weights ----------------
__global__ __launch_bounds__(256) void cvt_all(const float* __restrict__ hs,
                                               const float* __restrict__ Wq,
                                               const float* __restrict__ Wk,
                                               const float* __restrict__ Wv,
                                               const float* __restrict__ Wo) {
    int i = blockIdx.x * 256 + threadIdx.x;    // float4 index
    const float* src;
    __half* dst;
    int off;
    if (i < 786432)       { src = hs; dst = g_H + AH_OFF; off = i; }
    else if (i < 1048576) { src = Wq; dst = g_H + WQ_OFF; off = i - 786432; }
    else if (i < 1310720) { src = Wk; dst = g_H + WK_OFF; off = i - 1048576; }
    else if (i < 1572864) { src = Wv; dst = g_H + WV_OFF; off = i - 1310720; }
    else                  { src = Wo; dst = g_H + WO_OFF; off = i - 1572864; }
    float4 v = ((const float4*)src)[off];
    ((uint2*)dst)[off] = h4(v);
}

// ---------------- 128x128 GEMM body, half operands, 32x64 warp tiles -------------
// mode 0/1/2: Q/K/V head-major half out (Q scaled 0.125). mode 3: fp32 out to Cout.
__device__ __forceinline__ void gemm128_body(const __half* __restrict__ A,
                                             const __half* __restrict__ W,
                                             const float* __restrict__ bias,
                                             __half* __restrict__ Ch,
                                             float* __restrict__ Cf, int mode) {
    extern __shared__ char dsm[];
    float* BiasT = (float*)dsm;                       // [16][132]
    __half* AsB = (__half*)(dsm + G_TILE_OFF);        // [2][128][40]
    __half* BsB = AsB + 2 * 128 * 40;                 // [2][32][136]
    float* Cst = (float*)(dsm + G_TILE_OFF);          // [128][132] (epilogue, modes 0-2)

    const int m0 = blockIdx.y * 128;
    const int n0 = blockIdx.x * 128;
    const int t = threadIdx.x;
    const int warp = t >> 5;
    const int wm = (warp & 3) * 32;
    const int wn = (warp >> 2) * 64;

#pragma unroll
    for (int r = 0; r < 2; r++) {
        int idx = t + r * 256;
        int row = idx >> 5;
        int col = (idx & 31) << 2;
        *(float4*)(BiasT + row * 132 + col) = *(const float4*)(bias + n0 + col);
    }

    FragC c[2][4];
#pragma unroll
    for (int i = 0; i < 2; i++)
#pragma unroll
        for (int j = 0; j < 4; j++) wmma::fill_fragment(c[i][j], 0.f);

    uint4 apre[2], bpre[2];
#pragma unroll
    for (int r = 0; r < 2; r++) {
        int idx = t + r * 256;
        apre[r] = *(const uint4*)(A + (size_t)(m0 + (idx >> 2)) * DD + ((idx & 3) << 3));
        bpre[r] = *(const uint4*)(W + (size_t)(idx >> 4) * PP + n0 + ((idx & 15) << 3));
    }
#pragma unroll
    for (int r = 0; r < 2; r++) {
        int idx = t + r * 256;
        *(uint4*)(AsB + (idx >> 2) * 40 + ((idx & 3) << 3)) = apre[r];
        *(uint4*)(BsB + (idx >> 4) * 136 + ((idx & 15) << 3)) = bpre[r];
    }
    __syncthreads();

    for (int k0 = 0; k0 < DD; k0 += 32) {
        const int cur = (k0 >> 5) & 1, nxt = cur ^ 1;
        const bool more = (k0 + 32 < DD);
        if (more) {
#pragma unroll
            for (int r = 0; r < 2; r++) {
                int idx = t + r * 256;
                apre[r] = *(const uint4*)(A + (size_t)(m0 + (idx >> 2)) * DD + k0 + 32 + ((idx & 3) << 3));
                bpre[r] = *(const uint4*)(W + (size_t)(k0 + 32 + (idx >> 4)) * PP + n0 + ((idx & 15) << 3));
            }
        }
        const __half* Asc = AsB + cur * 128 * 40;
        const __half* Bsc = BsB + cur * 32 * 136;
#pragma unroll
        for (int kk = 0; kk < 32; kk += 16) {
            HFragA a[2];
#pragma unroll
            for (int i = 0; i < 2; i++)
                wmma::load_matrix_sync(a[i], Asc + (wm + i * 16) * 40 + kk, 40);
#pragma unroll
            for (int j = 0; j < 4; j++) {
                HFragB b;
                wmma::load_matrix_sync(b, Bsc + kk * 136 + wn + j * 16, 136);
#pragma unroll
                for (int i = 0; i < 2; i++) wmma::mma_sync(c[i][j], a[i], b, c[i][j]);
            }
        }
        if (more) {
#pragma unroll
            for (int r = 0; r < 2; r++) {
                int idx = t + r * 256;
                *(uint4*)(AsB + nxt * 128 * 40 + (idx >> 2) * 40 + ((idx & 3) << 3)) = apre[r];
                *(uint4*)(BsB + nxt * 32 * 136 + (idx >> 4) * 136 + ((idx & 15) << 3)) = bpre[r];
            }
        }
        __syncthreads();
    }

    const float scale = (mode == 0) ? 0.125f : 1.0f;
#pragma unroll
    for (int j = 0; j < 4; j++) {
        FragC bf;
        wmma::load_matrix_sync(bf, BiasT + wn + j * 16, 132, wmma::mem_row_major);
#pragma unroll
        for (int i = 0; i < 2; i++)
#pragma unroll
            for (int e = 0; e < bf.num_elements; e++)
                c[i][j].x[e] = (c[i][j].x[e] + bf.x[e]) * scale;
    }

    if (mode <= 2) {
        // stage fp32, convert -> half head-major
#pragma unroll
        for (int i = 0; i < 2; i++)
#pragma unroll
            for (int j = 0; j < 4; j++)
                wmma::store_matrix_sync(Cst + (size_t)(wm + i * 16) * 132 + wn + j * 16,
                                        c[i][j], 132, wmma::mem_row_major);
        __syncthreads();

        const int b = m0 / LL;
        const int l0 = m0 - b * LL;
        const int hbase = n0 >> 6;
#pragma unroll
        for (int r = 0; r < 16; r++) {
            int idx = t + r * 256;
            int row = idx >> 5;
            int col = (idx & 31) << 2;
            uint2 hv = h4(*(float4*)(Cst + (size_t)row * 132 + col));
            int h = hbase + (col >> 6);
            int d = col & 63;
            __half* out = Ch + (((size_t)(b * HH + h)) * LL + l0 + row) * HDIM + d;
            *(uint2*)out = hv;
        }
    } else {
#pragma unroll
        for (int i = 0; i < 2; i++)
#pragma unroll
            for (int j = 0; j < 4; j++)
                wmma::store_matrix_sync(Cf + (size_t)(m0 + wm + i * 16) * PP + n0 + wn + j * 16,
                                        c[i][j], PP, wmma::mem_row_major);
    }
}

__global__ __launch_bounds__(256, 2) void qkv_wmma(const float* __restrict__ bq,
                                                   const float* __restrict__ bk,
                                                   const float* __restrict__ bv) {
    const int zz = blockIdx.z;
    const __half* W = g_H + ((zz == 0) ? WQ_OFF : (zz == 1) ? WK_OFF : WV_OFF);
    const float* bias = (zz == 0) ? bq : (zz == 1) ? bk : bv;
    __half* C = (zz == 0) ? g_Q : (zz == 1) ? g_K : g_V;
    gemm128_body(g_H + AH_OFF, W, bias, C, nullptr, zz);
}

__global__ __launch_bounds__(256, 2) void oproj_wmma(const float* __restrict__ bias,
                                                     float* __restrict__ Cout) {
    gemm128_body(g_attn, g_H + WO_OFF, bias, nullptr, Cout, 3);
}

// ---------------- fused_all: S = Q@K^T (SMEM) + softmax + diffusion + p@V ------------
__global__ __launch_bounds__(512, 1) void fused_all(const int* __restrict__ mask,
                                                    const float* __restrict__ kw) {
    extern __shared__ char smraw[];
    float* Sf = (float*)smraw;                         // [16][PSTRF]: [8 pad][1536 data]
    __half* Ps = (__half*)smraw;                       // half p (aliases Sf)
    float* Vred = (float*)(smraw + VRED_OFF);          // [4][16][68]
    float* kvs = (float*)(smraw + KVS_OFF);            // [1536]
    float* w5s = (float*)(smraw + W5_OFF);             // [5]
    __half* Qs = (__half*)(smraw + Q_OFF);             // [16][72]
    __half* KVb = (__half*)(smraw + KV_OFF);           // [2][256][72]

    const int t = threadIdx.x;
    const int warp = t >> 5, lane = t & 31;
    const int row0 = blockIdx.x * FROWS;
    const int z = row0 / LL;
    const int q0 = row0 - z * LL;
    const int b = z >> 4;
    const int h = z & 15;
    const int* mrow = mask + b * LL;
    const __half* Qg = g_Q + ((size_t)z * LL + q0) * HDIM;
    const __half* Kg = g_K + (size_t)z * LL * HDIM;
    const __half* Vg = g_V + (size_t)z * LL * HDIM;

    if (t == 0) {
        float mxw = kw[0];
#pragma unroll
        for (int j = 1; j < 5; j++) mxw = fmaxf(mxw, kw[j]);
        float e[5], s = 0.f;
#pragma unroll
        for (int j = 0; j < 5; j++) { e[j] = __expf(kw[j] - mxw); s += e[j]; }
#pragma unroll
        for (int j = 0; j < 5; j++) w5s[j] = e[j] / s;
    }
    if (t < LL / 4) {
        int4 m4 = *(const int4*)(mrow + t * 4);
        *(float4*)(kvs + t * 4) = make_float4(m4.x > 0 ? 1.f : 0.f, m4.y > 0 ? 1.f : 0.f,
                                              m4.z > 0 ? 1.f : 0.f, m4.w > 0 ? 1.f : 0.f);
    }
    if (t < 256) {
        int row = t >> 4, col = (t & 15) << 2;
        *(uint2*)(Qs + row * 72 + col) = *(const uint2*)(Qg + (size_t)row * HDIM + col);
    }

    // ---- S-compute: 6 slabs of 256 key-rows, double-buffered K ----
    uint2 kpre[8];
#pragma unroll
    for (int r = 0; r < 8; r++) {
        int u = t + r * 512;
        int row = u >> 4, col = (u & 15) << 2;
        kpre[r] = *(const uint2*)(Kg + (size_t)row * HDIM + col);
    }
#pragma unroll
    for (int r = 0; r < 8; r++) {
        int u = t + r * 512;
        int row = u >> 4, col = (u & 15) << 2;
        *(uint2*)(KVb + row * 72 + col) = kpre[r];
    }
    __syncthreads();

    const int si = warp >> 3;
    const int sj = warp & 7;

    for (int s = 0; s < 6; s++) {
        const int cur = s & 1, nxt = cur ^ 1;
        const bool more = (s + 1 < 6);
        if (more) {
#pragma unroll
            for (int r = 0; r < 8; r++) {
                int u = t + r * 512;
                int row = u >> 4, col = (u & 15) << 2;
                kpre[r] = *(const uint2*)(Kg + (size_t)((s + 1) * 256 + row) * HDIM + col);
            }
        }
        const __half* Kc = KVb + cur * 256 * 72;
        PFragC sacc;
        wmma::fill_fragment(sacc, 0.f);
#pragma unroll
        for (int kk = 0; kk < 64; kk += 16) {
            PFragA a;
            PFragBc bb;
            wmma::load_matrix_sync(a, Qs + (si * 8) * 72 + kk, 72);
            wmma::load_matrix_sync(bb, Kc + (sj * 32) * 72 + kk, 72);
            wmma::mma_sync(sacc, a, bb, sacc);
        }
        wmma::store_matrix_sync(Sf + (size_t)(si * 8) * PSTRF + 8 + s * 256 + sj * 32, sacc,
                                PSTRF, wmma::mem_row_major);
        if (more) {
#pragma unroll
            for (int r = 0; r < 8; r++) {
                int u = t + r * 512;
                int row = u >> 4, col = (u & 15) << 2;
                *(uint2*)(KVb + nxt * 256 * 72 + row * 72 + col) = kpre[r];
            }
        }
        __syncthreads();
    }

    const float w0 = w5s[0], w1 = w5s[1], w2 = w5s[2], w3 = w5s[3], w4 = w5s[4];
    const float4* kvs4 = (const float4*)kvs;

    // ---- phase 1: warp-per-row softmax + diffusion; halo via SMEM mirror ----
    {
        float* rowF = Sf + (size_t)warp * PSTRF;
        float4 p4[12];
        float mx = -3.4e38f;
#pragma unroll
        for (int k = 0; k < 12; k++) {
            int m = lane + 32 * k;
            float4 v = *(const float4*)(rowF + 8 + 4 * m);
            float4 kv = kvs4[m];
            v.x += (kv.x > 0.f) ? 0.f : -1e9f;
            v.y += (kv.y > 0.f) ? 0.f : -1e9f;
            v.z += (kv.z > 0.f) ? 0.f : -1e9f;
            v.w += (kv.w > 0.f) ? 0.f : -1e9f;
            p4[k] = v;
            mx = fmaxf(mx, fmaxf(fmaxf(v.x, v.y), fmaxf(v.z, v.w)));
        }
        if (lane < 2) *(float4*)(rowF + lane * 4) = make_float4(0.f, 0.f, 0.f, 0.f);
#pragma unroll
        for (int o = 16; o; o >>= 1) mx = fmaxf(mx, __shfl_xor_sync(0xffffffffu, mx, o));

        float s = 0.f;
#pragma unroll
        for (int k = 0; k < 12; k++) {
            float4 v = p4[k];
            v.x = __expf(v.x - mx); v.y = __expf(v.y - mx);
            v.z = __expf(v.z - mx); v.w = __expf(v.w - mx);
            p4[k] = v;
            s += v.x + v.y + v.z + v.w;
        }
#pragma unroll
        for (int o = 16; o; o >>= 1) s += __shfl_xor_sync(0xffffffffu, s, o);
        float inv = 1.f / s;
#pragma unroll
        for (int k = 0; k < 12; k++) {
            p4[k].x *= inv; p4[k].y *= inv; p4[k].z *= inv; p4[k].w *= inv;
            *(float4*)(rowF + 8 + 4 * (lane + 32 * k)) = p4[k];
        }
        __syncwarp();

#pragma unroll 1
        for (int step = 0; step < 3; step++) {
            float4 c4[12];
            float sa = 0.f;
#pragma unroll
            for (int k = 0; k < 12; k++) {
                int m = lane + 32 * k;
                float4 o4 = p4[k];
                float4 h4v = *(const float4*)(rowF + 4 + 4 * m);
                float4 kv = kvs4[m];
                float4 cc;
                cc.x = (w0 * h4v.x + w1 * h4v.y + w2 * h4v.z + w3 * h4v.w + w4 * o4.x) * kv.x;
                cc.y = (w0 * h4v.y + w1 * h4v.z + w2 * h4v.w + w3 * o4.x + w4 * o4.y) * kv.y;
                cc.z = (w0 * h4v.z + w1 * h4v.w + w2 * o4.x + w3 * o4.y + w4 * o4.z) * kv.z;
                cc.w = (w0 * h4v.w + w1 * o4.x + w2 * o4.y + w3 * o4.z + w4 * o4.w) * kv.w;
                c4[k] = cc;
                sa += cc.x + cc.y + cc.z + cc.w;
            }
#pragma unroll
            for (int o = 16; o; o >>= 1) sa += __shfl_xor_sync(0xffffffffu, sa, o);
            const float rmul = 0.02f / (sa + 1e-9f);
            __syncwarp();
#pragma unroll
            for (int k = 0; k < 12; k++) {
                p4[k].x = 0.98f * p4[k].x + rmul * c4[k].x;
                p4[k].y = 0.98f * p4[k].y + rmul * c4[k].y;
                p4[k].z = 0.98f * p4[k].z + rmul * c4[k].z;
                p4[k].w = 0.98f * p4[k].w + rmul * c4[k].w;
                *(float4*)(rowF + 8 + 4 * (lane + 32 * k)) = p4[k];
            }
            __syncwarp();
        }

        __syncthreads();
        __half* pr = Ps + (size_t)warp * PSTRF;
#pragma unroll
        for (int k = 0; k < 12; k++)
            *(uint2*)(pr + (size_t)(lane + 32 * k) * 4) = h4(p4[k]);
    }
    __syncthreads();

    // ---- phase 2: out[16x64] = p[16x1536] @ V[1536x64], m8n32k16, double-buffered ----
    const int pi = warp >> 3;
    const int pg = (warp >> 1) & 3;
    const int pj = warp & 1;

    PFragC acc;
    wmma::fill_fragment(acc, 0.f);

    uint2 vpre[4];
#pragma unroll
    for (int r = 0; r < 4; r++) {
        int u = t + r * 512;
        int row = u >> 4, col = (u & 15) << 2;
        vpre[r] = *(const uint2*)(Vg + (size_t)row * HDIM + col);
    }
#pragma unroll
    for (int r = 0; r < 4; r++) {
        int u = t + r * 512;
        int row = u >> 4, col = (u & 15) << 2;
        *(uint2*)(KVb + row * 72 + col) = vpre[r];
    }
    __syncthreads();

    for (int c = 0; c < 12; c++) {
        const int cur = c & 1, nxt = cur ^ 1;
        const bool more = (c + 1 < 12);
        if (more) {
#pragma unroll
            for (int r = 0; r < 4; r++) {
                int u = t + r * 512;
                int row = u >> 4, col = (u & 15) << 2;
                vpre[r] = *(const uint2*)(Vg + (size_t)((c + 1) * 128 + row) * HDIM + col);
            }
        }
        const __half* Vc = KVb + cur * 128 * 72;
#pragma unroll
        for (int kk = 0; kk < 32; kk += 16) {
            PFragA a;
            PFragB bb;
            wmma::load_matrix_sync(a, Ps + (size_t)(pi * 8) * PSTRF + c * 128 + pg * 32 + kk, PSTRF);
            wmma::load_matrix_sync(bb, Vc + (pg * 32 + kk) * 72 + pj * 32, 72);
            wmma::mma_sync(acc, a, bb, acc);
        }
        if (more) {
#pragma unroll
            for (int r = 0; r < 4; r++) {
                int u = t + r * 512;
                int row = u >> 4, col = (u & 15) << 2;
                *(uint2*)(KVb + nxt * 128 * 72 + row * 72 + col) = vpre[r];
            }
        }
        __syncthreads();
    }

    wmma::store_matrix_sync(Vred + (size_t)(pg * 16 + pi * 8) * 68 + pj * 32, acc,
                            68, wmma::mem_row_major);
    __syncthreads();

    if (t < 256) {
        const int row = t >> 4;
        const int col = (t & 15) << 2;
        float4 s0 = *(float4*)(Vred + (size_t)row * 68 + col);
#pragma unroll
        for (int gg = 1; gg < 4; gg++) {
            float4 a0 = *(float4*)(Vred + (size_t)(gg * 16 + row) * 68 + col);
            s0.x += a0.x; s0.y += a0.y; s0.z += a0.z; s0.w += a0.w;
        }
        __half* out = g_attn + ((size_t)(b * LL + q0 + row)) * PP + h * 64 + col;
        *(uint2*)out = h4(s0);
    }
}

// ---------------- launch ----------------
extern "C" void kernel_launch(void* const* d_in, const int* in_sizes, int n_in,
                              void* d_out, int out_size) {
    const float* hs = (const float*)d_in[0];
    const int* mask = (const int*)d_in[1];
    const float* Wq = (const float*)d_in[2];
    const float* bq = (const float*)d_in[3];
    const float* Wk = (const float*)d_in[4];
    const float* bk = (const float*)d_in[5];
    const float* Wv = (const float*)d_in[6];
    const float* bv = (const float*)d_in[7];
    const float* Wo = (const float*)d_in[8];
    const float* bo = (const float*)d_in[9];
    const float* kw = (const float*)d_in[10];

    cudaFuncSetAttribute(qkv_wmma, cudaFuncAttributeMaxDynamicSharedMemorySize, G_SMEM_BYTES);
    cudaFuncSetAttribute(oproj_wmma, cudaFuncAttributeMaxDynamicSharedMemorySize, G_SMEM_BYTES);
    cudaFuncSetAttribute(fused_all, cudaFuncAttributeMaxDynamicSharedMemorySize, FUSED_SMEM_BYTES);

    cvt_all<<<7168, 256>>>(hs, Wq, Wk, Wv, Wo);

    qkv_wmma<<<dim3(PP / 128, (BB * LL) / 128, 3), 256, G_SMEM_BYTES>>>(bq, bk, bv);

    fused_all<<<(BB * HH * LL) / FROWS, 512, FUSED_SMEM_BYTES>>>(mask, kw);

    oproj_wmma<<<dim3(PP / 128, (BB * LL) / 128), 256, G_SMEM_BYTES>>>(bo, (float*)d_out);
}

// round 14
// speedup vs baseline: 3.4289x; 1.0640x over previous
#include <cuda_runtime.h>
#include <cuda_fp16.h>
#include <mma.h>
using namespace nvcuda;

#define BB 2
#define LL 1536
#define DD 1024
#define HH 16
#define PP 1024
#define HDIM 64

// gemm128 dynamic smem (bytes): BiasT(8448) + union(tiles 37888, Cst 67584)
#define G_TILE_OFF 8448
#define G_SMEM_BYTES (8448 + 67584)

// ---------------- fused_all smem layout (bytes) ----------------
#define FROWS 16
#define PSTRF 1544
#define SF_OFF   0
#define VRED_OFF 65536
#define KVS_OFF  98816
#define W5_OFF   104960
#define Q_OFF    104992
#define KV_OFF   107328
#define FUSED_SMEM_BYTES (KV_OFF + 73728 + 32)

// half arena: hs | Wq | Wk | Wv | Wo
#define AH_OFF  0
#define WQ_OFF  3145728
#define WK_OFF  4194304
#define WV_OFF  5242880
#define WO_OFF  6291456
__device__ __half g_H[7340032];

// ---------------- device scratch ----------------
__device__ __half g_Q[BB * HH * LL * HDIM];     // head-major, pre-scaled by 0.125
__device__ __half g_K[BB * HH * LL * HDIM];
__device__ __half g_V[BB * HH * LL * HDIM];
__device__ __half g_attn[BB * LL * PP];         // [b,l,h*64+d]

typedef wmma::fragment<wmma::matrix_a, 16, 16, 16, __half, wmma::row_major> HFragA;
typedef wmma::fragment<wmma::matrix_b, 16, 16, 16, __half, wmma::row_major> HFragB;
typedef wmma::fragment<wmma::accumulator, 16, 16, 16, float> FragC;

typedef wmma::fragment<wmma::matrix_a, 8, 32, 16, __half, wmma::row_major> PFragA;
typedef wmma::fragment<wmma::matrix_b, 8, 32, 16, __half, wmma::row_major> PFragB;
typedef wmma::fragment<wmma::matrix_b, 8, 32, 16, __half, wmma::col_major> PFragBc;
typedef wmma::fragment<wmma::accumulator, 8, 32, 16, float> PFragC;

__device__ __forceinline__ uint2 h4(float4 v) {
    __half2 a = __floats2half2_rn(v.x, v.y);
    __half2 b = __floats2half2_rn(v.z, v.w);
    uint2 r;
    r.x = *(unsigned*)&a;
    r.y = *(unsigned*)&b;
    return r;
}

#define CP_ASYNC16(dst_u32, src_ptr) \
    asm volatile("cp.async.cg.shared.global [%0], [%1], 16;" :: "r"(dst_u32), "l"(src_ptr))
#define CP_COMMIT() asm volatile("cp.async.commit_group;" ::: "memory")
#define CP_WAIT(n)  asm volatile("cp.async.wait_group %0;" :: "n"(n) : "memory")

// ---------------- one-time fp32 -> fp16 conversion of hs + weights ----------------
__global__ __launch_bounds__(256) void cvt_all(const float* __restrict__ hs,
                                               const float* __restrict__ Wq,
                                               const float* __restrict__ Wk,
                                               const float* __restrict__ Wv,
                                               const float* __restrict__ Wo) {
    int i = blockIdx.x * 256 + threadIdx.x;
    const float* src;
    __half* dst;
    int off;
    if (i < 786432)       { src = hs; dst = g_H + AH_OFF; off = i; }
    else if (i < 1048576) { src = Wq; dst = g_H + WQ_OFF; off = i - 786432; }
    else if (i < 1310720) { src = Wk; dst = g_H + WK_OFF; off = i - 1048576; }
    else if (i < 1572864) { src = Wv; dst = g_H + WV_OFF; off = i - 1310720; }
    else                  { src = Wo; dst = g_H + WO_OFF; off = i - 1572864; }
    float4 v = ((const float4*)src)[off];
    ((uint2*)dst)[off] = h4(v);
}

// ---------------- 128x128 GEMM body, half operands, 32x64 warp tiles -------------
__device__ __forceinline__ void gemm128_body(const __half* __restrict__ A,
                                             const __half* __restrict__ W,
                                             const float* __restrict__ bias,
                                             __half* __restrict__ Ch,
                                             float* __restrict__ Cf, int mode) {
    extern __shared__ char dsm[];
    float* BiasT = (float*)dsm;
    __half* AsB = (__half*)(dsm + G_TILE_OFF);        // [2][128][40]
    __half* BsB = AsB + 2 * 128 * 40;                 // [2][32][136]
    float* Cst = (float*)(dsm + G_TILE_OFF);          // [128][132]

    const int m0 = blockIdx.y * 128;
    const int n0 = blockIdx.x * 128;
    const int t = threadIdx.x;
    const int warp = t >> 5;
    const int wm = (warp & 3) * 32;
    const int wn = (warp >> 2) * 64;

#pragma unroll
    for (int r = 0; r < 2; r++) {
        int idx = t + r * 256;
        int row = idx >> 5;
        int col = (idx & 31) << 2;
        *(float4*)(BiasT + row * 132 + col) = *(const float4*)(bias + n0 + col);
    }

    FragC c[2][4];
#pragma unroll
    for (int i = 0; i < 2; i++)
#pragma unroll
        for (int j = 0; j < 4; j++) wmma::fill_fragment(c[i][j], 0.f);

    uint4 apre[2], bpre[2];
#pragma unroll
    for (int r = 0; r < 2; r++) {
        int idx = t + r * 256;
        apre[r] = *(const uint4*)(A + (size_t)(m0 + (idx >> 2)) * DD + ((idx & 3) << 3));
        bpre[r] = *(const uint4*)(W + (size_t)(idx >> 4) * PP + n0 + ((idx & 15) << 3));
    }
#pragma unroll
    for (int r = 0; r < 2; r++) {
        int idx = t + r * 256;
        *(uint4*)(AsB + (idx >> 2) * 40 + ((idx & 3) << 3)) = apre[r];
        *(uint4*)(BsB + (idx >> 4) * 136 + ((idx & 15) << 3)) = bpre[r];
    }
    __syncthreads();

    for (int k0 = 0; k0 < DD; k0 += 32) {
        const int cur = (k0 >> 5) & 1, nxt = cur ^ 1;
        const bool more = (k0 + 32 < DD);
        if (more) {
#pragma unroll
            for (int r = 0; r < 2; r++) {
                int idx = t + r * 256;
                apre[r] = *(const uint4*)(A + (size_t)(m0 + (idx >> 2)) * DD + k0 + 32 + ((idx & 3) << 3));
                bpre[r] = *(const uint4*)(W + (size_t)(k0 + 32 + (idx >> 4)) * PP + n0 + ((idx & 15) << 3));
            }
        }
        const __half* Asc = AsB + cur * 128 * 40;
        const __half* Bsc = BsB + cur * 32 * 136;
#pragma unroll
        for (int kk = 0; kk < 32; kk += 16) {
            HFragA a[2];
#pragma unroll
            for (int i = 0; i < 2; i++)
                wmma::load_matrix_sync(a[i], Asc + (wm + i * 16) * 40 + kk, 40);
#pragma unroll
            for (int j = 0; j < 4; j++) {
                HFragB b;
                wmma::load_matrix_sync(b, Bsc + kk * 136 + wn + j * 16, 136);
#pragma unroll
                for (int i = 0; i < 2; i++) wmma::mma_sync(c[i][j], a[i], b, c[i][j]);
            }
        }
        if (more) {
#pragma unroll
            for (int r = 0; r < 2; r++) {
                int idx = t + r * 256;
                *(uint4*)(AsB + nxt * 128 * 40 + (idx >> 2) * 40 + ((idx & 3) << 3)) = apre[r];
                *(uint4*)(BsB + nxt * 32 * 136 + (idx >> 4) * 136 + ((idx & 15) << 3)) = bpre[r];
            }
        }
        __syncthreads();
    }

    const float scale = (mode == 0) ? 0.125f : 1.0f;
#pragma unroll
    for (int j = 0; j < 4; j++) {
        FragC bf;
        wmma::load_matrix_sync(bf, BiasT + wn + j * 16, 132, wmma::mem_row_major);
#pragma unroll
        for (int i = 0; i < 2; i++)
#pragma unroll
            for (int e = 0; e < bf.num_elements; e++)
                c[i][j].x[e] = (c[i][j].x[e] + bf.x[e]) * scale;
    }

    if (mode <= 2) {
#pragma unroll
        for (int i = 0; i < 2; i++)
#pragma unroll
            for (int j = 0; j < 4; j++)
                wmma::store_matrix_sync(Cst + (size_t)(wm + i * 16) * 132 + wn + j * 16,
                                        c[i][j], 132, wmma::mem_row_major);
        __syncthreads();

        const int b = m0 / LL;
        const int l0 = m0 - b * LL;
        const int hbase = n0 >> 6;
#pragma unroll
        for (int r = 0; r < 16; r++) {
            int idx = t + r * 256;
            int row = idx >> 5;
            int col = (idx & 31) << 2;
            uint2 hv = h4(*(float4*)(Cst + (size_t)row * 132 + col));
            int h = hbase + (col >> 6);
            int d = col & 63;
            __half* out = Ch + (((size_t)(b * HH + h)) * LL + l0 + row) * HDIM + d;
            *(uint2*)out = hv;
        }
    } else {
#pragma unroll
        for (int i = 0; i < 2; i++)
#pragma unroll
            for (int j = 0; j < 4; j++)
                wmma::store_matrix_sync(Cf + (size_t)(m0 + wm + i * 16) * PP + n0 + wn + j * 16,
                                        c[i][j], PP, wmma::mem_row_major);
    }
}

__global__ __launch_bounds__(256, 2) void qkv_wmma(const float* __restrict__ bq,
                                                   const float* __restrict__ bk,
                                                   const float* __restrict__ bv) {
    const int zz = blockIdx.z;
    const __half* W = g_H + ((zz == 0) ? WQ_OFF : (zz == 1) ? WK_OFF : WV_OFF);
    const float* bias = (zz == 0) ? bq : (zz == 1) ? bk : bv;
    __half* C = (zz == 0) ? g_Q : (zz == 1) ? g_K : g_V;
    gemm128_body(g_H + AH_OFF, W, bias, C, nullptr, zz);
}

__global__ __launch_bounds__(256, 2) void oproj_wmma(const float* __restrict__ bias,
                                                     float* __restrict__ Cout) {
    gemm128_body(g_attn, g_H + WO_OFF, bias, nullptr, Cout, 3);
}

// ---------------- fused_all: S = Q@K^T (SMEM) + softmax + diffusion + p@V ------------
// cp.async staging: K slabs double-buffered async; V prefetch hidden under phase 1.
__global__ __launch_bounds__(512, 1) void fused_all(const int* __restrict__ mask,
                                                    const float* __restrict__ kw) {
    extern __shared__ char smraw[];
    float* Sf = (float*)smraw;                         // [16][PSTRF]: [8 pad][1536 data]
    __half* Ps = (__half*)smraw;                       // half p (aliases Sf)
    float* Vred = (float*)(smraw + VRED_OFF);          // [4][16][68]
    float* kvs = (float*)(smraw + KVS_OFF);            // [1536]
    float* w5s = (float*)(smraw + W5_OFF);             // [5]
    __half* Qs = (__half*)(smraw + Q_OFF);             // [16][72]
    __half* KVb = (__half*)(smraw + KV_OFF);           // [2][256][72]
    const unsigned KVb_u32 = (unsigned)__cvta_generic_to_shared(KVb);

    const int t = threadIdx.x;
    const int warp = t >> 5, lane = t & 31;
    const int row0 = blockIdx.x * FROWS;
    const int z = row0 / LL;
    const int q0 = row0 - z * LL;
    const int b = z >> 4;
    const int h = z & 15;
    const int* mrow = mask + b * LL;
    const __half* Qg = g_Q + ((size_t)z * LL + q0) * HDIM;
    const __half* Kg = g_K + (size_t)z * LL * HDIM;
    const __half* Vg = g_V + (size_t)z * LL * HDIM;

    // async K slab issue: 256 rows x 8 chunks of 16B; 512 thr -> 4 chunks each
    auto issue_k = [&](int slab, int buf) {
#pragma unroll
        for (int r = 0; r < 4; r++) {
            int u = t + r * 512;
            int row = u >> 3, cc = (u & 7) << 3;
            CP_ASYNC16(KVb_u32 + (buf * 256 * 72 + row * 72 + cc) * 2,
                       Kg + (size_t)(slab * 256 + row) * HDIM + cc);
        }
    };
    // async V chunk issue: 128 rows x 8 chunks; 2 chunks each
    auto issue_v = [&](int chunk, int buf) {
#pragma unroll
        for (int r = 0; r < 2; r++) {
            int u = t + r * 512;
            int row = u >> 3, cc = (u & 7) << 3;
            CP_ASYNC16(KVb_u32 + (buf * 128 * 72 + row * 72 + cc) * 2,
                       Vg + (size_t)(chunk * 128 + row) * HDIM + cc);
        }
    };

    issue_k(0, 0); CP_COMMIT();

    if (t == 0) {
        float mxw = kw[0];
#pragma unroll
        for (int j = 1; j < 5; j++) mxw = fmaxf(mxw, kw[j]);
        float e[5], s = 0.f;
#pragma unroll
        for (int j = 0; j < 5; j++) { e[j] = __expf(kw[j] - mxw); s += e[j]; }
#pragma unroll
        for (int j = 0; j < 5; j++) w5s[j] = e[j] / s;
    }
    if (t < LL / 4) {
        int4 m4 = *(const int4*)(mrow + t * 4);
        *(float4*)(kvs + t * 4) = make_float4(m4.x > 0 ? 1.f : 0.f, m4.y > 0 ? 1.f : 0.f,
                                              m4.z > 0 ? 1.f : 0.f, m4.w > 0 ? 1.f : 0.f);
    }
    if (t < 256) {
        int row = t >> 4, col = (t & 15) << 2;
        *(uint2*)(Qs + row * 72 + col) = *(const uint2*)(Qg + (size_t)row * HDIM + col);
    }
    __syncthreads();   // Qs visible for fragment hoist

    const int si = warp >> 3;
    const int sj = warp & 7;

    // hoist Q fragments (reused across all 6 slabs)
    PFragA aq[4];
#pragma unroll
    for (int kk = 0; kk < 4; kk++)
        wmma::load_matrix_sync(aq[kk], Qs + (si * 8) * 72 + kk * 16, 72);

    // ---- S-compute: 6 slabs of 256 key-rows, cp.async double-buffered ----
    for (int s = 0; s < 6; s++) {
        const int cur = s & 1, nxt = cur ^ 1;
        const bool more = (s + 1 < 6);
        if (more) { issue_k(s + 1, nxt); CP_COMMIT(); }
        if (more) CP_WAIT(1); else CP_WAIT(0);
        __syncthreads();   // slab s resident

        const __half* Kc = KVb + cur * 256 * 72;
        PFragC sacc;
        wmma::fill_fragment(sacc, 0.f);
#pragma unroll
        for (int kk = 0; kk < 4; kk++) {
            PFragBc bb;
            wmma::load_matrix_sync(bb, Kc + (sj * 32) * 72 + kk * 16, 72);
            wmma::mma_sync(sacc, aq[kk], bb, sacc);
        }
        wmma::store_matrix_sync(Sf + (size_t)(si * 8) * PSTRF + 8 + s * 256 + sj * 32, sacc,
                                PSTRF, wmma::mem_row_major);
        __syncthreads();   // all reads of cur done before it is refilled
    }

    // prefetch both V chunks under phase 1 (KVb free now)
    issue_v(0, 0); CP_COMMIT();
    issue_v(1, 1); CP_COMMIT();

    const float w0 = w5s[0], w1 = w5s[1], w2 = w5s[2], w3 = w5s[3], w4 = w5s[4];
    const float4* kvs4 = (const float4*)kvs;

    // ---- phase 1: warp-per-row softmax + diffusion; halo via SMEM mirror ----
    {
        float* rowF = Sf + (size_t)warp * PSTRF;
        float4 p4[12];
        float mx = -3.4e38f;
#pragma unroll
        for (int k = 0; k < 12; k++) {
            int m = lane + 32 * k;
            float4 v = *(const float4*)(rowF + 8 + 4 * m);
            float4 kv = kvs4[m];
            v.x += (kv.x > 0.f) ? 0.f : -1e9f;
            v.y += (kv.y > 0.f) ? 0.f : -1e9f;
            v.z += (kv.z > 0.f) ? 0.f : -1e9f;
            v.w += (kv.w > 0.f) ? 0.f : -1e9f;
            p4[k] = v;
            mx = fmaxf(mx, fmaxf(fmaxf(v.x, v.y), fmaxf(v.z, v.w)));
        }
        if (lane < 2) *(float4*)(rowF + lane * 4) = make_float4(0.f, 0.f, 0.f, 0.f);
#pragma unroll
        for (int o = 16; o; o >>= 1) mx = fmaxf(mx, __shfl_xor_sync(0xffffffffu, mx, o));

        float s = 0.f;
#pragma unroll
        for (int k = 0; k < 12; k++) {
            float4 v = p4[k];
            v.x = __expf(v.x - mx); v.y = __expf(v.y - mx);
            v.z = __expf(v.z - mx); v.w = __expf(v.w - mx);
            p4[k] = v;
            s += v.x + v.y + v.z + v.w;
        }
#pragma unroll
        for (int o = 16; o; o >>= 1) s += __shfl_xor_sync(0xffffffffu, s, o);
        float inv = 1.f / s;
#pragma unroll
        for (int k = 0; k < 12; k++) {
            p4[k].x *= inv; p4[k].y *= inv; p4[k].z *= inv; p4[k].w *= inv;
            *(float4*)(rowF + 8 + 4 * (lane + 32 * k)) = p4[k];
        }
        __syncwarp();

#pragma unroll 1
        for (int step = 0; step < 3; step++) {
            float4 c4[12];
            float sa = 0.f;
#pragma unroll
            for (int k = 0; k < 12; k++) {
                int m = lane + 32 * k;
                float4 o4 = p4[k];
                float4 h4v = *(const float4*)(rowF + 4 + 4 * m);
                float4 kv = kvs4[m];
                float4 cc;
                cc.x = (w0 * h4v.x + w1 * h4v.y + w2 * h4v.z + w3 * h4v.w + w4 * o4.x) * kv.x;
                cc.y = (w0 * h4v.y + w1 * h4v.z + w2 * h4v.w + w3 * o4.x + w4 * o4.y) * kv.y;
                cc.z = (w0 * h4v.z + w1 * h4v.w + w2 * o4.x + w3 * o4.y + w4 * o4.z) * kv.z;
                cc.w = (w0 * h4v.w + w1 * o4.x + w2 * o4.y + w3 * o4.z + w4 * o4.w) * kv.w;
                c4[k] = cc;
                sa += cc.x + cc.y + cc.z + cc.w;
            }
#pragma unroll
            for (int o = 16; o; o >>= 1) sa += __shfl_xor_sync(0xffffffffu, sa, o);
            const float rmul = 0.02f / (sa + 1e-9f);
            __syncwarp();
#pragma unroll
            for (int k = 0; k < 12; k++) {
                p4[k].x = 0.98f * p4[k].x + rmul * c4[k].x;
                p4[k].y = 0.98f * p4[k].y + rmul * c4[k].y;
                p4[k].z = 0.98f * p4[k].z + rmul * c4[k].z;
                p4[k].w = 0.98f * p4[k].w + rmul * c4[k].w;
                *(float4*)(rowF + 8 + 4 * (lane + 32 * k)) = p4[k];
            }
            __syncwarp();
        }

        __syncthreads();
        __half* pr = Ps + (size_t)warp * PSTRF;
#pragma unroll
        for (int k = 0; k < 12; k++)
            *(uint2*)(pr + (size_t)(lane + 32 * k) * 4) = h4(p4[k]);
    }
    __syncthreads();

    // ---- phase 2: out[16x64] = p[16x1536] @ V[1536x64], cp.async 2-deep pipeline ----
    const int pi = warp >> 3;
    const int pg = (warp >> 1) & 3;
    const int pj = warp & 1;

    PFragC acc;
    wmma::fill_fragment(acc, 0.f);

    for (int c = 0; c < 12; c++) {
        if (c < 11) CP_WAIT(1); else CP_WAIT(0);
        __syncthreads();   // chunk c resident

        const __half* Vc = KVb + (c & 1) * 128 * 72;
#pragma unroll
        for (int kk = 0; kk < 32; kk += 16) {
            PFragA a;
            PFragB bb;
            wmma::load_matrix_sync(a, Ps + (size_t)(pi * 8) * PSTRF + c * 128 + pg * 32 + kk, PSTRF);
            wmma::load_matrix_sync(bb, Vc + (pg * 32 + kk) * 72 + pj * 32, 72);
            wmma::mma_sync(acc, a, bb, acc);
        }
        __syncthreads();   // reads of buffer (c&1) done
        if (c + 2 < 12) { issue_v(c + 2, c & 1); CP_COMMIT(); }
    }

    wmma::store_matrix_sync(Vred + (size_t)(pg * 16 + pi * 8) * 68 + pj * 32, acc,
                            68, wmma::mem_row_major);
    __syncthreads();

    if (t < 256) {
        const int row = t >> 4;
        const int col = (t & 15) << 2;
        float4 s0 = *(float4*)(Vred + (size_t)row * 68 + col);
#pragma unroll
        for (int gg = 1; gg < 4; gg++) {
            float4 a0 = *(float4*)(Vred + (size_t)(gg * 16 + row) * 68 + col);
            s0.x += a0.x; s0.y += a0.y; s0.z += a0.z; s0.w += a0.w;
        }
        __half* out = g_attn + ((size_t)(b * LL + q0 + row)) * PP + h * 64 + col;
        *(uint2*)out = h4(s0);
    }
}

// ---------------- launch ----------------
extern "C" void kernel_launch(void* const* d_in, const int* in_sizes, int n_in,
                              void* d_out, int out_size) {
    const float* hs = (const float*)d_in[0];
    const int* mask = (const int*)d_in[1];
    const float* Wq = (const float*)d_in[2];
    const float* bq = (const float*)d_in[3];
    const float* Wk = (const float*)d_in[4];
    const float* bk = (const float*)d_in[5];
    const float* Wv = (const float*)d_in[6];
    const float* bv = (const float*)d_in[7];
    const float* Wo = (const float*)d_in[8];
    const float* bo = (const float*)d_in[9];
    const float* kw = (const float*)d_in[10];

    cudaFuncSetAttribute(qkv_wmma, cudaFuncAttributeMaxDynamicSharedMemorySize, G_SMEM_BYTES);
    cudaFuncSetAttribute(oproj_wmma, cudaFuncAttributeMaxDynamicSharedMemorySize, G_SMEM_BYTES);
    cudaFuncSetAttribute(fused_all, cudaFuncAttributeMaxDynamicSharedMemorySize, FUSED_SMEM_BYTES);

    cvt_all<<<7168, 256>>>(hs, Wq, Wk, Wv, Wo);

    qkv_wmma<<<dim3(PP / 128, (BB * LL) / 128, 3), 256, G_SMEM_BYTES>>>(bq, bk, bv);

    fused_all<<<(BB * HH * LL) / FROWS, 512, FUSED_SMEM_BYTES>>>(mask, kw);

    oproj_wmma<<<dim3(PP / 128, (BB * LL) / 128), 256, G_SMEM_BYTES>>>(bo, (float*)d_out);
}

// round 15
// speedup vs baseline: 3.7252x; 1.0864x over previous
#include <cuda_runtime.h>
#include <cuda_fp16.h>
#include <mma.h>
using namespace nvcuda;

#define BB 2
#define LL 1536
#define DD 1024
#define HH 16
#define PP 1024
#define HDIM 64

// gemm128 dynamic smem (bytes)
#define G_TILE_OFF 8448
#define G_SMEM_BYTES (8448 + 67584)

// ---------------- fused_all smem layout (bytes) ----------------
#define FROWS 32
#define PSTRH 1544                               // halves per mirror row: [8 pad][1536]
#define PS_OFF   0                               // half PsF[32][1544] = 98816
#define KVS_OFF  98816                           // float kvs[1536] = 6144
#define W5_OFF   104960                          // float w5[5] (+pad) -> 104992
#define Q_OFF    104992                          // half Qs[32][72] = 4608 -> 109600
#define STG_OFF  109600                          // float Sstg[16][8][36] = 18432 -> 128032
#define KV_OFF   128032                          // half KVb[2][256][72] = 73728 -> 201760
#define FUSED_SMEM_BYTES (KV_OFF + 73728 + 32)   // ~197 KB; Vred float[2][32][68] aliases KVb

// half arena: hs | Wq | Wk | Wv | Wo
#define AH_OFF  0
#define WQ_OFF  3145728
#define WK_OFF  4194304
#define WV_OFF  5242880
#define WO_OFF  6291456
__device__ __half g_H[7340032];

__device__ __half g_Q[BB * HH * LL * HDIM];     // head-major, pre-scaled by 0.125
__device__ __half g_K[BB * HH * LL * HDIM];
__device__ __half g_V[BB * HH * LL * HDIM];
__device__ __half g_attn[BB * LL * PP];

typedef wmma::fragment<wmma::matrix_a, 16, 16, 16, __half, wmma::row_major> HFragA;
typedef wmma::fragment<wmma::matrix_b, 16, 16, 16, __half, wmma::row_major> HFragB;
typedef wmma::fragment<wmma::accumulator, 16, 16, 16, float> FragC;

typedef wmma::fragment<wmma::matrix_a, 8, 32, 16, __half, wmma::row_major> PFragA;
typedef wmma::fragment<wmma::matrix_b, 8, 32, 16, __half, wmma::row_major> PFragB;
typedef wmma::fragment<wmma::matrix_b, 8, 32, 16, __half, wmma::col_major> PFragBc;
typedef wmma::fragment<wmma::accumulator, 8, 32, 16, float> PFragC;

__device__ __forceinline__ uint2 h4(float4 v) {
    __half2 a = __floats2half2_rn(v.x, v.y);
    __half2 b = __floats2half2_rn(v.z, v.w);
    uint2 r;
    r.x = *(unsigned*)&a;
    r.y = *(unsigned*)&b;
    return r;
}
__device__ __forceinline__ float4 f4h(uint2 u) {
    float2 a = __half22float2(*(__half2*)&u.x);
    float2 b = __half22float2(*(__half2*)&u.y);
    return make_float4(a.x, a.y, b.x, b.y);
}

#define CP_ASYNC16(dst_u32, src_ptr) \
    asm volatile("cp.async.cg.shared.global [%0], [%1], 16;" :: "r"(dst_u32), "l"(src_ptr))
#define CP_COMMIT() asm volatile("cp.async.commit_group;" ::: "memory")
#define CP_WAIT(n)  asm volatile("cp.async.wait_group %0;" :: "n"(n) : "memory")

// ---------------- one-time fp32 -> fp16 conversion ----------------
__global__ __launch_bounds__(256) void cvt_all(const float* __restrict__ hs,
                                               const float* __restrict__ Wq,
                                               const float* __restrict__ Wk,
                                               const float* __restrict__ Wv,
                                               const float* __restrict__ Wo) {
    int i = blockIdx.x * 256 + threadIdx.x;
    const float* src;
    __half* dst;
    int off;
    if (i < 786432)       { src = hs; dst = g_H + AH_OFF; off = i; }
    else if (i < 1048576) { src = Wq; dst = g_H + WQ_OFF; off = i - 786432; }
    else if (i < 1310720) { src = Wk; dst = g_H + WK_OFF; off = i - 1048576; }
    else if (i < 1572864) { src = Wv; dst = g_H + WV_OFF; off = i - 1310720; }
    else                  { src = Wo; dst = g_H + WO_OFF; off = i - 1572864; }
    float4 v = ((const float4*)src)[off];
    ((uint2*)dst)[off] = h4(v);
}

// ---------------- 128x128 GEMM body (unchanged from round 14) -------------
__device__ __forceinline__ void gemm128_body(const __half* __restrict__ A,
                                             const __half* __restrict__ W,
                                             const float* __restrict__ bias,
                                             __half* __restrict__ Ch,
                                             float* __restrict__ Cf, int mode) {
    extern __shared__ char dsm[];
    float* BiasT = (float*)dsm;
    __half* AsB = (__half*)(dsm + G_TILE_OFF);
    __half* BsB = AsB + 2 * 128 * 40;
    float* Cst = (float*)(dsm + G_TILE_OFF);

    const int m0 = blockIdx.y * 128;
    const int n0 = blockIdx.x * 128;
    const int t = threadIdx.x;
    const int warp = t >> 5;
    const int wm = (warp & 3) * 32;
    const int wn = (warp >> 2) * 64;

#pragma unroll
    for (int r = 0; r < 2; r++) {
        int idx = t + r * 256;
        int row = idx >> 5;
        int col = (idx & 31) << 2;
        *(float4*)(BiasT + row * 132 + col) = *(const float4*)(bias + n0 + col);
    }

    FragC c[2][4];
#pragma unroll
    for (int i = 0; i < 2; i++)
#pragma unroll
        for (int j = 0; j < 4; j++) wmma::fill_fragment(c[i][j], 0.f);

    uint4 apre[2], bpre[2];
#pragma unroll
    for (int r = 0; r < 2; r++) {
        int idx = t + r * 256;
        apre[r] = *(const uint4*)(A + (size_t)(m0 + (idx >> 2)) * DD + ((idx & 3) << 3));
        bpre[r] = *(const uint4*)(W + (size_t)(idx >> 4) * PP + n0 + ((idx & 15) << 3));
    }
#pragma unroll
    for (int r = 0; r < 2; r++) {
        int idx = t + r * 256;
        *(uint4*)(AsB + (idx >> 2) * 40 + ((idx & 3) << 3)) = apre[r];
        *(uint4*)(BsB + (idx >> 4) * 136 + ((idx & 15) << 3)) = bpre[r];
    }
    __syncthreads();

    for (int k0 = 0; k0 < DD; k0 += 32) {
        const int cur = (k0 >> 5) & 1, nxt = cur ^ 1;
        const bool more = (k0 + 32 < DD);
        if (more) {
#pragma unroll
            for (int r = 0; r < 2; r++) {
                int idx = t + r * 256;
                apre[r] = *(const uint4*)(A + (size_t)(m0 + (idx >> 2)) * DD + k0 + 32 + ((idx & 3) << 3));
                bpre[r] = *(const uint4*)(W + (size_t)(k0 + 32 + (idx >> 4)) * PP + n0 + ((idx & 15) << 3));
            }
        }
        const __half* Asc = AsB + cur * 128 * 40;
        const __half* Bsc = BsB + cur * 32 * 136;
#pragma unroll
        for (int kk = 0; kk < 32; kk += 16) {
            HFragA a[2];
#pragma unroll
            for (int i = 0; i < 2; i++)
                wmma::load_matrix_sync(a[i], Asc + (wm + i * 16) * 40 + kk, 40);
#pragma unroll
            for (int j = 0; j < 4; j++) {
                HFragB b;
                wmma::load_matrix_sync(b, Bsc + kk * 136 + wn + j * 16, 136);
#pragma unroll
                for (int i = 0; i < 2; i++) wmma::mma_sync(c[i][j], a[i], b, c[i][j]);
            }
        }
        if (more) {
#pragma unroll
            for (int r = 0; r < 2; r++) {
                int idx = t + r * 256;
                *(uint4*)(AsB + nxt * 128 * 40 + (idx >> 2) * 40 + ((idx & 3) << 3)) = apre[r];
                *(uint4*)(BsB + nxt * 32 * 136 + (idx >> 4) * 136 + ((idx & 15) << 3)) = bpre[r];
            }
        }
        __syncthreads();
    }

    const float scale = (mode == 0) ? 0.125f : 1.0f;
#pragma unroll
    for (int j = 0; j < 4; j++) {
        FragC bf;
        wmma::load_matrix_sync(bf, BiasT + wn + j * 16, 132, wmma::mem_row_major);
#pragma unroll
        for (int i = 0; i < 2; i++)
#pragma unroll
            for (int e = 0; e < bf.num_elements; e++)
                c[i][j].x[e] = (c[i][j].x[e] + bf.x[e]) * scale;
    }

    if (mode <= 2) {
#pragma unroll
        for (int i = 0; i < 2; i++)
#pragma unroll
            for (int j = 0; j < 4; j++)
                wmma::store_matrix_sync(Cst + (size_t)(wm + i * 16) * 132 + wn + j * 16,
                                        c[i][j], 132, wmma::mem_row_major);
        __syncthreads();

        const int b = m0 / LL;
        const int l0 = m0 - b * LL;
        const int hbase = n0 >> 6;
#pragma unroll
        for (int r = 0; r < 16; r++) {
            int idx = t + r * 256;
            int row = idx >> 5;
            int col = (idx & 31) << 2;
            uint2 hv = h4(*(float4*)(Cst + (size_t)row * 132 + col));
            int h = hbase + (col >> 6);
            int d = col & 63;
            __half* out = Ch + (((size_t)(b * HH + h)) * LL + l0 + row) * HDIM + d;
            *(uint2*)out = hv;
        }
    } else {
#pragma unroll
        for (int i = 0; i < 2; i++)
#pragma unroll
            for (int j = 0; j < 4; j++)
                wmma::store_matrix_sync(Cf + (size_t)(m0 + wm + i * 16) * PP + n0 + wn + j * 16,
                                        c[i][j], PP, wmma::mem_row_major);
    }
}

__global__ __launch_bounds__(256, 2) void qkv_wmma(const float* __restrict__ bq,
                                                   const float* __restrict__ bk,
                                                   const float* __restrict__ bv) {
    const int zz = blockIdx.z;
    const __half* W = g_H + ((zz == 0) ? WQ_OFF : (zz == 1) ? WK_OFF : WV_OFF);
    const float* bias = (zz == 0) ? bq : (zz == 1) ? bk : bv;
    __half* C = (zz == 0) ? g_Q : (zz == 1) ? g_K : g_V;
    gemm128_body(g_H + AH_OFF, W, bias, C, nullptr, zz);
}

__global__ __launch_bounds__(256, 2) void oproj_wmma(const float* __restrict__ bias,
                                                     float* __restrict__ Cout) {
    gemm128_body(g_attn, g_H + WO_OFF, bias, nullptr, Cout, 3);
}

// ---------------- fused_all: 32 q-rows/block; fp16 S/p mirror ------------------------
__global__ __launch_bounds__(512, 1) void fused_all(const int* __restrict__ mask,
                                                    const float* __restrict__ kw) {
    extern __shared__ char smraw[];
    __half* PsF = (__half*)smraw;                      // [32][1544]: [8 pad][1536 data]
    float* kvs = (float*)(smraw + KVS_OFF);            // [1536]
    float* w5s = (float*)(smraw + W5_OFF);             // [5]
    __half* Qs = (__half*)(smraw + Q_OFF);             // [32][72]
    float* Sstg = (float*)(smraw + STG_OFF);           // [16][8][36]
    __half* KVb = (__half*)(smraw + KV_OFF);           // [2][256][72]
    float* Vred = (float*)(smraw + KV_OFF);            // [2][32][68] (aliases KVb at end)
    const unsigned KVb_u32 = (unsigned)__cvta_generic_to_shared(KVb);

    const int t = threadIdx.x;
    const int warp = t >> 5, lane = t & 31;
    const int row0 = blockIdx.x * FROWS;
    const int z = row0 / LL;
    const int q0 = row0 - z * LL;
    const int b = z >> 4;
    const int h = z & 15;
    const int* mrow = mask + b * LL;
    const __half* Qg = g_Q + ((size_t)z * LL + q0) * HDIM;
    const __half* Kg = g_K + (size_t)z * LL * HDIM;
    const __half* Vg = g_V + (size_t)z * LL * HDIM;

    auto issue_k = [&](int slab, int buf) {
#pragma unroll
        for (int r = 0; r < 4; r++) {
            int u = t + r * 512;
            int row = u >> 3, cc = (u & 7) << 3;
            CP_ASYNC16(KVb_u32 + (buf * 256 * 72 + row * 72 + cc) * 2,
                       Kg + (size_t)(slab * 256 + row) * HDIM + cc);
        }
    };
    auto issue_v = [&](int chunk, int buf) {
#pragma unroll
        for (int r = 0; r < 2; r++) {
            int u = t + r * 512;
            int row = u >> 3, cc = (u & 7) << 3;
            CP_ASYNC16(KVb_u32 + (buf * 128 * 72 + row * 72 + cc) * 2,
                       Vg + (size_t)(chunk * 128 + row) * HDIM + cc);
        }
    };

    issue_k(0, 0); CP_COMMIT();

    if (t == 0) {
        float mxw = kw[0];
#pragma unroll
        for (int j = 1; j < 5; j++) mxw = fmaxf(mxw, kw[j]);
        float e[5], s = 0.f;
#pragma unroll
        for (int j = 0; j < 5; j++) { e[j] = __expf(kw[j] - mxw); s += e[j]; }
#pragma unroll
        for (int j = 0; j < 5; j++) w5s[j] = e[j] / s;
    }
    if (t < LL / 4) {
        int4 m4 = *(const int4*)(mrow + t * 4);
        *(float4*)(kvs + t * 4) = make_float4(m4.x > 0 ? 1.f : 0.f, m4.y > 0 ? 1.f : 0.f,
                                              m4.z > 0 ? 1.f : 0.f, m4.w > 0 ? 1.f : 0.f);
    }
    {   // Q tile: 32 rows x 16 uint2 cols = 512 threads, 1 each
        int row = t >> 4, col = (t & 15) << 2;
        *(uint2*)(Qs + row * 72 + col) = *(const uint2*)(Qg + (size_t)row * HDIM + col);
    }
    __syncthreads();

    const int rg = warp >> 3;     // 0..1: row-group base selector
    const int sj = warp & 7;      // 0..7: key col tile (32 keys)

    // hoist Q fragments: rows rg*8+16*i
    PFragA aq[2][4];
#pragma unroll
    for (int i = 0; i < 2; i++)
#pragma unroll
        for (int kk = 0; kk < 4; kk++)
            wmma::load_matrix_sync(aq[i][kk], Qs + (rg * 8 + 16 * i) * 72 + kk * 16, 72);

    float* Sw = Sstg + warp * 8 * 36;

    // ---- S-compute: 6 slabs of 256 keys, cp.async double-buffered; S -> fp16 mirror ----
    for (int s = 0; s < 6; s++) {
        const int cur = s & 1, nxt = cur ^ 1;
        const bool more = (s + 1 < 6);
        if (more) { issue_k(s + 1, nxt); CP_COMMIT(); }
        if (more) CP_WAIT(1); else CP_WAIT(0);
        __syncthreads();

        const __half* Kc = KVb + cur * 256 * 72;
#pragma unroll
        for (int i = 0; i < 2; i++) {
            PFragC sacc;
            wmma::fill_fragment(sacc, 0.f);
#pragma unroll
            for (int kk = 0; kk < 4; kk++) {
                PFragBc bb;
                wmma::load_matrix_sync(bb, Kc + (sj * 32) * 72 + kk * 16, 72);
                wmma::mma_sync(sacc, aq[i][kk], bb, sacc);
            }
            wmma::store_matrix_sync(Sw, sacc, 36, wmma::mem_row_major);
            __syncwarp();
            // convert 8x32 floats -> fp16 mirror
            {
                int r = lane >> 2, q = lane & 3;
                const float* src = Sw + r * 36 + q * 8;
                float4 f0 = *(const float4*)src;
                float4 f1 = *(const float4*)(src + 4);
                uint2 u0 = h4(f0), u1 = h4(f1);
                uint4 uu = make_uint4(u0.x, u0.y, u1.x, u1.y);
                int row = rg * 8 + 16 * i + r;
                *(uint4*)(PsF + (size_t)row * PSTRH + 8 + s * 256 + sj * 32 + q * 8) = uu;
            }
            __syncwarp();
        }
        __syncthreads();
    }

    // prefetch both V chunks under phase 1
    issue_v(0, 0); CP_COMMIT();
    issue_v(1, 1); CP_COMMIT();

    const float w0 = w5s[0], w1 = w5s[1], w2 = w5s[2], w3 = w5s[3], w4 = w5s[4];
    const float4* kvs4 = (const float4*)kvs;

    // ---- phase 1: warp handles rows warp and warp+16 sequentially ----
#pragma unroll 1
    for (int i = 0; i < 2; i++) {
        const int row = warp + 16 * i;
        __half* rowH = PsF + (size_t)row * PSTRH;     // [0..7]=pad, data at +8
        if (lane == 0) *(uint4*)rowH = make_uint4(0, 0, 0, 0);

        float4 p4[12];
        float mx = -3.4e38f;
#pragma unroll
        for (int k = 0; k < 12; k++) {
            int m = lane + 32 * k;
            float4 v = f4h(*(const uint2*)(rowH + 8 + 4 * m));
            float4 kv = kvs4[m];
            v.x += (kv.x > 0.f) ? 0.f : -1e9f;
            v.y += (kv.y > 0.f) ? 0.f : -1e9f;
            v.z += (kv.z > 0.f) ? 0.f : -1e9f;
            v.w += (kv.w > 0.f) ? 0.f : -1e9f;
            p4[k] = v;
            mx = fmaxf(mx, fmaxf(fmaxf(v.x, v.y), fmaxf(v.z, v.w)));
        }
#pragma unroll
        for (int o = 16; o; o >>= 1) mx = fmaxf(mx, __shfl_xor_sync(0xffffffffu, mx, o));

        float s = 0.f;
#pragma unroll
        for (int k = 0; k < 12; k++) {
            float4 v = p4[k];
            v.x = __expf(v.x - mx); v.y = __expf(v.y - mx);
            v.z = __expf(v.z - mx); v.w = __expf(v.w - mx);
            p4[k] = v;
            s += v.x + v.y + v.z + v.w;
        }
#pragma unroll
        for (int o = 16; o; o >>= 1) s += __shfl_xor_sync(0xffffffffu, s, o);
        float inv = 1.f / s;
#pragma unroll
        for (int k = 0; k < 12; k++) {
            p4[k].x *= inv; p4[k].y *= inv; p4[k].z *= inv; p4[k].w *= inv;
            *(uint2*)(rowH + 8 + 4 * (lane + 32 * k)) = h4(p4[k]);
        }
        __syncwarp();

#pragma unroll 1
        for (int step = 0; step < 3; step++) {
            float4 c4[12];
            float sa = 0.f;
#pragma unroll
            for (int k = 0; k < 12; k++) {
                int m = lane + 32 * k;
                float4 o4 = p4[k];
                float4 h4v = f4h(*(const uint2*)(rowH + 4 + 4 * m));   // halo, fp16
                float4 kv = kvs4[m];
                float4 cc;
                cc.x = (w0 * h4v.x + w1 * h4v.y + w2 * h4v.z + w3 * h4v.w + w4 * o4.x) * kv.x;
                cc.y = (w0 * h4v.y + w1 * h4v.z + w2 * h4v.w + w3 * o4.x + w4 * o4.y) * kv.y;
                cc.z = (w0 * h4v.z + w1 * h4v.w + w2 * o4.x + w3 * o4.y + w4 * o4.z) * kv.z;
                cc.w = (w0 * h4v.w + w1 * o4.x + w2 * o4.y + w3 * o4.z + w4 * o4.w) * kv.w;
                c4[k] = cc;
                sa += cc.x + cc.y + cc.z + cc.w;
            }
#pragma unroll
            for (int o = 16; o; o >>= 1) sa += __shfl_xor_sync(0xffffffffu, sa, o);
            const float rmul = 0.02f / (sa + 1e-9f);
            __syncwarp();
#pragma unroll
            for (int k = 0; k < 12; k++) {
                p4[k].x = 0.98f * p4[k].x + rmul * c4[k].x;
                p4[k].y = 0.98f * p4[k].y + rmul * c4[k].y;
                p4[k].z = 0.98f * p4[k].z + rmul * c4[k].z;
                p4[k].w = 0.98f * p4[k].w + rmul * c4[k].w;
                *(uint2*)(rowH + 8 + 4 * (lane + 32 * k)) = h4(p4[k]);
            }
            __syncwarp();
        }
    }
    __syncthreads();   // all mirrors final (they ARE the p operand)

    // ---- phase 2: out[32x64] = p @ V; chunk-parity k-split across 16 warps ----
    const int rp = warp >> 2;            // 0..3 row group (8 rows)
    const int pj = (warp >> 1) & 1;      // 0..1 col tile (32 cols)
    const int pg = warp & 1;             // 0..1 chunk parity

    PFragC acc;
    wmma::fill_fragment(acc, 0.f);

    for (int c = 0; c < 12; c++) {
        if (c < 11) CP_WAIT(1); else CP_WAIT(0);
        __syncthreads();
        const __half* Vc = KVb + (c & 1) * 128 * 72;
        if ((c & 1) == pg) {
#pragma unroll
            for (int kk = 0; kk < 128; kk += 16) {
                PFragA a;
                PFragB bb;
                wmma::load_matrix_sync(a, PsF + (size_t)(rp * 8) * PSTRH + 8 + c * 128 + kk, PSTRH);
                wmma::load_matrix_sync(bb, Vc + kk * 72 + pj * 32, 72);
                wmma::mma_sync(acc, a, bb, acc);
            }
        }
        __syncthreads();
        if (c + 2 < 12) { issue_v(c + 2, c & 1); CP_COMMIT(); }
    }

    wmma::store_matrix_sync(Vred + (size_t)(pg * 32 + rp * 8) * 68 + pj * 32, acc,
                            68, wmma::mem_row_major);
    __syncthreads();

    {   // 32 rows x 16 float4 cols = 512 threads
        const int row = t >> 4;
        const int col = (t & 15) << 2;
        float4 s0 = *(float4*)(Vred + (size_t)row * 68 + col);
        float4 s1 = *(float4*)(Vred + (size_t)(32 + row) * 68 + col);
        s0.x += s1.x; s0.y += s1.y; s0.z += s1.z; s0.w += s1.w;
        __half* out = g_attn + ((size_t)(b * LL + q0 + row)) * PP + h * 64 + col;
        *(uint2*)out = h4(s0);
    }
}

// ---------------- launch ----------------
extern "C" void kernel_launch(void* const* d_in, const int* in_sizes, int n_in,
                              void* d_out, int out_size) {
    const float* hs = (const float*)d_in[0];
    const int* mask = (const int*)d_in[1];
    const float* Wq = (const float*)d_in[2];
    const float* bq = (const float*)d_in[3];
    const float* Wk = (const float*)d_in[4];
    const float* bk = (const float*)d_in[5];
    const float* Wv = (const float*)d_in[6];
    const float* bv = (const float*)d_in[7];
    const float* Wo = (const float*)d_in[8];
    const float* bo = (const float*)d_in[9];
    const float* kw = (const float*)d_in[10];

    cudaFuncSetAttribute(qkv_wmma, cudaFuncAttributeMaxDynamicSharedMemorySize, G_SMEM_BYTES);
    cudaFuncSetAttribute(oproj_wmma, cudaFuncAttributeMaxDynamicSharedMemorySize, G_SMEM_BYTES);
    cudaFuncSetAttribute(fused_all, cudaFuncAttributeMaxDynamicSharedMemorySize, FUSED_SMEM_BYTES);

    cvt_all<<<7168, 256>>>(hs, Wq, Wk, Wv, Wo);

    qkv_wmma<<<dim3(PP / 128, (BB * LL) / 128, 3), 256, G_SMEM_BYTES>>>(bq, bk, bv);

    fused_all<<<(BB * HH * LL) / FROWS, 512, FUSED_SMEM_BYTES>>>(mask, kw);

    oproj_wmma<<<dim3(PP / 128, (BB * LL) / 128), 256, G_SMEM_BYTES>>>(bo, (float*)d_out);
}

// round 16
// speedup vs baseline: 3.9925x; 1.0718x over previous
#include <cuda_runtime.h>
#include <cuda_fp16.h>
#include <mma.h>
using namespace nvcuda;

#define BB 2
#define LL 1536
#define DD 1024
#define HH 16
#define PP 1024
#define HDIM 64

// gemm128 dynamic smem (bytes)
#define G_TILE_OFF 8448
#define G_SMEM_BYTES (8448 + 67584)

// ---------------- fused_all smem layout (bytes) ----------------
#define FROWS 32
#define PSTRH 1544                               // halves per mirror row: [8 pad][1536]
#define KVS_OFF  98816                           // float kvs[1536] = 6144
#define KVH_OFF  104960                          // half kvh[1536] = 3072
#define W5_OFF   108032                          // float w5[5] (+pad) -> 108064
#define Q_OFF    108064                          // half Qs[32][72] = 4608 -> 112672
#define STG_OFF  112672                          // float Sstg[16][8][36] = 18432 -> 131104
#define KV_OFF   131104                          // half KVb[2][256][72] = 73728 -> 204832
#define FUSED_SMEM_BYTES (KV_OFF + 73728 + 32)   // ~200 KB; Vred float[2][32][68] aliases KVb

// half arena: hs | Wq | Wk | Wv | Wo
#define AH_OFF  0
#define WQ_OFF  3145728
#define WK_OFF  4194304
#define WV_OFF  5242880
#define WO_OFF  6291456
__device__ __half g_H[7340032];

__device__ __half g_Q[BB * HH * LL * HDIM];     // head-major, pre-scaled by 0.125
__device__ __half g_K[BB * HH * LL * HDIM];
__device__ __half g_V[BB * HH * LL * HDIM];
__device__ __half g_attn[BB * LL * PP];

typedef wmma::fragment<wmma::matrix_a, 16, 16, 16, __half, wmma::row_major> HFragA;
typedef wmma::fragment<wmma::matrix_b, 16, 16, 16, __half, wmma::row_major> HFragB;
typedef wmma::fragment<wmma::accumulator, 16, 16, 16, float> FragC;

typedef wmma::fragment<wmma::matrix_a, 8, 32, 16, __half, wmma::row_major> PFragA;
typedef wmma::fragment<wmma::matrix_b, 8, 32, 16, __half, wmma::row_major> PFragB;
typedef wmma::fragment<wmma::matrix_b, 8, 32, 16, __half, wmma::col_major> PFragBc;
typedef wmma::fragment<wmma::accumulator, 8, 32, 16, float> PFragC;

__device__ __forceinline__ uint2 h4(float4 v) {
    __half2 a = __floats2half2_rn(v.x, v.y);
    __half2 b = __floats2half2_rn(v.z, v.w);
    uint2 r;
    r.x = *(unsigned*)&a;
    r.y = *(unsigned*)&b;
    return r;
}
__device__ __forceinline__ float4 f4h(uint2 u) {
    float2 a = __half22float2(*(__half2*)&u.x);
    float2 b = __half22float2(*(__half2*)&u.y);
    return make_float4(a.x, a.y, b.x, b.y);
}
__device__ __forceinline__ __half2 u2h(unsigned u) { return *(__half2*)&u; }
__device__ __forceinline__ unsigned h2u(__half2 h) { return *(unsigned*)&h; }

#define CP_ASYNC16(dst_u32, src_ptr) \
    asm volatile("cp.async.cg.shared.global [%0], [%1], 16;" :: "r"(dst_u32), "l"(src_ptr))
#define CP_COMMIT() asm volatile("cp.async.commit_group;" ::: "memory")
#define CP_WAIT(n)  asm volatile("cp.async.wait_group %0;" :: "n"(n) : "memory")

// ---------------- one-time fp32 -> fp16 conversion ----------------
__global__ __launch_bounds__(256) void cvt_all(const float* __restrict__ hs,
                                               const float* __restrict__ Wq,
                                               const float* __restrict__ Wk,
                                               const float* __restrict__ Wv,
                                               const float* __restrict__ Wo) {
    int i = blockIdx.x * 256 + threadIdx.x;
    const float* src;
    __half* dst;
    int off;
    if (i < 786432)       { src = hs; dst = g_H + AH_OFF; off = i; }
    else if (i < 1048576) { src = Wq; dst = g_H + WQ_OFF; off = i - 786432; }
    else if (i < 1310720) { src = Wk; dst = g_H + WK_OFF; off = i - 1048576; }
    else if (i < 1572864) { src = Wv; dst = g_H + WV_OFF; off = i - 1310720; }
    else                  { src = Wo; dst = g_H + WO_OFF; off = i - 1572864; }
    float4 v = ((const float4*)src)[off];
    ((uint2*)dst)[off] = h4(v);
}

// ---------------- 128x128 GEMM body, cp.async staged -------------
__device__ __forceinline__ void gemm128_body(const __half* __restrict__ A,
                                             const __half* __restrict__ W,
                                             const float* __restrict__ bias,
                                             __half* __restrict__ Ch,
                                             float* __restrict__ Cf, int mode) {
    extern __shared__ char dsm[];
    float* BiasT = (float*)dsm;
    __half* AsB = (__half*)(dsm + G_TILE_OFF);        // [2][128][40]
    __half* BsB = AsB + 2 * 128 * 40;                 // [2][32][136]
    float* Cst = (float*)(dsm + G_TILE_OFF);          // [128][132]
    const unsigned AsB_u32 = (unsigned)__cvta_generic_to_shared(AsB);
    const unsigned BsB_u32 = (unsigned)__cvta_generic_to_shared(BsB);

    const int m0 = blockIdx.y * 128;
    const int n0 = blockIdx.x * 128;
    const int t = threadIdx.x;
    const int warp = t >> 5;
    const int wm = (warp & 3) * 32;
    const int wn = (warp >> 2) * 64;

#pragma unroll
    for (int r = 0; r < 2; r++) {
        int idx = t + r * 256;
        int row = idx >> 5;
        int col = (idx & 31) << 2;
        *(float4*)(BiasT + row * 132 + col) = *(const float4*)(bias + n0 + col);
    }

    FragC c[2][4];
#pragma unroll
    for (int i = 0; i < 2; i++)
#pragma unroll
        for (int j = 0; j < 4; j++) wmma::fill_fragment(c[i][j], 0.f);

    auto issue = [&](int k0, int buf) {
#pragma unroll
        for (int r = 0; r < 2; r++) {
            int idx = t + r * 256;
            int arow = idx >> 2, ac = (idx & 3) << 3;
            CP_ASYNC16(AsB_u32 + (buf * 128 * 40 + arow * 40 + ac) * 2,
                       A + (size_t)(m0 + arow) * DD + k0 + ac);
            int brow = idx >> 4, bc = (idx & 15) << 3;
            CP_ASYNC16(BsB_u32 + (buf * 32 * 136 + brow * 136 + bc) * 2,
                       W + (size_t)(k0 + brow) * PP + n0 + bc);
        }
    };

    issue(0, 0); CP_COMMIT();

    for (int k0 = 0; k0 < DD; k0 += 32) {
        const int cur = (k0 >> 5) & 1, nxt = cur ^ 1;
        const bool more = (k0 + 32 < DD);
        if (more) { issue(k0 + 32, nxt); CP_COMMIT(); }
        if (more) CP_WAIT(1); else CP_WAIT(0);
        __syncthreads();

        const __half* Asc = AsB + cur * 128 * 40;
        const __half* Bsc = BsB + cur * 32 * 136;
#pragma unroll
        for (int kk = 0; kk < 32; kk += 16) {
            HFragA a[2];
#pragma unroll
            for (int i = 0; i < 2; i++)
                wmma::load_matrix_sync(a[i], Asc + (wm + i * 16) * 40 + kk, 40);
#pragma unroll
            for (int j = 0; j < 4; j++) {
                HFragB b;
                wmma::load_matrix_sync(b, Bsc + kk * 136 + wn + j * 16, 136);
#pragma unroll
                for (int i = 0; i < 2; i++) wmma::mma_sync(c[i][j], a[i], b, c[i][j]);
            }
        }
        __syncthreads();
    }

    const float scale = (mode == 0) ? 0.125f : 1.0f;
#pragma unroll
    for (int j = 0; j < 4; j++) {
        FragC bf;
        wmma::load_matrix_sync(bf, BiasT + wn + j * 16, 132, wmma::mem_row_major);
#pragma unroll
        for (int i = 0; i < 2; i++)
#pragma unroll
            for (int e = 0; e < bf.num_elements; e++)
                c[i][j].x[e] = (c[i][j].x[e] + bf.x[e]) * scale;
    }

    if (mode <= 2) {
#pragma unroll
        for (int i = 0; i < 2; i++)
#pragma unroll
            for (int j = 0; j < 4; j++)
                wmma::store_matrix_sync(Cst + (size_t)(wm + i * 16) * 132 + wn + j * 16,
                                        c[i][j], 132, wmma::mem_row_major);
        __syncthreads();

        const int b = m0 / LL;
        const int l0 = m0 - b * LL;
        const int hbase = n0 >> 6;
#pragma unroll
        for (int r = 0; r < 16; r++) {
            int idx = t + r * 256;
            int row = idx >> 5;
            int col = (idx & 31) << 2;
            uint2 hv = h4(*(float4*)(Cst + (size_t)row * 132 + col));
            int h = hbase + (col >> 6);
            int d = col & 63;
            __half* out = Ch + (((size_t)(b * HH + h)) * LL + l0 + row) * HDIM + d;
            *(uint2*)out = hv;
        }
    } else {
#pragma unroll
        for (int i = 0; i < 2; i++)
#pragma unroll
            for (int j = 0; j < 4; j++)
                wmma::store_matrix_sync(Cf + (size_t)(m0 + wm + i * 16) * PP + n0 + wn + j * 16,
                                        c[i][j], PP, wmma::mem_row_major);
    }
}

__global__ __launch_bounds__(256, 2) void qkv_wmma(const float* __restrict__ bq,
                                                   const float* __restrict__ bk,
                                                   const float* __restrict__ bv) {
    const int zz = blockIdx.z;
    const __half* W = g_H + ((zz == 0) ? WQ_OFF : (zz == 1) ? WK_OFF : WV_OFF);
    const float* bias = (zz == 0) ? bq : (zz == 1) ? bk : bv;
    __half* C = (zz == 0) ? g_Q : (zz == 1) ? g_K : g_V;
    gemm128_body(g_H + AH_OFF, W, bias, C, nullptr, zz);
}

__global__ __launch_bounds__(256, 2) void oproj_wmma(const float* __restrict__ bias,
                                                     float* __restrict__ Cout) {
    gemm128_body(g_attn, g_H + WO_OFF, bias, nullptr, Cout, 3);
}

// ---------------- fused_all: 32 q-rows/block; fp16 mirror; half2 diffusion -----------
__global__ __launch_bounds__(512, 1) void fused_all(const int* __restrict__ mask,
                                                    const float* __restrict__ kw) {
    extern __shared__ char smraw[];
    __half* PsF = (__half*)smraw;                      // [32][1544]: [8 pad][1536 data]
    float* kvs = (float*)(smraw + KVS_OFF);            // [1536]
    __half* kvh = (__half*)(smraw + KVH_OFF);          // [1536]
    float* w5s = (float*)(smraw + W5_OFF);             // [5]
    __half* Qs = (__half*)(smraw + Q_OFF);             // [32][72]
    float* Sstg = (float*)(smraw + STG_OFF);           // [16][8][36]
    __half* KVb = (__half*)(smraw + KV_OFF);           // [2][256][72]
    float* Vred = (float*)(smraw + KV_OFF);            // [2][32][68] (aliases KVb)
    const unsigned KVb_u32 = (unsigned)__cvta_generic_to_shared(KVb);

    const int t = threadIdx.x;
    const int warp = t >> 5, lane = t & 31;
    const int row0 = blockIdx.x * FROWS;
    const int z = row0 / LL;
    const int q0 = row0 - z * LL;
    const int b = z >> 4;
    const int h = z & 15;
    const int* mrow = mask + b * LL;
    const __half* Qg = g_Q + ((size_t)z * LL + q0) * HDIM;
    const __half* Kg = g_K + (size_t)z * LL * HDIM;
    const __half* Vg = g_V + (size_t)z * LL * HDIM;

    auto issue_k = [&](int slab, int buf) {
#pragma unroll
        for (int r = 0; r < 4; r++) {
            int u = t + r * 512;
            int row = u >> 3, cc = (u & 7) << 3;
            CP_ASYNC16(KVb_u32 + (buf * 256 * 72 + row * 72 + cc) * 2,
                       Kg + (size_t)(slab * 256 + row) * HDIM + cc);
        }
    };
    auto issue_v = [&](int chunk, int buf) {
#pragma unroll
        for (int r = 0; r < 2; r++) {
            int u = t + r * 512;
            int row = u >> 3, cc = (u & 7) << 3;
            CP_ASYNC16(KVb_u32 + (buf * 128 * 72 + row * 72 + cc) * 2,
                       Vg + (size_t)(chunk * 128 + row) * HDIM + cc);
        }
    };

    issue_k(0, 0); CP_COMMIT();

    if (t == 0) {
        float mxw = kw[0];
#pragma unroll
        for (int j = 1; j < 5; j++) mxw = fmaxf(mxw, kw[j]);
        float e[5], s = 0.f;
#pragma unroll
        for (int j = 0; j < 5; j++) { e[j] = __expf(kw[j] - mxw); s += e[j]; }
#pragma unroll
        for (int j = 0; j < 5; j++) w5s[j] = e[j] / s;
    }
    if (t < LL / 4) {
        int4 m4 = *(const int4*)(mrow + t * 4);
        float4 kvf = make_float4(m4.x > 0 ? 1.f : 0.f, m4.y > 0 ? 1.f : 0.f,
                                 m4.z > 0 ? 1.f : 0.f, m4.w > 0 ? 1.f : 0.f);
        *(float4*)(kvs + t * 4) = kvf;
        *(uint2*)(kvh + t * 4) = h4(kvf);
    }
    {
        int row = t >> 4, col = (t & 15) << 2;
        *(uint2*)(Qs + row * 72 + col) = *(const uint2*)(Qg + (size_t)row * HDIM + col);
    }
    __syncthreads();

    const int rg = warp >> 3;
    const int sj = warp & 7;

    PFragA aq[2][4];
#pragma unroll
    for (int i = 0; i < 2; i++)
#pragma unroll
        for (int kk = 0; kk < 4; kk++)
            wmma::load_matrix_sync(aq[i][kk], Qs + (rg * 8 + 16 * i) * 72 + kk * 16, 72);

    float* Sw = Sstg + warp * 8 * 36;

    // ---- S-compute: 6 slabs of 256 keys -> fp16 mirror ----
    for (int s = 0; s < 6; s++) {
        const int cur = s & 1, nxt = cur ^ 1;
        const bool more = (s + 1 < 6);
        if (more) { issue_k(s + 1, nxt); CP_COMMIT(); }
        if (more) CP_WAIT(1); else CP_WAIT(0);
        __syncthreads();

        const __half* Kc = KVb + cur * 256 * 72;
#pragma unroll
        for (int i = 0; i < 2; i++) {
            PFragC sacc;
            wmma::fill_fragment(sacc, 0.f);
#pragma unroll
            for (int kk = 0; kk < 4; kk++) {
                PFragBc bb;
                wmma::load_matrix_sync(bb, Kc + (sj * 32) * 72 + kk * 16, 72);
                wmma::mma_sync(sacc, aq[i][kk], bb, sacc);
            }
            wmma::store_matrix_sync(Sw, sacc, 36, wmma::mem_row_major);
            __syncwarp();
            {
                int r = lane >> 2, q = lane & 3;
                const float* src = Sw + r * 36 + q * 8;
                float4 f0 = *(const float4*)src;
                float4 f1 = *(const float4*)(src + 4);
                uint2 u0 = h4(f0), u1 = h4(f1);
                uint4 uu = make_uint4(u0.x, u0.y, u1.x, u1.y);
                int row = rg * 8 + 16 * i + r;
                *(uint4*)(PsF + (size_t)row * PSTRH + 8 + s * 256 + sj * 32 + q * 8) = uu;
            }
            __syncwarp();
        }
        __syncthreads();
    }

    issue_v(0, 0); CP_COMMIT();
    issue_v(1, 1); CP_COMMIT();

    const __half2 w0h = __float2half2_rn(w5s[0]);
    const __half2 w1h = __float2half2_rn(w5s[1]);
    const __half2 w2h = __float2half2_rn(w5s[2]);
    const __half2 w3h = __float2half2_rn(w5s[3]);
    const __half2 w4h = __float2half2_rn(w5s[4]);
    const __half2 a98 = __float2half2_rn(0.98f);
    const float4* kvs4 = (const float4*)kvs;

    // ---- phase 1: softmax fp32, then half2 diffusion; p fully fp16 ----
#pragma unroll 1
    for (int i = 0; i < 2; i++) {
        const int row = warp + 16 * i;
        __half* rowH = PsF + (size_t)row * PSTRH;
        if (lane == 0) *(uint4*)rowH = make_uint4(0, 0, 0, 0);

        unsigned plo[12], phi[12];
        {
            float4 p4[12];
            float mx = -3.4e38f;
#pragma unroll
            for (int k = 0; k < 12; k++) {
                int m = lane + 32 * k;
                float4 v = f4h(*(const uint2*)(rowH + 8 + 4 * m));
                float4 kv = kvs4[m];
                v.x += (kv.x > 0.f) ? 0.f : -1e9f;
                v.y += (kv.y > 0.f) ? 0.f : -1e9f;
                v.z += (kv.z > 0.f) ? 0.f : -1e9f;
                v.w += (kv.w > 0.f) ? 0.f : -1e9f;
                p4[k] = v;
                mx = fmaxf(mx, fmaxf(fmaxf(v.x, v.y), fmaxf(v.z, v.w)));
            }
#pragma unroll
            for (int o = 16; o; o >>= 1) mx = fmaxf(mx, __shfl_xor_sync(0xffffffffu, mx, o));

            float s = 0.f;
#pragma unroll
            for (int k = 0; k < 12; k++) {
                float4 v = p4[k];
                v.x = __expf(v.x - mx); v.y = __expf(v.y - mx);
                v.z = __expf(v.z - mx); v.w = __expf(v.w - mx);
                p4[k] = v;
                s += v.x + v.y + v.z + v.w;
            }
#pragma unroll
            for (int o = 16; o; o >>= 1) s += __shfl_xor_sync(0xffffffffu, s, o);
            float inv = 1.f / s;
#pragma unroll
            for (int k = 0; k < 12; k++) {
                p4[k].x *= inv; p4[k].y *= inv; p4[k].z *= inv; p4[k].w *= inv;
                uint2 u = h4(p4[k]);
                plo[k] = u.x; phi[k] = u.y;
                *(uint2*)(rowH + 8 + 4 * (lane + 32 * k)) = u;
            }
        }
        __syncwarp();

#pragma unroll 1
        for (int step = 0; step < 3; step++) {
            unsigned cx[12], cz[12];
            float sa = 0.f;
#pragma unroll
            for (int k = 0; k < 12; k++) {
                int m = lane + 32 * k;
                uint2 H = *(const uint2*)(rowH + 4 + 4 * m);   // halo: (e-4,e-3),(e-2,e-1)
                unsigned hlo = H.x, hhi = H.y;
                unsigned olo = plo[k], ohi = phi[k];
                unsigned P1 = __byte_perm(hlo, hhi, 0x5432);   // (e-3,e-2)
                unsigned P3 = __byte_perm(hhi, olo, 0x5432);   // (e-1,e0)
                unsigned P5 = __byte_perm(olo, ohi, 0x5432);   // (e1,e2)
                __half2 cxy = __hmul2(w0h, u2h(hlo));
                cxy = __hfma2(w1h, u2h(P1), cxy);
                cxy = __hfma2(w2h, u2h(hhi), cxy);
                cxy = __hfma2(w3h, u2h(P3), cxy);
                cxy = __hfma2(w4h, u2h(olo), cxy);
                __half2 czw = __hmul2(w0h, u2h(hhi));
                czw = __hfma2(w1h, u2h(P3), czw);
                czw = __hfma2(w2h, u2h(olo), czw);
                czw = __hfma2(w3h, u2h(P5), czw);
                czw = __hfma2(w4h, u2h(ohi), czw);
                uint2 kvu = *(const uint2*)(kvh + 4 * m);
                cxy = __hmul2(cxy, u2h(kvu.x));
                czw = __hmul2(czw, u2h(kvu.y));
                cx[k] = h2u(cxy); cz[k] = h2u(czw);
                float2 f = __half22float2(__hadd2(cxy, czw));
                sa += f.x + f.y;
            }
#pragma unroll
            for (int o = 16; o; o >>= 1) sa += __shfl_xor_sync(0xffffffffu, sa, o);
            const float rmul = 0.02f / (sa + 1e-9f);
            const __half2 rm2 = __float2half2_rn(rmul);
            __syncwarp();   // all halo reads done before mirror rewrite
#pragma unroll
            for (int k = 0; k < 12; k++) {
                __half2 pl = __hfma2(a98, u2h(plo[k]), __hmul2(rm2, u2h(cx[k])));
                __half2 ph = __hfma2(a98, u2h(phi[k]), __hmul2(rm2, u2h(cz[k])));
                plo[k] = h2u(pl); phi[k] = h2u(ph);
                *(uint2*)(rowH + 8 + 4 * (lane + 32 * k)) = make_uint2(plo[k], phi[k]);
            }
            __syncwarp();
        }
    }
    __syncthreads();   // mirrors final = p operand

    // ---- phase 2: out[32x64] = p @ V; all warps every chunk (within-chunk k-split) ----
    const int rp = warp >> 2;            // 0..3 row group (8 rows)
    const int pj = (warp >> 1) & 1;      // 0..1 col tile (32 cols)
    const int kg = warp & 1;             // 0..1 k half within chunk (64 rows)

    PFragC acc;
    wmma::fill_fragment(acc, 0.f);

    for (int c = 0; c < 12; c++) {
        if (c < 11) CP_WAIT(1); else CP_WAIT(0);
        __syncthreads();
        const __half* Vc = KVb + (c & 1) * 128 * 72;
#pragma unroll
        for (int kk = 0; kk < 64; kk += 16) {
            PFragA a;
            PFragB bb;
            wmma::load_matrix_sync(a, PsF + (size_t)(rp * 8) * PSTRH + 8 + c * 128 + kg * 64 + kk, PSTRH);
            wmma::load_matrix_sync(bb, Vc + (kg * 64 + kk) * 72 + pj * 32, 72);
            wmma::mma_sync(acc, a, bb, acc);
        }
        __syncthreads();
        if (c + 2 < 12) { issue_v(c + 2, c & 1); CP_COMMIT(); }
    }

    wmma::store_matrix_sync(Vred + (size_t)(kg * 32 + rp * 8) * 68 + pj * 32, acc,
                            68, wmma::mem_row_major);
    __syncthreads();

    {
        const int row = t >> 4;
        const int col = (t & 15) << 2;
        float4 s0 = *(float4*)(Vred + (size_t)row * 68 + col);
        float4 s1 = *(float4*)(Vred + (size_t)(32 + row) * 68 + col);
        s0.x += s1.x; s0.y += s1.y; s0.z += s1.z; s0.w += s1.w;
        __half* out = g_attn + ((size_t)(b * LL + q0 + row)) * PP + h * 64 + col;
        *(uint2*)out = h4(s0);
    }
}

// ---------------- launch ----------------
extern "C" void kernel_launch(void* const* d_in, const int* in_sizes, int n_in,
                              void* d_out, int out_size) {
    const float* hs = (const float*)d_in[0];
    const int* mask = (const int*)d_in[1];
    const float* Wq = (const float*)d_in[2];
    const float* bq = (const float*)d_in[3];
    const float* Wk = (const float*)d_in[4];
    const float* bk = (const float*)d_in[5];
    const float* Wv = (const float*)d_in[6];
    const float* bv = (const float*)d_in[7];
    const float* Wo = (const float*)d_in[8];
    const float* bo = (const float*)d_in[9];
    const float* kw = (const float*)d_in[10];

    cudaFuncSetAttribute(qkv_wmma, cudaFuncAttributeMaxDynamicSharedMemorySize, G_SMEM_BYTES);
    cudaFuncSetAttribute(oproj_wmma, cudaFuncAttributeMaxDynamicSharedMemorySize, G_SMEM_BYTES);
    cudaFuncSetAttribute(fused_all, cudaFuncAttributeMaxDynamicSharedMemorySize, FUSED_SMEM_BYTES);

    cvt_all<<<7168, 256>>>(hs, Wq, Wk, Wv, Wo);

    qkv_wmma<<<dim3(PP / 128, (BB * LL) / 128, 3), 256, G_SMEM_BYTES>>>(bq, bk, bv);

    fused_all<<<(BB * HH * LL) / FROWS, 512, FUSED_SMEM_BYTES>>>(mask, kw);

    oproj_wmma<<<dim3(PP / 128, (BB * LL) / 128), 256, G_SMEM_BYTES>>>(bo, (float*)d_out);
}

// round 17
// speedup vs baseline: 4.0987x; 1.0266x over previous
#include <cuda_runtime.h>
#include <cuda_fp16.h>
#include <mma.h>
using namespace nvcuda;

#define BB 2
#define LL 1536
#define DD 1024
#define HH 16
#define PP 1024
#define HDIM 64

// gemm128 dynamic smem (bytes)
#define G_TILE_OFF 8448
#define G_SMEM_BYTES (8448 + 67584)

// ---------------- fused_all smem layout (bytes), FROWS=16, 256 thr, 2 CTAs/SM --------
#define FROWS 16
#define PSTRH 1544                               // halves per mirror row: [8 pad][1536]
#define KVH_OFF  49408                           // half kvh[1536] = 3072 -> 52480
#define W5_OFF   52480                           // float w5[8] = 32 -> 52512
#define Q_OFF    52512                           // half Qs[16][72] = 2304 -> 54816
#define STG_OFF  54816                           // float Sstg[8][8][36] = 9216 -> 64032
#define KV_OFF   64032                           // half KVb[2][128][72] = 36864 -> 100896
#define FUSED_SMEM_BYTES (100896 + 32)           // ~98.6 KB -> 2 CTAs/SM

// half arena: hs | Wq | Wk | Wv | Wo
#define AH_OFF  0
#define WQ_OFF  3145728
#define WK_OFF  4194304
#define WV_OFF  5242880
#define WO_OFF  6291456
__device__ __half g_H[7340032];

__device__ __half g_Q[BB * HH * LL * HDIM];     // head-major, pre-scaled by 0.125
__device__ __half g_K[BB * HH * LL * HDIM];
__device__ __half g_V[BB * HH * LL * HDIM];
__device__ __half g_attn[BB * LL * PP];

typedef wmma::fragment<wmma::matrix_a, 16, 16, 16, __half, wmma::row_major> HFragA;
typedef wmma::fragment<wmma::matrix_b, 16, 16, 16, __half, wmma::row_major> HFragB;
typedef wmma::fragment<wmma::accumulator, 16, 16, 16, float> FragC;

typedef wmma::fragment<wmma::matrix_a, 8, 32, 16, __half, wmma::row_major> PFragA;
typedef wmma::fragment<wmma::matrix_b, 8, 32, 16, __half, wmma::row_major> PFragB;
typedef wmma::fragment<wmma::matrix_b, 8, 32, 16, __half, wmma::col_major> PFragBc;
typedef wmma::fragment<wmma::accumulator, 8, 32, 16, float> PFragC;

__device__ __forceinline__ uint2 h4(float4 v) {
    __half2 a = __floats2half2_rn(v.x, v.y);
    __half2 b = __floats2half2_rn(v.z, v.w);
    uint2 r;
    r.x = *(unsigned*)&a;
    r.y = *(unsigned*)&b;
    return r;
}
__device__ __forceinline__ float4 f4h(uint2 u) {
    float2 a = __half22float2(*(__half2*)&u.x);
    float2 b = __half22float2(*(__half2*)&u.y);
    return make_float4(a.x, a.y, b.x, b.y);
}
__device__ __forceinline__ __half2 u2h(unsigned u) { return *(__half2*)&u; }
__device__ __forceinline__ unsigned h2u(__half2 h) { return *(unsigned*)&h; }

#define CP_ASYNC16(dst_u32, src_ptr) \
    asm volatile("cp.async.cg.shared.global [%0], [%1], 16;" :: "r"(dst_u32), "l"(src_ptr))
#define CP_COMMIT() asm volatile("cp.async.commit_group;" ::: "memory")
#define CP_WAIT(n)  asm volatile("cp.async.wait_group %0;" :: "n"(n) : "memory")

// ---------------- one-time fp32 -> fp16 conversion ----------------
__global__ __launch_bounds__(256) void cvt_all(const float* __restrict__ hs,
                                               const float* __restrict__ Wq,
                                               const float* __restrict__ Wk,
                                               const float* __restrict__ Wv,
                                               const float* __restrict__ Wo) {
    int i = blockIdx.x * 256 + threadIdx.x;
    const float* src;
    __half* dst;
    int off;
    if (i < 786432)       { src = hs; dst = g_H + AH_OFF; off = i; }
    else if (i < 1048576) { src = Wq; dst = g_H + WQ_OFF; off = i - 786432; }
    else if (i < 1310720) { src = Wk; dst = g_H + WK_OFF; off = i - 1048576; }
    else if (i < 1572864) { src = Wv; dst = g_H + WV_OFF; off = i - 1310720; }
    else                  { src = Wo; dst = g_H + WO_OFF; off = i - 1572864; }
    float4 v = ((const float4*)src)[off];
    ((uint2*)dst)[off] = h4(v);
}

// ---------------- 128x128 GEMM body, cp.async staged (unchanged) -------------
__device__ __forceinline__ void gemm128_body(const __half* __restrict__ A,
                                             const __half* __restrict__ W,
                                             const float* __restrict__ bias,
                                             __half* __restrict__ Ch,
                                             float* __restrict__ Cf, int mode) {
    extern __shared__ char dsm[];
    float* BiasT = (float*)dsm;
    __half* AsB = (__half*)(dsm + G_TILE_OFF);        // [2][128][40]
    __half* BsB = AsB + 2 * 128 * 40;                 // [2][32][136]
    float* Cst = (float*)(dsm + G_TILE_OFF);          // [128][132]
    const unsigned AsB_u32 = (unsigned)__cvta_generic_to_shared(AsB);
    const unsigned BsB_u32 = (unsigned)__cvta_generic_to_shared(BsB);

    const int m0 = blockIdx.y * 128;
    const int n0 = blockIdx.x * 128;
    const int t = threadIdx.x;
    const int warp = t >> 5;
    const int wm = (warp & 3) * 32;
    const int wn = (warp >> 2) * 64;

#pragma unroll
    for (int r = 0; r < 2; r++) {
        int idx = t + r * 256;
        int row = idx >> 5;
        int col = (idx & 31) << 2;
        *(float4*)(BiasT + row * 132 + col) = *(const float4*)(bias + n0 + col);
    }

    FragC c[2][4];
#pragma unroll
    for (int i = 0; i < 2; i++)
#pragma unroll
        for (int j = 0; j < 4; j++) wmma::fill_fragment(c[i][j], 0.f);

    auto issue = [&](int k0, int buf) {
#pragma unroll
        for (int r = 0; r < 2; r++) {
            int idx = t + r * 256;
            int arow = idx >> 2, ac = (idx & 3) << 3;
            CP_ASYNC16(AsB_u32 + (buf * 128 * 40 + arow * 40 + ac) * 2,
                       A + (size_t)(m0 + arow) * DD + k0 + ac);
            int brow = idx >> 4, bc = (idx & 15) << 3;
            CP_ASYNC16(BsB_u32 + (buf * 32 * 136 + brow * 136 + bc) * 2,
                       W + (size_t)(k0 + brow) * PP + n0 + bc);
        }
    };

    issue(0, 0); CP_COMMIT();

    for (int k0 = 0; k0 < DD; k0 += 32) {
        const int cur = (k0 >> 5) & 1, nxt = cur ^ 1;
        const bool more = (k0 + 32 < DD);
        if (more) { issue(k0 + 32, nxt); CP_COMMIT(); }
        if (more) CP_WAIT(1); else CP_WAIT(0);
        __syncthreads();

        const __half* Asc = AsB + cur * 128 * 40;
        const __half* Bsc = BsB + cur * 32 * 136;
#pragma unroll
        for (int kk = 0; kk < 32; kk += 16) {
            HFragA a[2];
#pragma unroll
            for (int i = 0; i < 2; i++)
                wmma::load_matrix_sync(a[i], Asc + (wm + i * 16) * 40 + kk, 40);
#pragma unroll
            for (int j = 0; j < 4; j++) {
                HFragB b;
                wmma::load_matrix_sync(b, Bsc + kk * 136 + wn + j * 16, 136);
#pragma unroll
                for (int i = 0; i < 2; i++) wmma::mma_sync(c[i][j], a[i], b, c[i][j]);
            }
        }
        __syncthreads();
    }

    const float scale = (mode == 0) ? 0.125f : 1.0f;
#pragma unroll
    for (int j = 0; j < 4; j++) {
        FragC bf;
        wmma::load_matrix_sync(bf, BiasT + wn + j * 16, 132, wmma::mem_row_major);
#pragma unroll
        for (int i = 0; i < 2; i++)
#pragma unroll
            for (int e = 0; e < bf.num_elements; e++)
                c[i][j].x[e] = (c[i][j].x[e] + bf.x[e]) * scale;
    }

    if (mode <= 2) {
#pragma unroll
        for (int i = 0; i < 2; i++)
#pragma unroll
            for (int j = 0; j < 4; j++)
                wmma::store_matrix_sync(Cst + (size_t)(wm + i * 16) * 132 + wn + j * 16,
                                        c[i][j], 132, wmma::mem_row_major);
        __syncthreads();

        const int b = m0 / LL;
        const int l0 = m0 - b * LL;
        const int hbase = n0 >> 6;
#pragma unroll
        for (int r = 0; r < 16; r++) {
            int idx = t + r * 256;
            int row = idx >> 5;
            int col = (idx & 31) << 2;
            uint2 hv = h4(*(float4*)(Cst + (size_t)row * 132 + col));
            int h = hbase + (col >> 6);
            int d = col & 63;
            __half* out = Ch + (((size_t)(b * HH + h)) * LL + l0 + row) * HDIM + d;
            *(uint2*)out = hv;
        }
    } else {
#pragma unroll
        for (int i = 0; i < 2; i++)
#pragma unroll
            for (int j = 0; j < 4; j++)
                wmma::store_matrix_sync(Cf + (size_t)(m0 + wm + i * 16) * PP + n0 + wn + j * 16,
                                        c[i][j], PP, wmma::mem_row_major);
    }
}

__global__ __launch_bounds__(256, 2) void qkv_wmma(const float* __restrict__ bq,
                                                   const float* __restrict__ bk,
                                                   const float* __restrict__ bv) {
    const int zz = blockIdx.z;
    const __half* W = g_H + ((zz == 0) ? WQ_OFF : (zz == 1) ? WK_OFF : WV_OFF);
    const float* bias = (zz == 0) ? bq : (zz == 1) ? bk : bv;
    __half* C = (zz == 0) ? g_Q : (zz == 1) ? g_K : g_V;
    gemm128_body(g_H + AH_OFF, W, bias, C, nullptr, zz);
}

__global__ __launch_bounds__(256, 2) void oproj_wmma(const float* __restrict__ bias,
                                                     float* __restrict__ Cout) {
    gemm128_body(g_attn, g_H + WO_OFF, bias, nullptr, Cout, 3);
}

// ---------------- fused_all: 16 q-rows/block, 256 thr, 2 CTAs/SM ---------------------
__global__ __launch_bounds__(256, 2) void fused_all(const int* __restrict__ mask,
                                                    const float* __restrict__ kw) {
    extern __shared__ char smraw[];
    __half* PsF = (__half*)smraw;                      // [16][1544]: [8 pad][1536 data]
    __half* kvh = (__half*)(smraw + KVH_OFF);          // [1536]
    float* w5s = (float*)(smraw + W5_OFF);             // [5]
    __half* Qs = (__half*)(smraw + Q_OFF);             // [16][72]
    float* Sstg = (float*)(smraw + STG_OFF);           // [8][8][36]
    __half* KVb = (__half*)(smraw + KV_OFF);           // [2][128][72]
    float* Vred = (float*)(smraw + KV_OFF);            // [2][16][68] (aliases KVb)
    const unsigned KVb_u32 = (unsigned)__cvta_generic_to_shared(KVb);

    const int t = threadIdx.x;
    const int warp = t >> 5, lane = t & 31;
    const int row0 = blockIdx.x * FROWS;
    const int z = row0 / LL;
    const int q0 = row0 - z * LL;
    const int b = z >> 4;
    const int h = z & 15;
    const int* mrow = mask + b * LL;
    const __half* Qg = g_Q + ((size_t)z * LL + q0) * HDIM;
    const __half* Kg = g_K + (size_t)z * LL * HDIM;
    const __half* Vg = g_V + (size_t)z * LL * HDIM;

    // 128-row slab/chunk: 128 rows x 8 chunks of 16B = 1024 xfers / 256 thr = 4 each
    auto issue_kv = [&](const __half* src, int base_row, int buf) {
#pragma unroll
        for (int r = 0; r < 4; r++) {
            int u = t + r * 256;
            int row = u >> 3, cc = (u & 7) << 3;
            CP_ASYNC16(KVb_u32 + (buf * 128 * 72 + row * 72 + cc) * 2,
                       src + (size_t)(base_row + row) * HDIM + cc);
        }
    };

    issue_kv(Kg, 0, 0); CP_COMMIT();

    if (t == 0) {
        float mxw = kw[0];
#pragma unroll
        for (int j = 1; j < 5; j++) mxw = fmaxf(mxw, kw[j]);
        float e[5], s = 0.f;
#pragma unroll
        for (int j = 0; j < 5; j++) { e[j] = __expf(kw[j] - mxw); s += e[j]; }
#pragma unroll
        for (int j = 0; j < 5; j++) w5s[j] = e[j] / s;
    }
    for (int i = t; i < LL / 4; i += 256) {
        int4 m4 = *(const int4*)(mrow + i * 4);
        float4 kvf = make_float4(m4.x > 0 ? 1.f : 0.f, m4.y > 0 ? 1.f : 0.f,
                                 m4.z > 0 ? 1.f : 0.f, m4.w > 0 ? 1.f : 0.f);
        *(uint2*)(kvh + i * 4) = h4(kvf);
    }
    if (t < 128) {   // Q tile: 16 rows x 8 uint2 cols
        int row = t >> 3, col = (t & 7) << 3;
        *(uint4*)(Qs + row * 72 + col) = *(const uint4*)(Qg + (size_t)row * HDIM + col);
    }
    __syncthreads();

    const int rg = warp >> 2;     // 0..1: 8-row group
    const int sj = warp & 3;      // 0..3: 32-key col tile

    PFragA aq[4];
#pragma unroll
    for (int kk = 0; kk < 4; kk++)
        wmma::load_matrix_sync(aq[kk], Qs + (rg * 8) * 72 + kk * 16, 72);

    float* Sw = Sstg + warp * 8 * 36;

    // ---- S-compute: 12 slabs of 128 keys, cp.async double-buffered -> fp16 mirror ----
    for (int s = 0; s < 12; s++) {
        const int cur = s & 1, nxt = cur ^ 1;
        const bool more = (s + 1 < 12);
        if (more) { issue_kv(Kg, (s + 1) * 128, nxt); CP_COMMIT(); }
        if (more) CP_WAIT(1); else CP_WAIT(0);
        __syncthreads();

        const __half* Kc = KVb + cur * 128 * 72;
        PFragC sacc;
        wmma::fill_fragment(sacc, 0.f);
#pragma unroll
        for (int kk = 0; kk < 4; kk++) {
            PFragBc bb;
            wmma::load_matrix_sync(bb, Kc + (sj * 32) * 72 + kk * 16, 72);
            wmma::mma_sync(sacc, aq[kk], bb, sacc);
        }
        wmma::store_matrix_sync(Sw, sacc, 36, wmma::mem_row_major);
        __syncwarp();
        {
            int r = lane >> 2, q = lane & 3;
            const float* src = Sw + r * 36 + q * 8;
            float4 f0 = *(const float4*)src;
            float4 f1 = *(const float4*)(src + 4);
            uint2 u0 = h4(f0), u1 = h4(f1);
            uint4 uu = make_uint4(u0.x, u0.y, u1.x, u1.y);
            int row = rg * 8 + r;
            *(uint4*)(PsF + (size_t)row * PSTRH + 8 + s * 128 + sj * 32 + q * 8) = uu;
        }
        __syncthreads();
    }

    // prefetch both V chunks under phase 1
    issue_kv(Vg, 0, 0); CP_COMMIT();
    issue_kv(Vg, 128, 1); CP_COMMIT();

    const __half2 w0h = __float2half2_rn(w5s[0]);
    const __half2 w1h = __float2half2_rn(w5s[1]);
    const __half2 w2h = __float2half2_rn(w5s[2]);
    const __half2 w3h = __float2half2_rn(w5s[3]);
    const __half2 w4h = __float2half2_rn(w5s[4]);
    const __half2 a98 = __float2half2_rn(0.98f);

    // ---- phase 1: warp handles rows warp and warp+8; fp16 p, fp32 softmax ----
#pragma unroll 1
    for (int i = 0; i < 2; i++) {
        const int row = warp + 8 * i;
        __half* rowH = PsF + (size_t)row * PSTRH;
        if (lane == 0) *(uint4*)rowH = make_uint4(0, 0, 0, 0);

        unsigned plo[12], phi[12];
        {
            float4 p4[12];
            float mx = -3.4e38f;
#pragma unroll
            for (int k = 0; k < 12; k++) {
                int m = lane + 32 * k;
                float4 v = f4h(*(const uint2*)(rowH + 8 + 4 * m));
                float4 kv = f4h(*(const uint2*)(kvh + 4 * m));
                v.x += (kv.x > 0.f) ? 0.f : -1e9f;
                v.y += (kv.y > 0.f) ? 0.f : -1e9f;
                v.z += (kv.z > 0.f) ? 0.f : -1e9f;
                v.w += (kv.w > 0.f) ? 0.f : -1e9f;
                p4[k] = v;
                mx = fmaxf(mx, fmaxf(fmaxf(v.x, v.y), fmaxf(v.z, v.w)));
            }
#pragma unroll
            for (int o = 16; o; o >>= 1) mx = fmaxf(mx, __shfl_xor_sync(0xffffffffu, mx, o));

            float s = 0.f;
#pragma unroll
            for (int k = 0; k < 12; k++) {
                float4 v = p4[k];
                v.x = __expf(v.x - mx); v.y = __expf(v.y - mx);
                v.z = __expf(v.z - mx); v.w = __expf(v.w - mx);
                p4[k] = v;
                s += v.x + v.y + v.z + v.w;
            }
#pragma unroll
            for (int o = 16; o; o >>= 1) s += __shfl_xor_sync(0xffffffffu, s, o);
            float inv = 1.f / s;
#pragma unroll
            for (int k = 0; k < 12; k++) {
                p4[k].x *= inv; p4[k].y *= inv; p4[k].z *= inv; p4[k].w *= inv;
                uint2 u = h4(p4[k]);
                plo[k] = u.x; phi[k] = u.y;
                *(uint2*)(rowH + 8 + 4 * (lane + 32 * k)) = u;
            }
        }
        __syncwarp();

#pragma unroll 1
        for (int step = 0; step < 3; step++) {
            unsigned cx[12], cz[12];
            float sa = 0.f;
#pragma unroll
            for (int k = 0; k < 12; k++) {
                int m = lane + 32 * k;
                uint2 H = *(const uint2*)(rowH + 4 + 4 * m);
                unsigned hlo = H.x, hhi = H.y;
                unsigned olo = plo[k], ohi = phi[k];
                unsigned P1 = __byte_perm(hlo, hhi, 0x5432);
                unsigned P3 = __byte_perm(hhi, olo, 0x5432);
                unsigned P5 = __byte_perm(olo, ohi, 0x5432);
                __half2 cxy = __hmul2(w0h, u2h(hlo));
                cxy = __hfma2(w1h, u2h(P1), cxy);
                cxy = __hfma2(w2h, u2h(hhi), cxy);
                cxy = __hfma2(w3h, u2h(P3), cxy);
                cxy = __hfma2(w4h, u2h(olo), cxy);
                __half2 czw = __hmul2(w0h, u2h(hhi));
                czw = __hfma2(w1h, u2h(P3), czw);
                czw = __hfma2(w2h, u2h(olo), czw);
                czw = __hfma2(w3h, u2h(P5), czw);
                czw = __hfma2(w4h, u2h(ohi), czw);
                uint2 kvu = *(const uint2*)(kvh + 4 * m);
                cxy = __hmul2(cxy, u2h(kvu.x));
                czw = __hmul2(czw, u2h(kvu.y));
                cx[k] = h2u(cxy); cz[k] = h2u(czw);
                float2 f = __half22float2(__hadd2(cxy, czw));
                sa += f.x + f.y;
            }
#pragma unroll
            for (int o = 16; o; o >>= 1) sa += __shfl_xor_sync(0xffffffffu, sa, o);
            const float rmul = 0.02f / (sa + 1e-9f);
            const __half2 rm2 = __float2half2_rn(rmul);
            __syncwarp();
#pragma unroll
            for (int k = 0; k < 12; k++) {
                __half2 pl = __hfma2(a98, u2h(plo[k]), __hmul2(rm2, u2h(cx[k])));
                __half2 ph = __hfma2(a98, u2h(phi[k]), __hmul2(rm2, u2h(cz[k])));
                plo[k] = h2u(pl); phi[k] = h2u(ph);
                *(uint2*)(rowH + 8 + 4 * (lane + 32 * k)) = make_uint2(plo[k], phi[k]);
            }
            __syncwarp();
        }
    }
    __syncthreads();   // mirrors final = p operand

    // ---- phase 2: out[16x64] = p @ V; 12 chunks, 8 tasks/chunk (all warps busy) ----
    const int rp = warp >> 2;            // 0..1 row group (8 rows)
    const int pj = (warp >> 1) & 1;      // 0..1 col tile (32 cols)
    const int kg = warp & 1;             // 0..1 k half (64 rows within chunk)

    PFragC acc;
    wmma::fill_fragment(acc, 0.f);

    for (int c = 0; c < 12; c++) {
        if (c < 11) CP_WAIT(1); else CP_WAIT(0);
        __syncthreads();
        const __half* Vc = KVb + (c & 1) * 128 * 72;
#pragma unroll
        for (int kk = 0; kk < 64; kk += 16) {
            PFragA a;
            PFragB bb;
            wmma::load_matrix_sync(a, PsF + (size_t)(rp * 8) * PSTRH + 8 + c * 128 + kg * 64 + kk, PSTRH);
            wmma::load_matrix_sync(bb, Vc + (kg * 64 + kk) * 72 + pj * 32, 72);
            wmma::mma_sync(acc, a, bb, acc);
        }
        __syncthreads();
        if (c + 2 < 12) { issue_kv(Vg, (c + 2) * 128, c & 1); CP_COMMIT(); }
    }

    wmma::store_matrix_sync(Vred + (size_t)(kg * 16 + rp * 8) * 68 + pj * 32, acc,
                            68, wmma::mem_row_major);
    __syncthreads();

    {   // 16 rows x 16 float4 cols = 256 threads
        const int row = t >> 4;
        const int col = (t & 15) << 2;
        float4 s0 = *(float4*)(Vred + (size_t)row * 68 + col);
        float4 s1 = *(float4*)(Vred + (size_t)(16 + row) * 68 + col);
        s0.x += s1.x; s0.y += s1.y; s0.z += s1.z; s0.w += s1.w;
        __half* out = g_attn + ((size_t)(b * LL + q0 + row)) * PP + h * 64 + col;
        *(uint2*)out = h4(s0);
    }
}

// ---------------- launch ----------------
extern "C" void kernel_launch(void* const* d_in, const int* in_sizes, int n_in,
                              void* d_out, int out_size) {
    const float* hs = (const float*)d_in[0];
    const int* mask = (const int*)d_in[1];
    const float* Wq = (const float*)d_in[2];
    const float* bq = (const float*)d_in[3];
    const float* Wk = (const float*)d_in[4];
    const float* bk = (const float*)d_in[5];
    const float* Wv = (const float*)d_in[6];
    const float* bv = (const float*)d_in[7];
    const float* Wo = (const float*)d_in[8];
    const float* bo = (const float*)d_in[9];
    const float* kw = (const float*)d_in[10];

    cudaFuncSetAttribute(qkv_wmma, cudaFuncAttributeMaxDynamicSharedMemorySize, G_SMEM_BYTES);
    cudaFuncSetAttribute(oproj_wmma, cudaFuncAttributeMaxDynamicSharedMemorySize, G_SMEM_BYTES);
    cudaFuncSetAttribute(fused_all, cudaFuncAttributeMaxDynamicSharedMemorySize, FUSED_SMEM_BYTES);

    cvt_all<<<7168, 256>>>(hs, Wq, Wk, Wv, Wo);

    qkv_wmma<<<dim3(PP / 128, (BB * LL) / 128, 3), 256, G_SMEM_BYTES>>>(bq, bk, bv);

    fused_all<<<(BB * HH * LL) / FROWS, 256, FUSED_SMEM_BYTES>>>(mask, kw);

    oproj_wmma<<<dim3(PP / 128, (BB * LL) / 128), 256, G_SMEM_BYTES>>>(bo, (float*)d_out);
}